// round 6
// baseline (speedup 1.0000x reference)
#include <cuda_runtime.h>
#include <cuda_fp16.h>
#include <cstdint>
#include <math.h>

#define HW 4096
#define NB 16
#define BK 32
#define NPART 2048

#define ASTR 20     // A smem row stride (uint32 words), rows = m, cols = kpair
#define BSTR 136    // B smem row stride (uint32 words), rows = kpair, cols = n

// ---------------- scratch (static device globals; no allocation) ----------------
static __device__ float g_tsc [(size_t)NB*256*HW];
static __device__ float g_h   [(size_t)NB*256*HW];   // PRE-BN; BN folded into consumers
static __device__ float g_qkv2[(size_t)NB*192*HW];
static __device__ float g_qkv3[(size_t)NB*192*HW];
static __device__ float g_preB[(size_t)NB*256*HW];   // PRE-BN branch outputs
static __device__ float g_pout[(size_t)NB*256*HW];
static __device__ float g_ctxp[2*NB*8*4096];
static __device__ float g_ctx [2*NB*4096];
static __device__ float g_Mm  [2*NB*4096];
static __device__ float g_psum  [(size_t)1024*NPART];
static __device__ float g_psumsq[(size_t)1024*NPART];
static __device__ float g_scale [1024];
static __device__ float g_shift [1024];

__device__ __forceinline__ uint32_t h2(float a, float b) {
    __half2 h = __floats2half2_rn(a, b);   // .x (lo) = a, .y (hi) = b
    return *(uint32_t*)&h;
}
__device__ __forceinline__ void mma16(float* c, const uint32_t* a, const uint32_t* b) {
    asm volatile("mma.sync.aligned.m16n8k16.row.col.f32.f16.f16.f32 "
        "{%0,%1,%2,%3}, {%4,%5,%6,%7}, {%8,%9}, {%0,%1,%2,%3};"
        : "+f"(c[0]), "+f"(c[1]), "+f"(c[2]), "+f"(c[3])
        : "r"(a[0]), "r"(a[1]), "r"(a[2]), "r"(a[3]), "r"(b[0]), "r"(b[1]));
}

// smem word offsets
#define BOFF128 2560               // A 128*20
#define SMEMSZ128 ((2560 + 16*BSTR) * 4)
#define BOFF64 1280                // A 64*20
#define SMEMSZ64 ((1280 + 16*BSTR) * 4)

// ================= 128-row tile GEMM (fp16 mma, fused BN-in / stats-out) =================
__global__ __launch_bounds__(256, 2) void tgemm_k(
    const float* __restrict__ Wg, const float* __restrict__ A, float* __restrict__ C,
    int K, long wbs, long abs_, int acoff, long cbs, int ccoff,
    int bnslot, int statslot)
{
    extern __shared__ uint32_t smw[];
    uint32_t* smA = smw;
    uint32_t* smB = smw + BOFF128;
    const int b = blockIdx.z;
    const float* Wp = Wg + (size_t)b * wbs;
    const float* Ap = A + (size_t)b * abs_ + (size_t)acoff * HW;
    float* Cp = C + (size_t)b * cbs + (size_t)ccoff * HW;
    const int n0 = blockIdx.x * 128, m0 = blockIdx.y * 128;
    const int tid = threadIdx.x, lane = tid & 31, wid = tid >> 5;
    const int wm0 = (wid >> 2) * 64, wn0 = (wid & 3) * 32;
    const int qr = lane >> 2, qc = lane & 3;
    const int nk = K / BK;

    float acc[4][4][4];
#pragma unroll
    for (int i = 0; i < 4; i++)
#pragma unroll
        for (int j = 0; j < 4; j++)
#pragma unroll
            for (int e = 0; e < 4; e++) acc[i][j][e] = 0.f;

    for (int kc = 0; kc < nk; kc++) {
        // ---- A fill: 128 m-rows x 16 kpairs ----
        {
            const int fam = tid >> 1, fkp = (tid & 1) * 8;
            const float* wr = Wp + (size_t)(m0 + fam) * K + kc * BK + fkp * 2;
            uint32_t* das = smA + fam * ASTR + fkp;
            uint32_t p[8];
#pragma unroll
            for (int t = 0; t < 4; t++) {
                float4 v = *(const float4*)(wr + t * 4);
                p[t * 2]     = h2(v.x, v.y);
                p[t * 2 + 1] = h2(v.z, v.w);
            }
            *(uint4*)(das)     = make_uint4(p[0], p[1], p[2], p[3]);
            *(uint4*)(das + 4) = make_uint4(p[4], p[5], p[6], p[7]);
        }
        // ---- B fill: 16 kpairs x 128 n (pack k,k+1; optional BN+ReLU) ----
        {
            const int fkp = tid >> 4, fn = (tid & 15) * 8;
            const int k0 = kc * BK + fkp * 2;
            const float* r0 = Ap + (size_t)k0 * HW + n0 + fn;
            const float* r1 = r0 + HW;
            float4 a0 = *(const float4*)(r0), a1 = *(const float4*)(r0 + 4);
            float4 c0 = *(const float4*)(r1), c1 = *(const float4*)(r1 + 4);
            if (bnslot >= 0) {
                const float s0 = g_scale[bnslot + acoff + k0],     h0 = g_shift[bnslot + acoff + k0];
                const float s1 = g_scale[bnslot + acoff + k0 + 1], h1 = g_shift[bnslot + acoff + k0 + 1];
                a0.x = fmaxf(a0.x * s0 + h0, 0.f); a0.y = fmaxf(a0.y * s0 + h0, 0.f);
                a0.z = fmaxf(a0.z * s0 + h0, 0.f); a0.w = fmaxf(a0.w * s0 + h0, 0.f);
                a1.x = fmaxf(a1.x * s0 + h0, 0.f); a1.y = fmaxf(a1.y * s0 + h0, 0.f);
                a1.z = fmaxf(a1.z * s0 + h0, 0.f); a1.w = fmaxf(a1.w * s0 + h0, 0.f);
                c0.x = fmaxf(c0.x * s1 + h1, 0.f); c0.y = fmaxf(c0.y * s1 + h1, 0.f);
                c0.z = fmaxf(c0.z * s1 + h1, 0.f); c0.w = fmaxf(c0.w * s1 + h1, 0.f);
                c1.x = fmaxf(c1.x * s1 + h1, 0.f); c1.y = fmaxf(c1.y * s1 + h1, 0.f);
                c1.z = fmaxf(c1.z * s1 + h1, 0.f); c1.w = fmaxf(c1.w * s1 + h1, 0.f);
            }
            uint32_t* dbs = smB + fkp * BSTR + fn;
            *(uint4*)(dbs)     = make_uint4(h2(a0.x, c0.x), h2(a0.y, c0.y), h2(a0.z, c0.z), h2(a0.w, c0.w));
            *(uint4*)(dbs + 4) = make_uint4(h2(a1.x, c1.x), h2(a1.y, c1.y), h2(a1.z, c1.z), h2(a1.w, c1.w));
        }
        __syncthreads();
#pragma unroll
        for (int ks = 0; ks < 2; ks++) {
            const int kb = ks * 8;
            uint32_t af[4][4], bf[4][2];
#pragma unroll
            for (int mt = 0; mt < 4; mt++) {
                const uint32_t* ap = smA + (wm0 + mt * 16 + qr) * ASTR + kb + qc;
                af[mt][0] = ap[0];
                af[mt][1] = ap[8 * ASTR];
                af[mt][2] = ap[4];
                af[mt][3] = ap[8 * ASTR + 4];
            }
#pragma unroll
            for (int nt = 0; nt < 4; nt++) {
                const uint32_t* bp = smB + (kb + qc) * BSTR + wn0 + nt * 8 + qr;
                bf[nt][0] = bp[0];
                bf[nt][1] = bp[4 * BSTR];
            }
#pragma unroll
            for (int mt = 0; mt < 4; mt++)
#pragma unroll
                for (int nt = 0; nt < 4; nt++) mma16(acc[mt][nt], af[mt], bf[nt]);
        }
        __syncthreads();
    }

    const int pidx = (b * 32 + blockIdx.x) * 4 + (wid & 3);
#pragma unroll
    for (int mt = 0; mt < 4; mt++) {
        const int m = m0 + wm0 + mt * 16 + qr;
#pragma unroll
        for (int nt = 0; nt < 4; nt++) {
            const int n = n0 + wn0 + nt * 8 + qc * 2;
            *(float2*)(Cp + (size_t)m * HW + n) = make_float2(acc[mt][nt][0], acc[mt][nt][1]);
            *(float2*)(Cp + (size_t)(m + 8) * HW + n) = make_float2(acc[mt][nt][2], acc[mt][nt][3]);
        }
        if (statslot >= 0) {
            float s0 = 0.f, q0 = 0.f, s1 = 0.f, q1 = 0.f;
#pragma unroll
            for (int nt = 0; nt < 4; nt++) {
                s0 += acc[mt][nt][0] + acc[mt][nt][1];
                q0 += acc[mt][nt][0] * acc[mt][nt][0] + acc[mt][nt][1] * acc[mt][nt][1];
                s1 += acc[mt][nt][2] + acc[mt][nt][3];
                q1 += acc[mt][nt][2] * acc[mt][nt][2] + acc[mt][nt][3] * acc[mt][nt][3];
            }
#pragma unroll
            for (int off = 1; off < 4; off <<= 1) {
                s0 += __shfl_xor_sync(0xffffffffu, s0, off);
                q0 += __shfl_xor_sync(0xffffffffu, q0, off);
                s1 += __shfl_xor_sync(0xffffffffu, s1, off);
                q1 += __shfl_xor_sync(0xffffffffu, q1, off);
            }
            if (qc == 0) {
                g_psum  [(size_t)(statslot + ccoff + m) * NPART + pidx] = s0;
                g_psumsq[(size_t)(statslot + ccoff + m) * NPART + pidx] = q0;
                g_psum  [(size_t)(statslot + ccoff + m + 8) * NPART + pidx] = s1;
                g_psumsq[(size_t)(statslot + ccoff + m + 8) * NPART + pidx] = q1;
            }
        }
    }
}

// ================= 64-row tile GEMM (fp16 mma) =================
__global__ __launch_bounds__(256, 2) void tgemm64_k(
    const float* __restrict__ Wg, const float* __restrict__ A, float* __restrict__ C,
    int K, long wbs, long abs_, int acoff, long cbs, int ccoff,
    int bnslot, int statslot)
{
    extern __shared__ uint32_t smw[];
    uint32_t* smA = smw;
    uint32_t* smB = smw + BOFF64;
    const int b = blockIdx.z;
    const float* Wp = Wg + (size_t)b * wbs;
    const float* Ap = A + (size_t)b * abs_ + (size_t)acoff * HW;
    float* Cp = C + (size_t)b * cbs + (size_t)ccoff * HW;
    const int n0 = blockIdx.x * 128, m0 = blockIdx.y * 64;
    const int tid = threadIdx.x, lane = tid & 31, wid = tid >> 5;
    const int wm0 = (wid >> 2) * 32, wn0 = (wid & 3) * 32;
    const int qr = lane >> 2, qc = lane & 3;
    const int nk = K / BK;

    float acc[2][4][4];
#pragma unroll
    for (int i = 0; i < 2; i++)
#pragma unroll
        for (int j = 0; j < 4; j++)
#pragma unroll
            for (int e = 0; e < 4; e++) acc[i][j][e] = 0.f;

    for (int kc = 0; kc < nk; kc++) {
        // ---- A fill: 64 rows x 16 kpairs (4 pairs/thread) ----
        {
            const int fam = tid >> 2, fkp = (tid & 3) * 4;
            const float* wr = Wp + (size_t)(m0 + fam) * K + kc * BK + fkp * 2;
            float4 v0 = *(const float4*)(wr), v1 = *(const float4*)(wr + 4);
            uint32_t* das = smA + fam * ASTR + fkp;
            *(uint4*)(das) = make_uint4(h2(v0.x, v0.y), h2(v0.z, v0.w), h2(v1.x, v1.y), h2(v1.z, v1.w));
        }
        // ---- B fill ----
        {
            const int fkp = tid >> 4, fn = (tid & 15) * 8;
            const int k0 = kc * BK + fkp * 2;
            const float* r0 = Ap + (size_t)k0 * HW + n0 + fn;
            const float* r1 = r0 + HW;
            float4 a0 = *(const float4*)(r0), a1 = *(const float4*)(r0 + 4);
            float4 c0 = *(const float4*)(r1), c1 = *(const float4*)(r1 + 4);
            if (bnslot >= 0) {
                const float s0 = g_scale[bnslot + acoff + k0],     h0 = g_shift[bnslot + acoff + k0];
                const float s1 = g_scale[bnslot + acoff + k0 + 1], h1 = g_shift[bnslot + acoff + k0 + 1];
                a0.x = fmaxf(a0.x * s0 + h0, 0.f); a0.y = fmaxf(a0.y * s0 + h0, 0.f);
                a0.z = fmaxf(a0.z * s0 + h0, 0.f); a0.w = fmaxf(a0.w * s0 + h0, 0.f);
                a1.x = fmaxf(a1.x * s0 + h0, 0.f); a1.y = fmaxf(a1.y * s0 + h0, 0.f);
                a1.z = fmaxf(a1.z * s0 + h0, 0.f); a1.w = fmaxf(a1.w * s0 + h0, 0.f);
                c0.x = fmaxf(c0.x * s1 + h1, 0.f); c0.y = fmaxf(c0.y * s1 + h1, 0.f);
                c0.z = fmaxf(c0.z * s1 + h1, 0.f); c0.w = fmaxf(c0.w * s1 + h1, 0.f);
                c1.x = fmaxf(c1.x * s1 + h1, 0.f); c1.y = fmaxf(c1.y * s1 + h1, 0.f);
                c1.z = fmaxf(c1.z * s1 + h1, 0.f); c1.w = fmaxf(c1.w * s1 + h1, 0.f);
            }
            uint32_t* dbs = smB + fkp * BSTR + fn;
            *(uint4*)(dbs)     = make_uint4(h2(a0.x, c0.x), h2(a0.y, c0.y), h2(a0.z, c0.z), h2(a0.w, c0.w));
            *(uint4*)(dbs + 4) = make_uint4(h2(a1.x, c1.x), h2(a1.y, c1.y), h2(a1.z, c1.z), h2(a1.w, c1.w));
        }
        __syncthreads();
#pragma unroll
        for (int ks = 0; ks < 2; ks++) {
            const int kb = ks * 8;
            uint32_t af[2][4], bf[4][2];
#pragma unroll
            for (int mt = 0; mt < 2; mt++) {
                const uint32_t* ap = smA + (wm0 + mt * 16 + qr) * ASTR + kb + qc;
                af[mt][0] = ap[0];
                af[mt][1] = ap[8 * ASTR];
                af[mt][2] = ap[4];
                af[mt][3] = ap[8 * ASTR + 4];
            }
#pragma unroll
            for (int nt = 0; nt < 4; nt++) {
                const uint32_t* bp = smB + (kb + qc) * BSTR + wn0 + nt * 8 + qr;
                bf[nt][0] = bp[0];
                bf[nt][1] = bp[4 * BSTR];
            }
#pragma unroll
            for (int mt = 0; mt < 2; mt++)
#pragma unroll
                for (int nt = 0; nt < 4; nt++) mma16(acc[mt][nt], af[mt], bf[nt]);
        }
        __syncthreads();
    }

    const int pidx = (b * 32 + blockIdx.x) * 4 + (wid & 3);
#pragma unroll
    for (int mt = 0; mt < 2; mt++) {
        const int m = m0 + wm0 + mt * 16 + qr;
#pragma unroll
        for (int nt = 0; nt < 4; nt++) {
            const int n = n0 + wn0 + nt * 8 + qc * 2;
            *(float2*)(Cp + (size_t)m * HW + n) = make_float2(acc[mt][nt][0], acc[mt][nt][1]);
            *(float2*)(Cp + (size_t)(m + 8) * HW + n) = make_float2(acc[mt][nt][2], acc[mt][nt][3]);
        }
        if (statslot >= 0) {
            float s0 = 0.f, q0 = 0.f, s1 = 0.f, q1 = 0.f;
#pragma unroll
            for (int nt = 0; nt < 4; nt++) {
                s0 += acc[mt][nt][0] + acc[mt][nt][1];
                q0 += acc[mt][nt][0] * acc[mt][nt][0] + acc[mt][nt][1] * acc[mt][nt][1];
                s1 += acc[mt][nt][2] + acc[mt][nt][3];
                q1 += acc[mt][nt][2] * acc[mt][nt][2] + acc[mt][nt][3] * acc[mt][nt][3];
            }
#pragma unroll
            for (int off = 1; off < 4; off <<= 1) {
                s0 += __shfl_xor_sync(0xffffffffu, s0, off);
                q0 += __shfl_xor_sync(0xffffffffu, q0, off);
                s1 += __shfl_xor_sync(0xffffffffu, s1, off);
                q1 += __shfl_xor_sync(0xffffffffu, q1, off);
            }
            if (qc == 0) {
                g_psum  [(size_t)(statslot + ccoff + m) * NPART + pidx] = s0;
                g_psumsq[(size_t)(statslot + ccoff + m) * NPART + pidx] = q0;
                g_psum  [(size_t)(statslot + ccoff + m + 8) * NPART + pidx] = s1;
                g_psumsq[(size_t)(statslot + ccoff + m + 8) * NPART + pidx] = q1;
            }
        }
    }
}

// ================= fp16 implicit-GEMM 3x3 conv on s1 (BN-in, stats-out) =================
__global__ __launch_bounds__(256, 2) void tconv_k(const float* __restrict__ Wb1)
{
    extern __shared__ uint32_t smw[];
    uint32_t* smA = smw;
    uint32_t* smB = smw + BOFF64;
    const int b = blockIdx.z;
    const float* Ap = g_h + (size_t)b * 256 * HW + (size_t)64 * HW;
    float* Cp = g_preB + (size_t)b * 256 * HW + (size_t)64 * HW;
    const int n0 = blockIdx.x * 128;
    const int tid = threadIdx.x, lane = tid & 31, wid = tid >> 5;
    const int wm0 = (wid >> 2) * 32, wn0 = (wid & 3) * 32;
    const int qr = lane >> 2, qc = lane & 3;
    const int nk = 18;

    float acc[2][4][4];
#pragma unroll
    for (int i = 0; i < 2; i++)
#pragma unroll
        for (int j = 0; j < 4; j++)
#pragma unroll
            for (int e = 0; e < 4; e++) acc[i][j][e] = 0.f;

    for (int kc = 0; kc < nk; kc++) {
        const int tap = kc >> 1, half = kc & 1;
        const int dy = tap / 3 - 1, dx = tap % 3 - 1;
        // ---- A fill: weights ----
        {
            const int fam = tid >> 2, fkp = (tid & 3) * 4;
            const float* wr = Wb1 + (size_t)fam * 576 + tap;
            uint32_t p[4];
#pragma unroll
            for (int j = 0; j < 4; j++) {
                int ic = half * 32 + 2 * (fkp + j);
                p[j] = h2(wr[ic * 9], wr[(ic + 1) * 9]);
            }
            *(uint4*)(smA + fam * ASTR + fkp) = make_uint4(p[0], p[1], p[2], p[3]);
        }
        // ---- B fill: shifted planes, BN+ReLU on in-bounds ----
        {
            const int fkp = tid >> 4, fn = (tid & 15) * 8;
            const int ic0 = half * 32 + 2 * fkp;
            const float* p0 = Ap + (size_t)ic0 * HW;
            const float* p1 = p0 + HW;
            const float s0 = g_scale[256 + 64 + ic0], h0 = g_shift[256 + 64 + ic0];
            const float s1 = g_scale[256 + 64 + ic0 + 1], h1 = g_shift[256 + 64 + ic0 + 1];
            uint32_t pk[8];
#pragma unroll
            for (int j = 0; j < 8; j++) {
                int p = n0 + fn + j;
                int y = (p >> 6) + dy, x = (p & 63) + dx;
                float u0 = 0.f, u1 = 0.f;
                if ((unsigned)y < 64u && (unsigned)x < 64u) {
                    int o = y * 64 + x;
                    u0 = fmaxf(p0[o] * s0 + h0, 0.f);
                    u1 = fmaxf(p1[o] * s1 + h1, 0.f);
                }
                pk[j] = h2(u0, u1);
            }
            uint32_t* dbs = smB + fkp * BSTR + fn;
            *(uint4*)(dbs)     = make_uint4(pk[0], pk[1], pk[2], pk[3]);
            *(uint4*)(dbs + 4) = make_uint4(pk[4], pk[5], pk[6], pk[7]);
        }
        __syncthreads();
#pragma unroll
        for (int ks = 0; ks < 2; ks++) {
            const int kb = ks * 8;
            uint32_t af[2][4], bf[4][2];
#pragma unroll
            for (int mt = 0; mt < 2; mt++) {
                const uint32_t* ap = smA + (wm0 + mt * 16 + qr) * ASTR + kb + qc;
                af[mt][0] = ap[0];
                af[mt][1] = ap[8 * ASTR];
                af[mt][2] = ap[4];
                af[mt][3] = ap[8 * ASTR + 4];
            }
#pragma unroll
            for (int nt = 0; nt < 4; nt++) {
                const uint32_t* bp = smB + (kb + qc) * BSTR + wn0 + nt * 8 + qr;
                bf[nt][0] = bp[0];
                bf[nt][1] = bp[4 * BSTR];
            }
#pragma unroll
            for (int mt = 0; mt < 2; mt++)
#pragma unroll
                for (int nt = 0; nt < 4; nt++) mma16(acc[mt][nt], af[mt], bf[nt]);
        }
        __syncthreads();
    }

    const int pidx = (b * 32 + blockIdx.x) * 4 + (wid & 3);
#pragma unroll
    for (int mt = 0; mt < 2; mt++) {
        const int m = wm0 + mt * 16 + qr;
#pragma unroll
        for (int nt = 0; nt < 4; nt++) {
            const int n = n0 + wn0 + nt * 8 + qc * 2;
            *(float2*)(Cp + (size_t)m * HW + n) = make_float2(acc[mt][nt][0], acc[mt][nt][1]);
            *(float2*)(Cp + (size_t)(m + 8) * HW + n) = make_float2(acc[mt][nt][2], acc[mt][nt][3]);
        }
        float s0 = 0.f, q0 = 0.f, s1 = 0.f, q1 = 0.f;
#pragma unroll
        for (int nt = 0; nt < 4; nt++) {
            s0 += acc[mt][nt][0] + acc[mt][nt][1];
            q0 += acc[mt][nt][0] * acc[mt][nt][0] + acc[mt][nt][1] * acc[mt][nt][1];
            s1 += acc[mt][nt][2] + acc[mt][nt][3];
            q1 += acc[mt][nt][2] * acc[mt][nt][2] + acc[mt][nt][3] * acc[mt][nt][3];
        }
#pragma unroll
        for (int off = 1; off < 4; off <<= 1) {
            s0 += __shfl_xor_sync(0xffffffffu, s0, off);
            q0 += __shfl_xor_sync(0xffffffffu, q0, off);
            s1 += __shfl_xor_sync(0xffffffffu, s1, off);
            q1 += __shfl_xor_sync(0xffffffffu, q1, off);
        }
        if (qc == 0) {
            g_psum  [(size_t)(576 + m) * NPART + pidx] = s0;
            g_psumsq[(size_t)(576 + m) * NPART + pidx] = q0;
            g_psum  [(size_t)(576 + m + 8) * NPART + pidx] = s1;
            g_psumsq[(size_t)(576 + m + 8) * NPART + pidx] = q1;
        }
    }
}

// ---------------- finalize: reduce NPART partials -> scale/shift ----------------
__global__ __launch_bounds__(256) void finalize_k(int slot, const float* __restrict__ gamma, const float* __restrict__ beta)
{
    const int c = blockIdx.x, tid = threadIdx.x;
    const float* ps = g_psum   + (size_t)(slot + c) * NPART;
    const float* pq = g_psumsq + (size_t)(slot + c) * NPART;
    float s = 0.f, q = 0.f;
    for (int i = tid; i < NPART; i += 256) { s += ps[i]; q += pq[i]; }
    __shared__ float ss[256], sq[256];
    ss[tid] = s; sq[tid] = q; __syncthreads();
    for (int st = 128; st > 0; st >>= 1) {
        if (tid < st) { ss[tid] += ss[tid + st]; sq[tid] += sq[tid + st]; }
        __syncthreads();
    }
    if (tid == 0) {
        const float inv = 1.f / 65536.f;
        float m = ss[0] * inv;
        float v = sq[0] * inv - m * m;
        float sc = gamma[c] * rsqrtf(v + 1e-5f);
        g_scale[slot + c] = sc;
        g_shift[slot + c] = beta[c] - m * sc;
    }
}

// ---------------- softmax over N=4096 on the k-section of qkv ----------------
__global__ __launch_bounds__(256) void softmax_k(float* __restrict__ q2, float* __restrict__ q3)
{
    __shared__ float row[4096];
    __shared__ float red[256];
    const int id = blockIdx.x;
    const int lga = id >> 10, rem = id & 1023;
    const int b = rem >> 6, c = rem & 63;
    float* p = (lga ? q3 : q2) + ((size_t)b * 192 + 64 + c) * HW;
    const int tid = threadIdx.x;

    float m = -1e30f;
    for (int i = tid; i < 4096; i += 256) { float v = p[i]; row[i] = v; m = fmaxf(m, v); }
    red[tid] = m; __syncthreads();
    for (int st = 128; st > 0; st >>= 1) { if (tid < st) red[tid] = fmaxf(red[tid], red[tid + st]); __syncthreads(); }
    m = red[0]; __syncthreads();

    float s = 0.f;
    for (int i = tid; i < 4096; i += 256) { float e = expf(row[i] - m); row[i] = e; s += e; }
    red[tid] = s; __syncthreads();
    for (int st = 128; st > 0; st >>= 1) { if (tid < st) red[tid] += red[tid + st]; __syncthreads(); }
    float inv = 1.f / red[0];
    for (int i = tid; i < 4096; i += 256) p[i] = row[i] * inv;
}

// ---------------- ctx partials: ctx[b,c,d] = sum_n k[c,n]*v[d,n] ----------------
__global__ __launch_bounds__(256) void ctx_k(const float* __restrict__ q2, const float* __restrict__ q3)
{
    __shared__ float Ks[64][33];
    __shared__ float Vs[64][33];
    const int chunk = blockIdx.x >> 4, b = blockIdx.x & 15, lga = blockIdx.y;
    const float* base = (lga ? q3 : q2) + (size_t)b * 192 * HW;
    const float* kp = base + (size_t)64 * HW;
    const float* vp = base + (size_t)128 * HW;
    const int tid = threadIdx.x;
    const int cb = (tid >> 4) << 2, db = (tid & 15) << 2;

    float acc[4][4];
#pragma unroll
    for (int i = 0; i < 4; i++)
#pragma unroll
        for (int j = 0; j < 4; j++) acc[i][j] = 0.f;

    for (int sub = 0; sub < 16; sub++) {
        const int n0 = chunk * 512 + sub * 32;
        for (int idx = tid; idx < 2048; idx += 256) {
            int r = idx >> 5, cc = idx & 31;
            Ks[r][cc] = kp[(size_t)r * HW + n0 + cc];
            Vs[r][cc] = vp[(size_t)r * HW + n0 + cc];
        }
        __syncthreads();
#pragma unroll 8
        for (int nn = 0; nn < 32; nn++) {
            float kc[4], vd[4];
#pragma unroll
            for (int i = 0; i < 4; i++) { kc[i] = Ks[cb + i][nn]; vd[i] = Vs[db + i][nn]; }
#pragma unroll
            for (int i = 0; i < 4; i++)
#pragma unroll
                for (int j = 0; j < 4; j++) acc[i][j] += kc[i] * vd[j];
        }
        __syncthreads();
    }
    float* cp = g_ctxp + ((size_t)(lga * 16 + b) * 8 + chunk) * 4096;
#pragma unroll
    for (int i = 0; i < 4; i++)
#pragma unroll
        for (int j = 0; j < 4; j++) cp[(cb + i) * 64 + db + j] = acc[i][j];
}

__global__ void ctxred_k()
{
    int i = blockIdx.x * 256 + threadIdx.x;
    if (i >= 2 * NB * 4096) return;
    int pair = i >> 12, e = i & 4095;
    const float* cp = g_ctxp + (size_t)pair * 8 * 4096 + e;
    float s = 0.f;
#pragma unroll
    for (int p = 0; p < 8; p++) s += cp[p * 4096];
    g_ctx[i] = s;
}

// ---------------- M[o,c] = sum_d Wproj[o,d] * ctx[c,d] ----------------
__global__ __launch_bounds__(256) void mproj_k(const float* __restrict__ Wp2, const float* __restrict__ Wp3)
{
    const int id = blockIdx.x;
    const int lga = id >> 4;
    const float* Wp = lga ? Wp3 : Wp2;
    const float* cx = g_ctx + (size_t)id * 4096;
    float* Mo = g_Mm + (size_t)id * 4096;
    for (int e = threadIdx.x; e < 4096; e += 256) {
        int o = e >> 6, c = e & 63;
        float s = 0.f;
#pragma unroll 16
        for (int d = 0; d < 64; d++) s += Wp[o * 64 + d] * cx[c * 64 + d];
        Mo[o * 64 + c] = s;
    }
}

// ---------------- final: out = relu( bn2(pout) + bn_sc(tsc) ) ----------------
__global__ __launch_bounds__(256) void final_k(float* __restrict__ out)
{
    size_t i = (size_t)blockIdx.x * 256 + threadIdx.x;
    int c = (int)((i >> 10) & 255);
    float s2 = g_scale[768 + c], h2v = g_shift[768 + c];
    float s0 = g_scale[c],       h0v = g_shift[c];
    float4 p = ((const float4*)g_pout)[i];
    float4 r = ((const float4*)g_tsc)[i];
    p.x = fmaxf(p.x * s2 + h2v + r.x * s0 + h0v, 0.f);
    p.y = fmaxf(p.y * s2 + h2v + r.y * s0 + h0v, 0.f);
    p.z = fmaxf(p.z * s2 + h2v + r.z * s0 + h0v, 0.f);
    p.w = fmaxf(p.w * s2 + h2v + r.w * s0 + h0v, 0.f);
    ((float4*)out)[i] = p;
}

// ---------------- launch ----------------
extern "C" void kernel_launch(void* const* d_in, const int* in_sizes, int n_in,
                              void* d_out, int out_size)
{
    (void)in_sizes; (void)n_in; (void)out_size;
    const float* x      = (const float*)d_in[0];
    const float* W_sc   = (const float*)d_in[1];
    const float* gsc    = (const float*)d_in[2];
    const float* bsc    = (const float*)d_in[3];
    const float* W1     = (const float*)d_in[4];
    const float* g1     = (const float*)d_in[5];
    const float* b1     = (const float*)d_in[6];
    const float* Wb0    = (const float*)d_in[7];
    const float* gb0    = (const float*)d_in[8];
    const float* bb0    = (const float*)d_in[9];
    const float* Wb1    = (const float*)d_in[10];
    const float* gb1    = (const float*)d_in[11];
    const float* bb1    = (const float*)d_in[12];
    const float* Wqkv2  = (const float*)d_in[13];
    const float* Wproj2 = (const float*)d_in[14];
    const float* ga2    = (const float*)d_in[15];
    const float* ba2    = (const float*)d_in[16];
    const float* Wqkv3  = (const float*)d_in[17];
    const float* Wproj3 = (const float*)d_in[18];
    const float* ga3    = (const float*)d_in[19];
    const float* ba3    = (const float*)d_in[20];
    const float* W2     = (const float*)d_in[21];
    const float* g2     = (const float*)d_in[22];
    const float* b2     = (const float*)d_in[23];

    float *tsc, *hh, *qk2, *qk3, *preB, *pout, *Mm;
    cudaGetSymbolAddress((void**)&tsc,  g_tsc);
    cudaGetSymbolAddress((void**)&hh,   g_h);
    cudaGetSymbolAddress((void**)&qk2,  g_qkv2);
    cudaGetSymbolAddress((void**)&qk3,  g_qkv3);
    cudaGetSymbolAddress((void**)&preB, g_preB);
    cudaGetSymbolAddress((void**)&pout, g_pout);
    cudaGetSymbolAddress((void**)&Mm,   g_Mm);

    // Stage 1: two 128->256 convs over x; stats fused into epilogues
    tgemm_k<<<dim3(32, 2, NB), 256, SMEMSZ128>>>(W_sc, x, tsc, 128, 0, (long)128 * HW, 0, (long)256 * HW, 0, -1, 0);
    tgemm_k<<<dim3(32, 2, NB), 256, SMEMSZ128>>>(W1,   x, hh,  128, 0, (long)128 * HW, 0, (long)256 * HW, 0, -1, 256);
    finalize_k<<<256, 256>>>(0,   gsc, bsc);
    finalize_k<<<256, 256>>>(256, g1,  b1);

    // Branch 0: 1x1 conv on s0 (BN of h folded into B loader)
    tgemm64_k<<<dim3(32, 1, NB), 256, SMEMSZ64>>>(Wb0, hh, preB, 64, 0, (long)256 * HW, 0, (long)256 * HW, 0, 256, 512);
    // Branch 1: 3x3 conv on s1 (implicit GEMM, BN folded)
    tconv_k<<<dim3(32, 1, NB), 256, SMEMSZ64>>>(Wb1);
    // Branches 2/3: qkv projections (BN folded; no stats)
    tgemm64_k<<<dim3(32, 3, NB), 256, SMEMSZ64>>>(Wqkv2, hh, qk2, 64, 0, (long)256 * HW, 128, (long)192 * HW, 0, 256, -1);
    tgemm64_k<<<dim3(32, 3, NB), 256, SMEMSZ64>>>(Wqkv3, hh, qk3, 64, 0, (long)256 * HW, 192, (long)192 * HW, 0, 256, -1);
    softmax_k<<<2048, 256>>>(qk2, qk3);
    ctx_k<<<dim3(128, 2), 256>>>(qk2, qk3);
    ctxred_k<<<512, 256>>>();
    mproj_k<<<32, 256>>>(Wproj2, Wproj3);
    // attn output fused with proj: preB ch 128..191 / 192..255 = M[b] @ q[b]
    tgemm64_k<<<dim3(32, 1, NB), 256, SMEMSZ64>>>(Mm,                   qk2, preB, 64, 4096, (long)192 * HW, 0, (long)256 * HW, 128, -1, 512);
    tgemm64_k<<<dim3(32, 1, NB), 256, SMEMSZ64>>>(Mm + (size_t)NB*4096, qk3, preB, 64, 4096, (long)192 * HW, 0, (long)256 * HW, 192, -1, 512);

    // Branch BN params
    finalize_k<<<64, 256>>>(512, gb0, bb0);
    finalize_k<<<64, 256>>>(576, gb1, bb1);
    finalize_k<<<64, 256>>>(640, ga2, ba2);
    finalize_k<<<64, 256>>>(704, ga3, ba3);

    // Final 256->256 conv (BN of preB folded into B loader; stats fused)
    tgemm_k<<<dim3(32, 2, NB), 256, SMEMSZ128>>>(W2, preB, pout, 256, 0, (long)256 * HW, 0, (long)256 * HW, 0, 512, 768);
    finalize_k<<<256, 256>>>(768, g2, b2);
    final_k<<<16384, 256>>>((float*)d_out);
}

// round 10
// speedup vs baseline: 1.2926x; 1.2926x over previous
#include <cuda_runtime.h>
#include <cstdint>
#include <math.h>

#define HW 4096
#define NB 16
#define BK 32
#define NPART 2048

// ---------------- fp32 scratch ----------------
static __device__ float g_tsc [(size_t)NB*256*HW];
static __device__ float g_h   [(size_t)NB*256*HW];
static __device__ float g_qkv2[(size_t)NB*192*HW];
static __device__ float g_qkv3[(size_t)NB*192*HW];
static __device__ float g_preB[(size_t)NB*256*HW];
static __device__ float g_pout[(size_t)NB*256*HW];
static __device__ float g_ctxp[2*NB*8*4096];
static __device__ float g_ctx [2*NB*4096];
static __device__ float g_psum  [(size_t)1024*NPART];
static __device__ float g_psumsq[(size_t)1024*NPART];
static __device__ float g_scale [1024];
static __device__ float g_shift [1024];
// tf32-rounded operand buffers
static __device__ __align__(16) float g_xT [(size_t)NB*128*HW];
static __device__ __align__(16) float g_hT [(size_t)NB*256*HW];   // BN+ReLU applied, tf32
static __device__ __align__(16) float g_pBT[(size_t)NB*256*HW];   // BN+ReLU applied, tf32
static __device__ __align__(16) float g_qT [(size_t)2*NB*64*HW];
static __device__ __align__(16) float g_MmT[2*NB*4096];
static __device__ __align__(16) float g_WT [196608];
#define OFF_WSC 0
#define OFF_W1  32768
#define OFF_WB0 65536
#define OFF_WQ2 69632
#define OFF_WQ3 81920
#define OFF_W2  94208
#define OFF_WC  159744

__device__ __forceinline__ float to_tf32f(float x) {
    float y; asm("cvt.rna.tf32.f32 %0, %1;" : "=f"(y) : "f"(x)); return y;
}
__device__ __forceinline__ void mma8(float* c, const uint32_t* a, const uint32_t* b) {
    asm volatile("mma.sync.aligned.m16n8k8.row.col.f32.tf32.tf32.f32 "
        "{%0,%1,%2,%3}, {%4,%5,%6,%7}, {%8,%9}, {%0,%1,%2,%3};"
        : "+f"(c[0]), "+f"(c[1]), "+f"(c[2]), "+f"(c[3])
        : "r"(a[0]), "r"(a[1]), "r"(a[2]), "r"(a[3]), "r"(b[0]), "r"(b[1]));
}

// smem (floats): A[rows][36], B[32][132] single-buffered (R5-proven layout)
#define AS_OFF 0
#define BS128_OFF 4608
#define SMEMSZ128 ((4608 + 4224) * 4)
#define BS64_OFF 2304
#define SMEMSZ64 ((2304 + 4224) * 4)

#define STATS_EPI(MT_, mexpr_, slotbase_)                                            \
    {                                                                                \
        float s0 = 0.f, q0 = 0.f, s1 = 0.f, q1 = 0.f;                                \
        _Pragma("unroll")                                                            \
        for (int nt = 0; nt < 4; nt++) {                                             \
            s0 += acc[MT_][nt][0] + acc[MT_][nt][1];                                 \
            q0 += acc[MT_][nt][0]*acc[MT_][nt][0] + acc[MT_][nt][1]*acc[MT_][nt][1]; \
            s1 += acc[MT_][nt][2] + acc[MT_][nt][3];                                 \
            q1 += acc[MT_][nt][2]*acc[MT_][nt][2] + acc[MT_][nt][3]*acc[MT_][nt][3]; \
        }                                                                            \
        _Pragma("unroll")                                                            \
        for (int off = 1; off < 4; off <<= 1) {                                      \
            s0 += __shfl_xor_sync(0xffffffffu, s0, off);                             \
            q0 += __shfl_xor_sync(0xffffffffu, q0, off);                             \
            s1 += __shfl_xor_sync(0xffffffffu, s1, off);                             \
            q1 += __shfl_xor_sync(0xffffffffu, q1, off);                             \
        }                                                                            \
        if (qc == 0) {                                                               \
            g_psum  [(size_t)((slotbase_) + (mexpr_)) * NPART + pidx] = s0;          \
            g_psumsq[(size_t)((slotbase_) + (mexpr_)) * NPART + pidx] = q0;          \
            g_psum  [(size_t)((slotbase_) + (mexpr_) + 8) * NPART + pidx] = s1;      \
            g_psumsq[(size_t)((slotbase_) + (mexpr_) + 8) * NPART + pidx] = q1;      \
        }                                                                            \
    }

// ================= 128-row tile tf32 GEMM (R5 core; pure-copy loader) =================
__global__ __launch_bounds__(256, 2) void tgemm_k(
    const float* __restrict__ Wg, const float* __restrict__ A, float* __restrict__ C,
    int K, long wbs, long abs_, int acoff, long cbs, int ccoff, int statslot)
{
    extern __shared__ float sm[];
    const int b = blockIdx.z;
    const float* Wp = Wg + (size_t)b * wbs;
    const float* Ap = A + (size_t)b * abs_ + (size_t)acoff * HW;
    float* Cp = C + (size_t)b * cbs + (size_t)ccoff * HW;
    const int n0 = blockIdx.x * 128, m0 = blockIdx.y * 128;
    const int tid = threadIdx.x, lane = tid & 31, wid = tid >> 5;
    const int wm0 = (wid >> 2) * 64, wn0 = (wid & 3) * 32;
    const int qr = lane >> 2, qc = lane & 3;

    const int fam = tid >> 1, fac = (tid & 1) * 16;
    const int fbk = tid >> 3, fbc = (tid & 7) * 16;
    const int rot = (tid & 7) >> 1;
    const int nk = K / BK;

    float acc[4][4][4];
#pragma unroll
    for (int i = 0; i < 4; i++)
#pragma unroll
        for (int j = 0; j < 4; j++)
#pragma unroll
            for (int e = 0; e < 4; e++) acc[i][j][e] = 0.f;

    for (int kc = 0; kc < nk; kc++) {
        {
            const float* wr = Wp + (size_t)(m0 + fam) * K + kc * BK + fac;   // FIX: m0 restored
            const float* br = Ap + (size_t)(kc * BK + fbk) * HW + n0 + fbc;
            float* das = sm + AS_OFF + fam * 36 + fac;
            float* dbs = sm + BS128_OFF + fbk * 132 + fbc;
#pragma unroll
            for (int t = 0; t < 4; t++)
                *(float4*)(das + t * 4) = *(const float4*)(wr + t * 4);
#pragma unroll
            for (int j = 0; j < 4; j++) {
                const int t = (j + rot) & 3;
                *(float4*)(dbs + t * 4) = *(const float4*)(br + t * 4);
            }
        }
        __syncthreads();
        const uint32_t* as = (const uint32_t*)(sm + AS_OFF);
        const uint32_t* bs = (const uint32_t*)(sm + BS128_OFF);
#pragma unroll
        for (int ks = 0; ks < 4; ks++) {
            uint32_t af[4][4], bf[4][2];
            const int kk = ks * 8 + qc;
#pragma unroll
            for (int mt = 0; mt < 4; mt++) {
                const uint32_t* ap = as + (wm0 + mt * 16 + qr) * 36 + kk;
                af[mt][0] = ap[0];
                af[mt][1] = ap[8 * 36];
                af[mt][2] = ap[4];
                af[mt][3] = ap[8 * 36 + 4];
            }
#pragma unroll
            for (int nt = 0; nt < 4; nt++) {
                const uint32_t* bp = bs + kk * 132 + wn0 + nt * 8 + qr;
                bf[nt][0] = bp[0];
                bf[nt][1] = bp[4 * 132];
            }
#pragma unroll
            for (int mt = 0; mt < 4; mt++)
#pragma unroll
                for (int nt = 0; nt < 4; nt++) mma8(acc[mt][nt], af[mt], bf[nt]);
        }
        __syncthreads();
    }

    const int pidx = (b * 32 + blockIdx.x) * 4 + (wid & 3);
#pragma unroll
    for (int mt = 0; mt < 4; mt++) {
        const int m = m0 + wm0 + mt * 16 + qr;
#pragma unroll
        for (int nt = 0; nt < 4; nt++) {
            const int n = n0 + wn0 + nt * 8 + qc * 2;
            *(float2*)(Cp + (size_t)m * HW + n) = make_float2(acc[mt][nt][0], acc[mt][nt][1]);
            *(float2*)(Cp + (size_t)(m + 8) * HW + n) = make_float2(acc[mt][nt][2], acc[mt][nt][3]);
        }
        if (statslot >= 0) STATS_EPI(mt, ccoff + m, statslot)
    }
}

// ================= 64-row tile tf32 GEMM (R5 core; pure-copy loader) =================
__global__ __launch_bounds__(256, 2) void tgemm64_k(
    const float* __restrict__ Wg, const float* __restrict__ A, float* __restrict__ C,
    int K, long wbs, long abs_, int acoff, long cbs, int ccoff, int statslot)
{
    extern __shared__ float sm[];
    const int b = blockIdx.z;
    const float* Wp = Wg + (size_t)b * wbs;
    const float* Ap = A + (size_t)b * abs_ + (size_t)acoff * HW;
    float* Cp = C + (size_t)b * cbs + (size_t)ccoff * HW;
    const int n0 = blockIdx.x * 128, m0 = blockIdx.y * 64;
    const int tid = threadIdx.x, lane = tid & 31, wid = tid >> 5;
    const int wm0 = (wid >> 2) * 32, wn0 = (wid & 3) * 32;
    const int qr = lane >> 2, qc = lane & 3;

    const int fam = tid >> 2, fac = (tid & 3) * 8;
    const int fbk = tid >> 3, fbc = (tid & 7) * 16;
    const int rot = (tid & 7) >> 1;
    const int nk = K / BK;

    float acc[2][4][4];
#pragma unroll
    for (int i = 0; i < 2; i++)
#pragma unroll
        for (int j = 0; j < 4; j++)
#pragma unroll
            for (int e = 0; e < 4; e++) acc[i][j][e] = 0.f;

    for (int kc = 0; kc < nk; kc++) {
        {
            const float* wr = Wp + (size_t)(m0 + fam) * K + kc * BK + fac;   // FIX: m0 restored
            const float* br = Ap + (size_t)(kc * BK + fbk) * HW + n0 + fbc;
            float* das = sm + AS_OFF + fam * 36 + fac;
            float* dbs = sm + BS64_OFF + fbk * 132 + fbc;
#pragma unroll
            for (int t = 0; t < 2; t++)
                *(float4*)(das + t * 4) = *(const float4*)(wr + t * 4);
#pragma unroll
            for (int j = 0; j < 4; j++) {
                const int t = (j + rot) & 3;
                *(float4*)(dbs + t * 4) = *(const float4*)(br + t * 4);
            }
        }
        __syncthreads();
        const uint32_t* as = (const uint32_t*)(sm + AS_OFF);
        const uint32_t* bs = (const uint32_t*)(sm + BS64_OFF);
#pragma unroll
        for (int ks = 0; ks < 4; ks++) {
            uint32_t af[2][4], bf[4][2];
            const int kk = ks * 8 + qc;
#pragma unroll
            for (int mt = 0; mt < 2; mt++) {
                const uint32_t* ap = as + (wm0 + mt * 16 + qr) * 36 + kk;
                af[mt][0] = ap[0];
                af[mt][1] = ap[8 * 36];
                af[mt][2] = ap[4];
                af[mt][3] = ap[8 * 36 + 4];
            }
#pragma unroll
            for (int nt = 0; nt < 4; nt++) {
                const uint32_t* bp = bs + kk * 132 + wn0 + nt * 8 + qr;
                bf[nt][0] = bp[0];
                bf[nt][1] = bp[4 * 132];
            }
#pragma unroll
            for (int mt = 0; mt < 2; mt++)
#pragma unroll
                for (int nt = 0; nt < 4; nt++) mma8(acc[mt][nt], af[mt], bf[nt]);
        }
        __syncthreads();
    }

    const int pidx = (b * 32 + blockIdx.x) * 4 + (wid & 3);
#pragma unroll
    for (int mt = 0; mt < 2; mt++) {
        const int m = m0 + wm0 + mt * 16 + qr;
#pragma unroll
        for (int nt = 0; nt < 4; nt++) {
            const int n = n0 + wn0 + nt * 8 + qc * 2;
            *(float2*)(Cp + (size_t)m * HW + n) = make_float2(acc[mt][nt][0], acc[mt][nt][1]);
            *(float2*)(Cp + (size_t)(m + 8) * HW + n) = make_float2(acc[mt][nt][2], acc[mt][nt][3]);
        }
        if (statslot >= 0) STATS_EPI(mt, ccoff + m, statslot)
    }
}

// ================= tf32 implicit-GEMM 3x3 conv (R5 core; pre-converted operands) =================
__global__ __launch_bounds__(256, 2) void tconv_k()
{
    extern __shared__ float sm[];
    const int b = blockIdx.z;
    const float* Ap = g_hT + (size_t)b * 256 * HW + (size_t)64 * HW;  // BN+ReLU, tf32
    const float* Wc = g_WT + OFF_WC;                                  // [tap][oc][ic]
    float* Cp = g_preB + (size_t)b * 256 * HW + (size_t)64 * HW;
    const int n0 = blockIdx.x * 128;
    const int tid = threadIdx.x, lane = tid & 31, wid = tid >> 5;
    const int wm0 = (wid >> 2) * 32, wn0 = (wid & 3) * 32;
    const int qr = lane >> 2, qc = lane & 3;
    const int fam = tid >> 2, fac = (tid & 3) * 8;
    const int fbk = tid >> 3, fbc = (tid & 7) * 16;
    const int rot = (tid & 7) >> 1;

    float acc[2][4][4];
#pragma unroll
    for (int i = 0; i < 2; i++)
#pragma unroll
        for (int j = 0; j < 4; j++)
#pragma unroll
            for (int e = 0; e < 4; e++) acc[i][j][e] = 0.f;

    for (int kc = 0; kc < 18; kc++) {
        const int tap = kc >> 1, half = kc & 1;
        const int dy = tap / 3 - 1, dx = tap % 3 - 1;
        {
            // A: repacked weights [tap][oc][64 ic], ic slice half*32..+32 (M=64, no m0 needed)
            const float* wr = Wc + (size_t)tap * 4096 + fam * 64 + half * 32 + fac;
            float* das = sm + AS_OFF + fam * 36 + fac;
            *(float4*)(das)     = *(const float4*)(wr);
            *(float4*)(das + 4) = *(const float4*)(wr + 4);
            // B: shifted masked gather (values already BN+ReLU+tf32; OOB pad = 0 post-activation)
            const int ic = half * 32 + fbk;
            const float* plane = Ap + (size_t)ic * HW;
            float* dbs = sm + BS64_OFF + fbk * 132 + fbc;
#pragma unroll
            for (int j = 0; j < 4; j++) {
                const int t = (j + rot) & 3;
                float4 v;
                float* ve = (float*)&v;
#pragma unroll
                for (int e = 0; e < 4; e++) {
                    int p = n0 + fbc + t * 4 + e;
                    int y = (p >> 6) + dy, x = (p & 63) + dx;
                    float u = 0.f;
                    if ((unsigned)y < 64u && (unsigned)x < 64u) u = plane[y * 64 + x];
                    ve[e] = u;
                }
                *(float4*)(dbs + t * 4) = v;
            }
        }
        __syncthreads();
        const uint32_t* as = (const uint32_t*)(sm + AS_OFF);
        const uint32_t* bs = (const uint32_t*)(sm + BS64_OFF);
#pragma unroll
        for (int ks = 0; ks < 4; ks++) {
            uint32_t af[2][4], bf[4][2];
            const int kk = ks * 8 + qc;
#pragma unroll
            for (int mt = 0; mt < 2; mt++) {
                const uint32_t* ap = as + (wm0 + mt * 16 + qr) * 36 + kk;
                af[mt][0] = ap[0];
                af[mt][1] = ap[8 * 36];
                af[mt][2] = ap[4];
                af[mt][3] = ap[8 * 36 + 4];
            }
#pragma unroll
            for (int nt = 0; nt < 4; nt++) {
                const uint32_t* bp = bs + kk * 132 + wn0 + nt * 8 + qr;
                bf[nt][0] = bp[0];
                bf[nt][1] = bp[4 * 132];
            }
#pragma unroll
            for (int mt = 0; mt < 2; mt++)
#pragma unroll
                for (int nt = 0; nt < 4; nt++) mma8(acc[mt][nt], af[mt], bf[nt]);
        }
        __syncthreads();
    }

    const int pidx = (b * 32 + blockIdx.x) * 4 + (wid & 3);
#pragma unroll
    for (int mt = 0; mt < 2; mt++) {
        const int m = wm0 + mt * 16 + qr;
#pragma unroll
        for (int nt = 0; nt < 4; nt++) {
            const int n = n0 + wn0 + nt * 8 + qc * 2;
            *(float2*)(Cp + (size_t)m * HW + n) = make_float2(acc[mt][nt][0], acc[mt][nt][1]);
            *(float2*)(Cp + (size_t)(m + 8) * HW + n) = make_float2(acc[mt][nt][2], acc[mt][nt][3]);
        }
        STATS_EPI(mt, m, 576)
    }
}

// ---------------- conversion kernels ----------------
__global__ __launch_bounds__(256) void wcvt_k(
    const float* __restrict__ Wsc, const float* __restrict__ W1, const float* __restrict__ Wb0,
    const float* __restrict__ Wq2, const float* __restrict__ Wq3, const float* __restrict__ W2,
    const float* __restrict__ Wb1)
{
    int i = blockIdx.x * 256 + threadIdx.x;
    if (i >= 196608) return;
    float v;
    if (i < 32768)       v = Wsc[i];
    else if (i < 65536)  v = W1[i - 32768];
    else if (i < 69632)  v = Wb0[i - 65536];
    else if (i < 81920)  v = Wq2[i - 69632];
    else if (i < 94208)  v = Wq3[i - 81920];
    else if (i < 159744) v = W2[i - 94208];
    else {
        int e = i - 159744;
        int tap = e >> 12, oc = (e >> 6) & 63, ic = e & 63;
        v = Wb1[oc * 576 + ic * 9 + tap];
    }
    g_WT[i] = to_tf32f(v);
}

__global__ __launch_bounds__(256) void cvtx_k(const float* __restrict__ x)
{
    size_t i = (size_t)blockIdx.x * 256 + threadIdx.x;   // 2,097,152 float4s
    float4 v = ((const float4*)x)[i];
    v.x = to_tf32f(v.x); v.y = to_tf32f(v.y); v.z = to_tf32f(v.z); v.w = to_tf32f(v.w);
    ((float4*)g_xT)[i] = v;
}

__global__ __launch_bounds__(256) void bnreluT_k(const float* __restrict__ src, float* __restrict__ dst, int slot)
{
    size_t i = (size_t)blockIdx.x * 256 + threadIdx.x;   // 4,194,304 float4s
    int c = (int)((i >> 10) & 255);
    float sc = g_scale[slot + c], sh = g_shift[slot + c];
    float4 v = ((const float4*)src)[i];
    v.x = to_tf32f(fmaxf(v.x * sc + sh, 0.f));
    v.y = to_tf32f(fmaxf(v.y * sc + sh, 0.f));
    v.z = to_tf32f(fmaxf(v.z * sc + sh, 0.f));
    v.w = to_tf32f(fmaxf(v.w * sc + sh, 0.f));
    ((float4*)dst)[i] = v;
}

__global__ __launch_bounds__(256) void cvtq_k(const float* __restrict__ q2, const float* __restrict__ q3)
{
    size_t i = (size_t)blockIdx.x * 256 + threadIdx.x;   // 2,097,152 float4s
    int lga = (int)(i >> 20);
    int r = (int)(i & 1048575);
    int b = r >> 16, r2 = r & 65535;
    int c = r2 >> 10, hw4 = r2 & 1023;
    const float* src = (lga ? q3 : q2) + ((size_t)b * 192 + c) * HW + hw4 * 4;
    float4 v = *(const float4*)src;
    v.x = to_tf32f(v.x); v.y = to_tf32f(v.y); v.z = to_tf32f(v.z); v.w = to_tf32f(v.w);
    *(float4*)(g_qT + (((size_t)(lga * 16 + b) * 64 + c) * HW + hw4 * 4)) = v;
}

// ---------------- finalize ----------------
__global__ __launch_bounds__(256) void finalize_k(int slot, const float* __restrict__ gamma, const float* __restrict__ beta)
{
    const int c = blockIdx.x, tid = threadIdx.x;
    const float* ps = g_psum   + (size_t)(slot + c) * NPART;
    const float* pq = g_psumsq + (size_t)(slot + c) * NPART;
    float s = 0.f, q = 0.f;
    for (int i = tid; i < NPART; i += 256) { s += ps[i]; q += pq[i]; }
    __shared__ float ss[256], sq[256];
    ss[tid] = s; sq[tid] = q; __syncthreads();
    for (int st = 128; st > 0; st >>= 1) {
        if (tid < st) { ss[tid] += ss[tid + st]; sq[tid] += sq[tid + st]; }
        __syncthreads();
    }
    if (tid == 0) {
        const float inv = 1.f / 65536.f;
        float m = ss[0] * inv;
        float v = sq[0] * inv - m * m;
        float sc = gamma[c] * rsqrtf(v + 1e-5f);
        g_scale[slot + c] = sc;
        g_shift[slot + c] = beta[c] - m * sc;
    }
}

// ---------------- softmax ----------------
__global__ __launch_bounds__(256) void softmax_k(float* __restrict__ q2, float* __restrict__ q3)
{
    __shared__ float row[4096];
    __shared__ float red[256];
    const int id = blockIdx.x;
    const int lga = id >> 10, rem = id & 1023;
    const int b = rem >> 6, c = rem & 63;
    float* p = (lga ? q3 : q2) + ((size_t)b * 192 + 64 + c) * HW;
    const int tid = threadIdx.x;

    float m = -1e30f;
    for (int i = tid; i < 4096; i += 256) { float v = p[i]; row[i] = v; m = fmaxf(m, v); }
    red[tid] = m; __syncthreads();
    for (int st = 128; st > 0; st >>= 1) { if (tid < st) red[tid] = fmaxf(red[tid], red[tid + st]); __syncthreads(); }
    m = red[0]; __syncthreads();

    float s = 0.f;
    for (int i = tid; i < 4096; i += 256) { float e = expf(row[i] - m); row[i] = e; s += e; }
    red[tid] = s; __syncthreads();
    for (int st = 128; st > 0; st >>= 1) { if (tid < st) red[tid] += red[tid + st]; __syncthreads(); }
    float inv = 1.f / red[0];
    for (int i = tid; i < 4096; i += 256) p[i] = row[i] * inv;
}

// ---------------- ctx ----------------
__global__ __launch_bounds__(256) void ctx_k(const float* __restrict__ q2, const float* __restrict__ q3)
{
    __shared__ float Ks[64][33];
    __shared__ float Vs[64][33];
    const int chunk = blockIdx.x >> 4, b = blockIdx.x & 15, lga = blockIdx.y;
    const float* base = (lga ? q3 : q2) + (size_t)b * 192 * HW;
    const float* kp = base + (size_t)64 * HW;
    const float* vp = base + (size_t)128 * HW;
    const int tid = threadIdx.x;
    const int cb = (tid >> 4) << 2, db = (tid & 15) << 2;

    float acc[4][4];
#pragma unroll
    for (int i = 0; i < 4; i++)
#pragma unroll
        for (int j = 0; j < 4; j++) acc[i][j] = 0.f;

    for (int sub = 0; sub < 16; sub++) {
        const int n0 = chunk * 512 + sub * 32;
        for (int idx = tid; idx < 2048; idx += 256) {
            int r = idx >> 5, cc = idx & 31;
            Ks[r][cc] = kp[(size_t)r * HW + n0 + cc];
            Vs[r][cc] = vp[(size_t)r * HW + n0 + cc];
        }
        __syncthreads();
#pragma unroll 8
        for (int nn = 0; nn < 32; nn++) {
            float kc[4], vd[4];
#pragma unroll
            for (int i = 0; i < 4; i++) { kc[i] = Ks[cb + i][nn]; vd[i] = Vs[db + i][nn]; }
#pragma unroll
            for (int i = 0; i < 4; i++)
#pragma unroll
                for (int j = 0; j < 4; j++) acc[i][j] += kc[i] * vd[j];
        }
        __syncthreads();
    }
    float* cp = g_ctxp + ((size_t)(lga * 16 + b) * 8 + chunk) * 4096;
#pragma unroll
    for (int i = 0; i < 4; i++)
#pragma unroll
        for (int j = 0; j < 4; j++) cp[(cb + i) * 64 + db + j] = acc[i][j];
}

__global__ void ctxred_k()
{
    int i = blockIdx.x * 256 + threadIdx.x;
    if (i >= 2 * NB * 4096) return;
    int pair = i >> 12, e = i & 4095;
    const float* cp = g_ctxp + (size_t)pair * 8 * 4096 + e;
    float s = 0.f;
#pragma unroll
    for (int p = 0; p < 8; p++) s += cp[p * 4096];
    g_ctx[i] = s;
}

// ---------------- M = Wproj @ ctx^T (tf32-rounded out) ----------------
__global__ __launch_bounds__(256) void mproj_k(const float* __restrict__ Wp2, const float* __restrict__ Wp3)
{
    const int id = blockIdx.x;
    const int lga = id >> 4;
    const float* Wp = lga ? Wp3 : Wp2;
    const float* cx = g_ctx + (size_t)id * 4096;
    float* Mo = g_MmT + (size_t)id * 4096;
    for (int e = threadIdx.x; e < 4096; e += 256) {
        int o = e >> 6, c = e & 63;
        float s = 0.f;
#pragma unroll 16
        for (int d = 0; d < 64; d++) s += Wp[o * 64 + d] * cx[c * 64 + d];
        Mo[o * 64 + c] = to_tf32f(s);
    }
}

// ---------------- final ----------------
__global__ __launch_bounds__(256) void final_k(float* __restrict__ out)
{
    size_t i = (size_t)blockIdx.x * 256 + threadIdx.x;
    int c = (int)((i >> 10) & 255);
    float s2 = g_scale[768 + c], h2v = g_shift[768 + c];
    float s0 = g_scale[c],       h0v = g_shift[c];
    float4 p = ((const float4*)g_pout)[i];
    float4 r = ((const float4*)g_tsc)[i];
    p.x = fmaxf(p.x * s2 + h2v + r.x * s0 + h0v, 0.f);
    p.y = fmaxf(p.y * s2 + h2v + r.y * s0 + h0v, 0.f);
    p.z = fmaxf(p.z * s2 + h2v + r.z * s0 + h0v, 0.f);
    p.w = fmaxf(p.w * s2 + h2v + r.w * s0 + h0v, 0.f);
    ((float4*)out)[i] = p;
}

// ---------------- launch ----------------
extern "C" void kernel_launch(void* const* d_in, const int* in_sizes, int n_in,
                              void* d_out, int out_size)
{
    (void)in_sizes; (void)n_in; (void)out_size;
    const float* x      = (const float*)d_in[0];
    const float* W_sc   = (const float*)d_in[1];
    const float* gsc    = (const float*)d_in[2];
    const float* bsc    = (const float*)d_in[3];
    const float* W1     = (const float*)d_in[4];
    const float* g1     = (const float*)d_in[5];
    const float* b1     = (const float*)d_in[6];
    const float* Wb0    = (const float*)d_in[7];
    const float* gb0    = (const float*)d_in[8];
    const float* bb0    = (const float*)d_in[9];
    const float* Wb1    = (const float*)d_in[10];
    const float* gb1    = (const float*)d_in[11];
    const float* bb1    = (const float*)d_in[12];
    const float* Wqkv2  = (const float*)d_in[13];
    const float* Wproj2 = (const float*)d_in[14];
    const float* ga2    = (const float*)d_in[15];
    const float* ba2    = (const float*)d_in[16];
    const float* Wqkv3  = (const float*)d_in[17];
    const float* Wproj3 = (const float*)d_in[18];
    const float* ga3    = (const float*)d_in[19];
    const float* ba3    = (const float*)d_in[20];
    const float* W2     = (const float*)d_in[21];
    const float* g2     = (const float*)d_in[22];
    const float* b2     = (const float*)d_in[23];

    float *tsc, *hh, *qk2, *qk3, *preB, *pout;
    float *xT, *hT, *pBT, *qT, *MmT, *WT;
    cudaGetSymbolAddress((void**)&tsc,  g_tsc);
    cudaGetSymbolAddress((void**)&hh,   g_h);
    cudaGetSymbolAddress((void**)&qk2,  g_qkv2);
    cudaGetSymbolAddress((void**)&qk3,  g_qkv3);
    cudaGetSymbolAddress((void**)&preB, g_preB);
    cudaGetSymbolAddress((void**)&pout, g_pout);
    cudaGetSymbolAddress((void**)&xT,   g_xT);
    cudaGetSymbolAddress((void**)&hT,   g_hT);
    cudaGetSymbolAddress((void**)&pBT,  g_pBT);
    cudaGetSymbolAddress((void**)&qT,   g_qT);
    cudaGetSymbolAddress((void**)&MmT,  g_MmT);
    cudaGetSymbolAddress((void**)&WT,   g_WT);

    // operand pre-conversion (tf32 rounding, BN folded where known)
    wcvt_k<<<768, 256>>>(W_sc, W1, Wb0, Wqkv2, Wqkv3, W2, Wb1);
    cvtx_k<<<8192, 256>>>(x);

    // Stage 1: two 128->256 GEMMs; stats fused
    tgemm_k<<<dim3(32, 2, NB), 256, SMEMSZ128>>>(WT + OFF_WSC, xT, tsc, 128, 0, (long)128 * HW, 0, (long)256 * HW, 0, 0);
    tgemm_k<<<dim3(32, 2, NB), 256, SMEMSZ128>>>(WT + OFF_W1,  xT, hh,  128, 0, (long)128 * HW, 0, (long)256 * HW, 0, 256);
    finalize_k<<<256, 256>>>(0,   gsc, bsc);
    finalize_k<<<256, 256>>>(256, g1,  b1);
    bnreluT_k<<<16384, 256>>>(hh, hT, 256);

    // Branch 0: 1x1 conv on s0
    tgemm64_k<<<dim3(32, 1, NB), 256, SMEMSZ64>>>(WT + OFF_WB0, hT, preB, 64, 0, (long)256 * HW, 0, (long)256 * HW, 0, 512);
    // Branch 1: 3x3 conv (implicit GEMM)
    tconv_k<<<dim3(32, 1, NB), 256, SMEMSZ64>>>();
    // Branches 2/3: qkv projections (s2 = hT ch 128.., s3 = hT ch 192..)
    tgemm64_k<<<dim3(32, 3, NB), 256, SMEMSZ64>>>(WT + OFF_WQ2, hT, qk2, 64, 0, (long)256 * HW, 128, (long)192 * HW, 0, -1);
    tgemm64_k<<<dim3(32, 3, NB), 256, SMEMSZ64>>>(WT + OFF_WQ3, hT, qk3, 64, 0, (long)256 * HW, 192, (long)192 * HW, 0, -1);
    cvtq_k<<<8192, 256>>>(qk2, qk3);
    softmax_k<<<2048, 256>>>(qk2, qk3);
    ctx_k<<<dim3(128, 2), 256>>>(qk2, qk3);
    ctxred_k<<<512, 256>>>();
    mproj_k<<<32, 256>>>(Wproj2, Wproj3);
    // attn out = M @ q
    tgemm64_k<<<dim3(32, 1, NB), 256, SMEMSZ64>>>(MmT,             qT,                        preB, 64, 4096, (long)64 * HW, 0, (long)256 * HW, 128, 512);
    tgemm64_k<<<dim3(32, 1, NB), 256, SMEMSZ64>>>(MmT + 16 * 4096, qT + (size_t)16 * 64 * HW, preB, 64, 4096, (long)64 * HW, 0, (long)256 * HW, 192, 512);

    // Branch BN params
    finalize_k<<<64, 256>>>(512, gb0, bb0);
    finalize_k<<<64, 256>>>(576, gb1, bb1);
    finalize_k<<<64, 256>>>(640, ga2, ba2);
    finalize_k<<<64, 256>>>(704, ga3, ba3);
    bnreluT_k<<<16384, 256>>>(preB, pBT, 512);

    // Final 256->256 GEMM
    tgemm_k<<<dim3(32, 2, NB), 256, SMEMSZ128>>>(WT + OFF_W2, pBT, pout, 256, 0, (long)256 * HW, 0, (long)256 * HW, 0, 768);
    finalize_k<<<256, 256>>>(768, g2, b2);
    final_k<<<16384, 256>>>((float*)d_out);
}

// round 11
// speedup vs baseline: 1.6366x; 1.2661x over previous
#include <cuda_runtime.h>
#include <cuda_fp16.h>
#include <cstdint>
#include <math.h>

#define HW 4096
#define NB 16
#define NPART 2048

// ---------------- fp32 scratch ----------------
static __device__ float  g_tsc [(size_t)NB*256*HW];
static __device__ float  g_h   [(size_t)NB*256*HW];
static __device__ float  g_qkv2[(size_t)NB*192*HW];
static __device__ float  g_qkv3[(size_t)NB*192*HW];
static __device__ float  g_preB[(size_t)NB*256*HW];
static __device__ float  g_pout[(size_t)NB*256*HW];
static __device__ float  g_ctxp[2*NB*8*4096];
static __device__ float  g_ctx [2*NB*4096];
static __device__ float  g_psum  [(size_t)1024*NPART];
static __device__ float  g_psumsq[(size_t)1024*NPART];
static __device__ float  g_scale [1024];
static __device__ float  g_shift [1024];
// fp16 operand buffers (16B-aligned: cp.async sources)
static __device__ __align__(16) __half g_x16 [(size_t)NB*128*HW];
static __device__ __align__(16) __half g_h16 [(size_t)NB*256*HW];
static __device__ __align__(16) __half g_pB16[(size_t)NB*256*HW];
static __device__ __align__(16) __half g_q16 [(size_t)2*NB*64*HW];
static __device__ __align__(16) __half g_Mm16[2*NB*4096];
static __device__ __align__(16) __half g_W16 [196608];
#define OFF_WSC 0
#define OFF_W1  32768
#define OFF_WB0 65536
#define OFF_WQ2 69632
#define OFF_WQ3 81920
#define OFF_W2  94208
#define OFF_WC  159744

__device__ __forceinline__ uint32_t pk2(float a, float b) {
    __half2 h = __floats2half2_rn(a, b);
    return *(uint32_t*)&h;
}
__device__ __forceinline__ void mma16(float* c, const uint32_t* a, const uint32_t* b) {
    asm volatile("mma.sync.aligned.m16n8k16.row.col.f32.f16.f16.f32 "
        "{%0,%1,%2,%3}, {%4,%5,%6,%7}, {%8,%9}, {%0,%1,%2,%3};"
        : "+f"(c[0]), "+f"(c[1]), "+f"(c[2]), "+f"(c[3])
        : "r"(a[0]), "r"(a[1]), "r"(a[2]), "r"(a[3]), "r"(b[0]), "r"(b[1]));
}
__device__ __forceinline__ void cpa16(uint32_t dst, const void* src) {
    asm volatile("cp.async.ca.shared.global [%0], [%1], 16;" :: "r"(dst), "l"(src));
}
#define CP_COMMIT() asm volatile("cp.async.commit_group;")
#define CP_WAIT(n)  asm volatile("cp.async.wait_group %0;" :: "n"(n))
#define LDSM4(r0,r1,r2,r3,addr) \
    asm volatile("ldmatrix.sync.aligned.m8n8.x4.shared.b16 {%0,%1,%2,%3}, [%4];" \
        : "=r"(r0), "=r"(r1), "=r"(r2), "=r"(r3) : "r"(addr))
#define LDSM4T(r0,r1,r2,r3,addr) \
    asm volatile("ldmatrix.sync.aligned.m8n8.x4.trans.shared.b16 {%0,%1,%2,%3}, [%4];" \
        : "=r"(r0), "=r"(r1), "=r"(r2), "=r"(r3) : "r"(addr))

// smem layout (bytes): A rows 80B (32 halfs + pad), B rows 272B (128 halfs + pad)
#define AROW 80
#define BROW 272
#define ABUF128 10240
#define ABUF64  5120
#define BBUF    8704
#define SM128 (2*ABUF128 + 2*BBUF)   // 37888
#define SM64  (2*ABUF64  + 2*BBUF)   // 27648
#define SMCV  (ABUF64 + BBUF)        // 13824

#define STATS_EPI(MT_, mexpr_, slotbase_)                                            \
    {                                                                                \
        float s0 = 0.f, q0 = 0.f, s1 = 0.f, q1 = 0.f;                                \
        _Pragma("unroll")                                                            \
        for (int nt = 0; nt < 4; nt++) {                                             \
            s0 += acc[MT_][nt][0] + acc[MT_][nt][1];                                 \
            q0 += acc[MT_][nt][0]*acc[MT_][nt][0] + acc[MT_][nt][1]*acc[MT_][nt][1]; \
            s1 += acc[MT_][nt][2] + acc[MT_][nt][3];                                 \
            q1 += acc[MT_][nt][2]*acc[MT_][nt][2] + acc[MT_][nt][3]*acc[MT_][nt][3]; \
        }                                                                            \
        _Pragma("unroll")                                                            \
        for (int off = 1; off < 4; off <<= 1) {                                      \
            s0 += __shfl_xor_sync(0xffffffffu, s0, off);                             \
            q0 += __shfl_xor_sync(0xffffffffu, q0, off);                             \
            s1 += __shfl_xor_sync(0xffffffffu, s1, off);                             \
            q1 += __shfl_xor_sync(0xffffffffu, q1, off);                             \
        }                                                                            \
        if (qc == 0) {                                                               \
            g_psum  [(size_t)((slotbase_) + (mexpr_)) * NPART + pidx] = s0;          \
            g_psumsq[(size_t)((slotbase_) + (mexpr_)) * NPART + pidx] = q0;          \
            g_psum  [(size_t)((slotbase_) + (mexpr_) + 8) * NPART + pidx] = s1;      \
            g_psumsq[(size_t)((slotbase_) + (mexpr_) + 8) * NPART + pidx] = q1;      \
        }                                                                            \
    }

// ================= 128-row tile fp16 GEMM, cp.async double-buffered =================
__global__ __launch_bounds__(256, 2) void tg16_k(
    const __half* __restrict__ Wg, const __half* __restrict__ A16, float* __restrict__ C,
    int K, long wbs, long abs16, int acoff, long cbs, int ccoff, int statslot)
{
    extern __shared__ char smem[];
    const uint32_t sbase = (uint32_t)__cvta_generic_to_shared(smem);
    const int b = blockIdx.z;
    const __half* Wp = Wg + (size_t)b * wbs;
    const __half* Ap = A16 + (size_t)b * abs16 + (size_t)acoff * HW;
    float* Cp = C + (size_t)b * cbs + (size_t)ccoff * HW;
    const int n0 = blockIdx.x * 128, m0 = blockIdx.y * 128;
    const int tid = threadIdx.x, lane = tid & 31, wid = tid >> 5;
    const int wm0 = (wid >> 2) * 64, wn0 = (wid & 3) * 32;
    const int qr = lane >> 2, qc = lane & 3;
    const int nk = K / 32;
    const int ar = tid >> 1, ac = (tid & 1) * 2;
    const int br = tid >> 3, bc = tid & 7;
    const int l15 = lane & 15, l8 = (lane >> 4) << 3;

    float acc[4][4][4];
#pragma unroll
    for (int i = 0; i < 4; i++)
#pragma unroll
        for (int j = 0; j < 4; j++)
#pragma unroll
            for (int e = 0; e < 4; e++) acc[i][j][e] = 0.f;

    // prologue: chunk 0 into buf 0
    {
        uint32_t da = sbase + ar * AROW + ac * 16;
        const __half* sa = Wp + (size_t)(m0 + ar) * K + ac * 8;      // FIX: m0
        cpa16(da, sa); cpa16(da + 16, sa + 8);
        uint32_t db = sbase + 2 * ABUF128 + br * BROW + bc * 16;
        const __half* sb = Ap + (size_t)br * HW + n0 + bc * 8;
        cpa16(db, sb); cpa16(db + 128, sb + 64);
    }
    CP_COMMIT();

    for (int kc = 0; kc < nk; kc++) {
        const int buf = kc & 1;
        if (kc + 1 < nk) {
            const int nb = buf ^ 1, k1 = kc + 1;
            uint32_t da = sbase + nb * ABUF128 + ar * AROW + ac * 16;
            const __half* sa = Wp + (size_t)(m0 + ar) * K + k1 * 32 + ac * 8;   // FIX: m0
            cpa16(da, sa); cpa16(da + 16, sa + 8);
            uint32_t db = sbase + 2 * ABUF128 + nb * BBUF + br * BROW + bc * 16;
            const __half* sb = Ap + (size_t)(k1 * 32 + br) * HW + n0 + bc * 8;
            cpa16(db, sb); cpa16(db + 128, sb + 64);
            CP_COMMIT();
            CP_WAIT(1);
        } else {
            CP_WAIT(0);
        }
        __syncthreads();
        const uint32_t ab = sbase + buf * ABUF128;
        const uint32_t bb = sbase + 2 * ABUF128 + buf * BBUF;
#pragma unroll
        for (int ks = 0; ks < 2; ks++) {
            const int kb = ks * 16;
            uint32_t af[4][4], bf[2][4];
#pragma unroll
            for (int mt = 0; mt < 4; mt++)
                LDSM4(af[mt][0], af[mt][1], af[mt][2], af[mt][3],
                      ab + (wm0 + mt * 16 + l15) * AROW + (kb + l8) * 2);
#pragma unroll
            for (int nh = 0; nh < 2; nh++)
                LDSM4T(bf[nh][0], bf[nh][1], bf[nh][2], bf[nh][3],
                       bb + (kb + l15) * BROW + (wn0 + nh * 16 + l8) * 2);
#pragma unroll
            for (int mt = 0; mt < 4; mt++)
#pragma unroll
                for (int nt = 0; nt < 4; nt++)
                    mma16(acc[mt][nt], af[mt], &bf[nt >> 1][(nt & 1) * 2]);
        }
        __syncthreads();
    }

    const int pidx = (b * 32 + blockIdx.x) * 4 + (wid & 3);
#pragma unroll
    for (int mt = 0; mt < 4; mt++) {
        const int m = m0 + wm0 + mt * 16 + qr;
#pragma unroll
        for (int nt = 0; nt < 4; nt++) {
            const int n = n0 + wn0 + nt * 8 + qc * 2;
            *(float2*)(Cp + (size_t)m * HW + n) = make_float2(acc[mt][nt][0], acc[mt][nt][1]);
            *(float2*)(Cp + (size_t)(m + 8) * HW + n) = make_float2(acc[mt][nt][2], acc[mt][nt][3]);
        }
        if (statslot >= 0) STATS_EPI(mt, ccoff + m, statslot)
    }
}

// ================= 64-row tile fp16 GEMM =================
__global__ __launch_bounds__(256, 2) void tg16_64_k(
    const __half* __restrict__ Wg, const __half* __restrict__ A16, float* __restrict__ C,
    int K, long wbs, long abs16, int acoff, long cbs, int ccoff, int statslot)
{
    extern __shared__ char smem[];
    const uint32_t sbase = (uint32_t)__cvta_generic_to_shared(smem);
    const int b = blockIdx.z;
    const __half* Wp = Wg + (size_t)b * wbs;
    const __half* Ap = A16 + (size_t)b * abs16 + (size_t)acoff * HW;
    float* Cp = C + (size_t)b * cbs + (size_t)ccoff * HW;
    const int n0 = blockIdx.x * 128, m0 = blockIdx.y * 64;
    const int tid = threadIdx.x, lane = tid & 31, wid = tid >> 5;
    const int wm0 = (wid >> 2) * 32, wn0 = (wid & 3) * 32;
    const int qr = lane >> 2, qc = lane & 3;
    const int nk = K / 32;
    const int ar = tid >> 2, ac = tid & 3;
    const int br = tid >> 3, bc = tid & 7;
    const int l15 = lane & 15, l8 = (lane >> 4) << 3;

    float acc[2][4][4];
#pragma unroll
    for (int i = 0; i < 2; i++)
#pragma unroll
        for (int j = 0; j < 4; j++)
#pragma unroll
            for (int e = 0; e < 4; e++) acc[i][j][e] = 0.f;

    {
        cpa16(sbase + ar * AROW + ac * 16, Wp + (size_t)(m0 + ar) * K + ac * 8);   // FIX: m0
        uint32_t db = sbase + 2 * ABUF64 + br * BROW + bc * 16;
        const __half* sb = Ap + (size_t)br * HW + n0 + bc * 8;
        cpa16(db, sb); cpa16(db + 128, sb + 64);
    }
    CP_COMMIT();

    for (int kc = 0; kc < nk; kc++) {
        const int buf = kc & 1;
        if (kc + 1 < nk) {
            const int nb = buf ^ 1, k1 = kc + 1;
            cpa16(sbase + nb * ABUF64 + ar * AROW + ac * 16,
                  Wp + (size_t)(m0 + ar) * K + k1 * 32 + ac * 8);                  // FIX: m0
            uint32_t db = sbase + 2 * ABUF64 + nb * BBUF + br * BROW + bc * 16;
            const __half* sb = Ap + (size_t)(k1 * 32 + br) * HW + n0 + bc * 8;
            cpa16(db, sb); cpa16(db + 128, sb + 64);
            CP_COMMIT();
            CP_WAIT(1);
        } else {
            CP_WAIT(0);
        }
        __syncthreads();
        const uint32_t ab = sbase + buf * ABUF64;
        const uint32_t bb = sbase + 2 * ABUF64 + buf * BBUF;
#pragma unroll
        for (int ks = 0; ks < 2; ks++) {
            const int kb = ks * 16;
            uint32_t af[2][4], bf[2][4];
#pragma unroll
            for (int mt = 0; mt < 2; mt++)
                LDSM4(af[mt][0], af[mt][1], af[mt][2], af[mt][3],
                      ab + (wm0 + mt * 16 + l15) * AROW + (kb + l8) * 2);
#pragma unroll
            for (int nh = 0; nh < 2; nh++)
                LDSM4T(bf[nh][0], bf[nh][1], bf[nh][2], bf[nh][3],
                       bb + (kb + l15) * BROW + (wn0 + nh * 16 + l8) * 2);
#pragma unroll
            for (int mt = 0; mt < 2; mt++)
#pragma unroll
                for (int nt = 0; nt < 4; nt++)
                    mma16(acc[mt][nt], af[mt], &bf[nt >> 1][(nt & 1) * 2]);
        }
        __syncthreads();
    }

    const int pidx = (b * 32 + blockIdx.x) * 4 + (wid & 3);
#pragma unroll
    for (int mt = 0; mt < 2; mt++) {
        const int m = m0 + wm0 + mt * 16 + qr;
#pragma unroll
        for (int nt = 0; nt < 4; nt++) {
            const int n = n0 + wn0 + nt * 8 + qc * 2;
            *(float2*)(Cp + (size_t)m * HW + n) = make_float2(acc[mt][nt][0], acc[mt][nt][1]);
            *(float2*)(Cp + (size_t)(m + 8) * HW + n) = make_float2(acc[mt][nt][2], acc[mt][nt][3]);
        }
        if (statslot >= 0) STATS_EPI(mt, ccoff + m, statslot)
    }
}

// ================= fp16 implicit-GEMM 3x3 conv (single-buffer, M=64) =================
__global__ __launch_bounds__(256, 2) void tcv16_k()
{
    extern __shared__ char smem[];
    const uint32_t sbase = (uint32_t)__cvta_generic_to_shared(smem);
    const int b = blockIdx.z;
    const __half* Ap = g_h16 + (size_t)b * 256 * HW + (size_t)64 * HW;  // BN+ReLU applied
    const __half* Wc = g_W16 + OFF_WC;
    float* Cp = g_preB + (size_t)b * 256 * HW + (size_t)64 * HW;
    const int n0 = blockIdx.x * 128;
    const int tid = threadIdx.x, lane = tid & 31, wid = tid >> 5;
    const int wm0 = (wid >> 2) * 32, wn0 = (wid & 3) * 32;
    const int qr = lane >> 2, qc = lane & 3;
    const int l15 = lane & 15, l8 = (lane >> 4) << 3;

    float acc[2][4][4];
#pragma unroll
    for (int i = 0; i < 2; i++)
#pragma unroll
        for (int j = 0; j < 4; j++)
#pragma unroll
            for (int e = 0; e < 4; e++) acc[i][j][e] = 0.f;

    for (int kc = 0; kc < 18; kc++) {
        const int tap = kc >> 1, half = kc & 1;
        const int dy = tap / 3 - 1, dx = tap % 3 - 1;
        // A: Wc16[tap][oc][half*32 .. +32]
        {
            const int row = tid >> 2, c = tid & 3;
            uint4 v = *(const uint4*)(Wc + (size_t)tap * 4096 + row * 64 + half * 32 + c * 8);
            *(uint4*)(smem + row * AROW + c * 16) = v;
        }
        // B: masked shifted gather from h16 plane ([k][n] halfs)
        {
            const int r = tid >> 3, g = tid & 7;
            const int ic = half * 32 + r;
            const __half* plane = Ap + (size_t)ic * HW;
            uint32_t w[8];
#pragma unroll
            for (int jj = 0; jj < 8; jj++) {
                uint32_t lohi[2];
#pragma unroll
                for (int e = 0; e < 2; e++) {
                    int p = n0 + g * 16 + jj * 2 + e;
                    int y = (p >> 6) + dy, x = (p & 63) + dx;
                    __half u = __float2half(0.f);
                    if ((unsigned)y < 64u && (unsigned)x < 64u) u = plane[y * 64 + x];
                    lohi[e] = (uint32_t)*(uint16_t*)&u;
                }
                w[jj] = lohi[0] | (lohi[1] << 16);
            }
            char* db = smem + ABUF64 + r * BROW + g * 32;
            *(uint4*)(db)      = make_uint4(w[0], w[1], w[2], w[3]);
            *(uint4*)(db + 16) = make_uint4(w[4], w[5], w[6], w[7]);
        }
        __syncthreads();
        const uint32_t ab = sbase;
        const uint32_t bb = sbase + ABUF64;
#pragma unroll
        for (int ks = 0; ks < 2; ks++) {
            const int kb = ks * 16;
            uint32_t af[2][4], bf[2][4];
#pragma unroll
            for (int mt = 0; mt < 2; mt++)
                LDSM4(af[mt][0], af[mt][1], af[mt][2], af[mt][3],
                      ab + (wm0 + mt * 16 + l15) * AROW + (kb + l8) * 2);
#pragma unroll
            for (int nh = 0; nh < 2; nh++)
                LDSM4T(bf[nh][0], bf[nh][1], bf[nh][2], bf[nh][3],
                       bb + (kb + l15) * BROW + (wn0 + nh * 16 + l8) * 2);
#pragma unroll
            for (int mt = 0; mt < 2; mt++)
#pragma unroll
                for (int nt = 0; nt < 4; nt++)
                    mma16(acc[mt][nt], af[mt], &bf[nt >> 1][(nt & 1) * 2]);
        }
        __syncthreads();
    }

    const int pidx = (b * 32 + blockIdx.x) * 4 + (wid & 3);
#pragma unroll
    for (int mt = 0; mt < 2; mt++) {
        const int m = wm0 + mt * 16 + qr;
#pragma unroll
        for (int nt = 0; nt < 4; nt++) {
            const int n = n0 + wn0 + nt * 8 + qc * 2;
            *(float2*)(Cp + (size_t)m * HW + n) = make_float2(acc[mt][nt][0], acc[mt][nt][1]);
            *(float2*)(Cp + (size_t)(m + 8) * HW + n) = make_float2(acc[mt][nt][2], acc[mt][nt][3]);
        }
        STATS_EPI(mt, m, 576)
    }
}

// ---------------- conversion kernels ----------------
__global__ __launch_bounds__(256) void wcvt_k(
    const float* __restrict__ Wsc, const float* __restrict__ W1, const float* __restrict__ Wb0,
    const float* __restrict__ Wq2, const float* __restrict__ Wq3, const float* __restrict__ W2,
    const float* __restrict__ Wb1)
{
    int i = blockIdx.x * 256 + threadIdx.x;
    if (i >= 196608) return;
    float v;
    if (i < 32768)       v = Wsc[i];
    else if (i < 65536)  v = W1[i - 32768];
    else if (i < 69632)  v = Wb0[i - 65536];
    else if (i < 81920)  v = Wq2[i - 69632];
    else if (i < 94208)  v = Wq3[i - 81920];
    else if (i < 159744) v = W2[i - 94208];
    else {
        int e = i - 159744;
        int tap = e >> 12, oc = (e >> 6) & 63, ic = e & 63;
        v = Wb1[oc * 576 + ic * 9 + tap];
    }
    g_W16[i] = __float2half(v);
}

__global__ __launch_bounds__(256) void cvtx_k(const float* __restrict__ x)
{
    size_t i = (size_t)blockIdx.x * 256 + threadIdx.x;   // 2,097,152 float4s
    float4 v = ((const float4*)x)[i];
    *(uint2*)(g_x16 + i * 4) = make_uint2(pk2(v.x, v.y), pk2(v.z, v.w));
}

__global__ __launch_bounds__(256) void bnrelu16_k(const float* __restrict__ src, __half* __restrict__ dst, int slot)
{
    size_t i = (size_t)blockIdx.x * 256 + threadIdx.x;   // 4,194,304 float4s
    int c = (int)((i >> 10) & 255);
    float sc = g_scale[slot + c], sh = g_shift[slot + c];
    float4 v = ((const float4*)src)[i];
    v.x = fmaxf(v.x * sc + sh, 0.f);
    v.y = fmaxf(v.y * sc + sh, 0.f);
    v.z = fmaxf(v.z * sc + sh, 0.f);
    v.w = fmaxf(v.w * sc + sh, 0.f);
    *(uint2*)(dst + i * 4) = make_uint2(pk2(v.x, v.y), pk2(v.z, v.w));
}

__global__ __launch_bounds__(256) void cvtq_k(const float* __restrict__ q2, const float* __restrict__ q3)
{
    size_t i = (size_t)blockIdx.x * 256 + threadIdx.x;   // 2,097,152 float4s
    int lga = (int)(i >> 20);
    int r = (int)(i & 1048575);
    int b = r >> 16, r2 = r & 65535;
    int c = r2 >> 10, hw4 = r2 & 1023;
    const float* src = (lga ? q3 : q2) + ((size_t)b * 192 + c) * HW + hw4 * 4;
    float4 v = *(const float4*)src;
    __half* dst = g_q16 + (((size_t)(lga * 16 + b) * 64 + c) * HW + hw4 * 4);
    *(uint2*)dst = make_uint2(pk2(v.x, v.y), pk2(v.z, v.w));
}

// ---------------- finalize ----------------
__global__ __launch_bounds__(256) void finalize_k(int slot, const float* __restrict__ gamma, const float* __restrict__ beta)
{
    const int c = blockIdx.x, tid = threadIdx.x;
    const float* ps = g_psum   + (size_t)(slot + c) * NPART;
    const float* pq = g_psumsq + (size_t)(slot + c) * NPART;
    float s = 0.f, q = 0.f;
    for (int i = tid; i < NPART; i += 256) { s += ps[i]; q += pq[i]; }
    __shared__ float ss[256], sq[256];
    ss[tid] = s; sq[tid] = q; __syncthreads();
    for (int st = 128; st > 0; st >>= 1) {
        if (tid < st) { ss[tid] += ss[tid + st]; sq[tid] += sq[tid + st]; }
        __syncthreads();
    }
    if (tid == 0) {
        const float inv = 1.f / 65536.f;
        float m = ss[0] * inv;
        float v = sq[0] * inv - m * m;
        float sc = gamma[c] * rsqrtf(v + 1e-5f);
        g_scale[slot + c] = sc;
        g_shift[slot + c] = beta[c] - m * sc;
    }
}

// ---------------- softmax ----------------
__global__ __launch_bounds__(256) void softmax_k(float* __restrict__ q2, float* __restrict__ q3)
{
    __shared__ float row[4096];
    __shared__ float red[256];
    const int id = blockIdx.x;
    const int lga = id >> 10, rem = id & 1023;
    const int b = rem >> 6, c = rem & 63;
    float* p = (lga ? q3 : q2) + ((size_t)b * 192 + 64 + c) * HW;
    const int tid = threadIdx.x;

    float m = -1e30f;
    for (int i = tid; i < 4096; i += 256) { float v = p[i]; row[i] = v; m = fmaxf(m, v); }
    red[tid] = m; __syncthreads();
    for (int st = 128; st > 0; st >>= 1) { if (tid < st) red[tid] = fmaxf(red[tid], red[tid + st]); __syncthreads(); }
    m = red[0]; __syncthreads();

    float s = 0.f;
    for (int i = tid; i < 4096; i += 256) { float e = expf(row[i] - m); row[i] = e; s += e; }
    red[tid] = s; __syncthreads();
    for (int st = 128; st > 0; st >>= 1) { if (tid < st) red[tid] += red[tid + st]; __syncthreads(); }
    float inv = 1.f / red[0];
    for (int i = tid; i < 4096; i += 256) p[i] = row[i] * inv;
}

// ---------------- ctx ----------------
__global__ __launch_bounds__(256) void ctx_k(const float* __restrict__ q2, const float* __restrict__ q3)
{
    __shared__ float Ks[64][33];
    __shared__ float Vs[64][33];
    const int chunk = blockIdx.x >> 4, b = blockIdx.x & 15, lga = blockIdx.y;
    const float* base = (lga ? q3 : q2) + (size_t)b * 192 * HW;
    const float* kp = base + (size_t)64 * HW;
    const float* vp = base + (size_t)128 * HW;
    const int tid = threadIdx.x;
    const int cb = (tid >> 4) << 2, db = (tid & 15) << 2;

    float acc[4][4];
#pragma unroll
    for (int i = 0; i < 4; i++)
#pragma unroll
        for (int j = 0; j < 4; j++) acc[i][j] = 0.f;

    for (int sub = 0; sub < 16; sub++) {
        const int n0 = chunk * 512 + sub * 32;
        for (int idx = tid; idx < 2048; idx += 256) {
            int r = idx >> 5, cc = idx & 31;
            Ks[r][cc] = kp[(size_t)r * HW + n0 + cc];
            Vs[r][cc] = vp[(size_t)r * HW + n0 + cc];
        }
        __syncthreads();
#pragma unroll 8
        for (int nn = 0; nn < 32; nn++) {
            float kc[4], vd[4];
#pragma unroll
            for (int i = 0; i < 4; i++) { kc[i] = Ks[cb + i][nn]; vd[i] = Vs[db + i][nn]; }
#pragma unroll
            for (int i = 0; i < 4; i++)
#pragma unroll
                for (int j = 0; j < 4; j++) acc[i][j] += kc[i] * vd[j];
        }
        __syncthreads();
    }
    float* cp = g_ctxp + ((size_t)(lga * 16 + b) * 8 + chunk) * 4096;
#pragma unroll
    for (int i = 0; i < 4; i++)
#pragma unroll
        for (int j = 0; j < 4; j++) cp[(cb + i) * 64 + db + j] = acc[i][j];
}

__global__ void ctxred_k()
{
    int i = blockIdx.x * 256 + threadIdx.x;
    if (i >= 2 * NB * 4096) return;
    int pair = i >> 12, e = i & 4095;
    const float* cp = g_ctxp + (size_t)pair * 8 * 4096 + e;
    float s = 0.f;
#pragma unroll
    for (int p = 0; p < 8; p++) s += cp[p * 4096];
    g_ctx[i] = s;
}

// ---------------- M = Wproj @ ctx^T (fp16 out) ----------------
__global__ __launch_bounds__(256) void mproj_k(const float* __restrict__ Wp2, const float* __restrict__ Wp3)
{
    const int id = blockIdx.x;
    const int lga = id >> 4;
    const float* Wp = lga ? Wp3 : Wp2;
    const float* cx = g_ctx + (size_t)id * 4096;
    __half* Mo = g_Mm16 + (size_t)id * 4096;
    for (int e = threadIdx.x; e < 4096; e += 256) {
        int o = e >> 6, c = e & 63;
        float s = 0.f;
#pragma unroll 16
        for (int d = 0; d < 64; d++) s += Wp[o * 64 + d] * cx[c * 64 + d];
        Mo[o * 64 + c] = __float2half(s);
    }
}

// ---------------- final ----------------
__global__ __launch_bounds__(256) void final_k(float* __restrict__ out)
{
    size_t i = (size_t)blockIdx.x * 256 + threadIdx.x;
    int c = (int)((i >> 10) & 255);
    float s2 = g_scale[768 + c], h2v = g_shift[768 + c];
    float s0 = g_scale[c],       h0v = g_shift[c];
    float4 p = ((const float4*)g_pout)[i];
    float4 r = ((const float4*)g_tsc)[i];
    p.x = fmaxf(p.x * s2 + h2v + r.x * s0 + h0v, 0.f);
    p.y = fmaxf(p.y * s2 + h2v + r.y * s0 + h0v, 0.f);
    p.z = fmaxf(p.z * s2 + h2v + r.z * s0 + h0v, 0.f);
    p.w = fmaxf(p.w * s2 + h2v + r.w * s0 + h0v, 0.f);
    ((float4*)out)[i] = p;
}

// ---------------- launch ----------------
extern "C" void kernel_launch(void* const* d_in, const int* in_sizes, int n_in,
                              void* d_out, int out_size)
{
    (void)in_sizes; (void)n_in; (void)out_size;
    const float* x      = (const float*)d_in[0];
    const float* W_sc   = (const float*)d_in[1];
    const float* gsc    = (const float*)d_in[2];
    const float* bsc    = (const float*)d_in[3];
    const float* W1     = (const float*)d_in[4];
    const float* g1     = (const float*)d_in[5];
    const float* b1     = (const float*)d_in[6];
    const float* Wb0    = (const float*)d_in[7];
    const float* gb0    = (const float*)d_in[8];
    const float* bb0    = (const float*)d_in[9];
    const float* Wb1    = (const float*)d_in[10];
    const float* gb1    = (const float*)d_in[11];
    const float* bb1    = (const float*)d_in[12];
    const float* Wqkv2  = (const float*)d_in[13];
    const float* Wproj2 = (const float*)d_in[14];
    const float* ga2    = (const float*)d_in[15];
    const float* ba2    = (const float*)d_in[16];
    const float* Wqkv3  = (const float*)d_in[17];
    const float* Wproj3 = (const float*)d_in[18];
    const float* ga3    = (const float*)d_in[19];
    const float* ba3    = (const float*)d_in[20];
    const float* W2     = (const float*)d_in[21];
    const float* g2     = (const float*)d_in[22];
    const float* b2     = (const float*)d_in[23];

    cudaFuncSetAttribute(tg16_k,    cudaFuncAttributeMaxDynamicSharedMemorySize, SM128);
    cudaFuncSetAttribute(tg16_64_k, cudaFuncAttributeMaxDynamicSharedMemorySize, SM64);

    float *tsc, *hh, *qk2, *qk3, *preB, *pout;
    __half *x16, *h16, *pB16, *q16, *Mm16, *W16;
    cudaGetSymbolAddress((void**)&tsc,  g_tsc);
    cudaGetSymbolAddress((void**)&hh,   g_h);
    cudaGetSymbolAddress((void**)&qk2,  g_qkv2);
    cudaGetSymbolAddress((void**)&qk3,  g_qkv3);
    cudaGetSymbolAddress((void**)&preB, g_preB);
    cudaGetSymbolAddress((void**)&pout, g_pout);
    cudaGetSymbolAddress((void**)&x16,  g_x16);
    cudaGetSymbolAddress((void**)&h16,  g_h16);
    cudaGetSymbolAddress((void**)&pB16, g_pB16);
    cudaGetSymbolAddress((void**)&q16,  g_q16);
    cudaGetSymbolAddress((void**)&Mm16, g_Mm16);
    cudaGetSymbolAddress((void**)&W16,  g_W16);

    // conversions
    wcvt_k<<<768, 256>>>(W_sc, W1, Wb0, Wqkv2, Wqkv3, W2, Wb1);
    cvtx_k<<<8192, 256>>>(x);

    // Stage 1: two 128->256 GEMMs over x16; stats fused
    tg16_k<<<dim3(32, 2, NB), 256, SM128>>>(W16 + OFF_WSC, x16, tsc, 128, 0, (long)128 * HW, 0, (long)256 * HW, 0, 0);
    tg16_k<<<dim3(32, 2, NB), 256, SM128>>>(W16 + OFF_W1,  x16, hh,  128, 0, (long)128 * HW, 0, (long)256 * HW, 0, 256);
    finalize_k<<<256, 256>>>(0,   gsc, bsc);
    finalize_k<<<256, 256>>>(256, g1,  b1);
    bnrelu16_k<<<16384, 256>>>(hh, h16, 256);

    // Branch 0: 1x1 conv
    tg16_64_k<<<dim3(32, 1, NB), 256, SM64>>>(W16 + OFF_WB0, h16, preB, 64, 0, (long)256 * HW, 0, (long)256 * HW, 0, 512);
    // Branch 1: 3x3 conv
    tcv16_k<<<dim3(32, 1, NB), 256, SMCV>>>();
    // Branches 2/3: qkv projections
    tg16_64_k<<<dim3(32, 3, NB), 256, SM64>>>(W16 + OFF_WQ2, h16, qk2, 64, 0, (long)256 * HW, 128, (long)192 * HW, 0, -1);
    tg16_64_k<<<dim3(32, 3, NB), 256, SM64>>>(W16 + OFF_WQ3, h16, qk3, 64, 0, (long)256 * HW, 192, (long)192 * HW, 0, -1);
    cvtq_k<<<8192, 256>>>(qk2, qk3);
    softmax_k<<<2048, 256>>>(qk2, qk3);
    ctx_k<<<dim3(128, 2), 256>>>(qk2, qk3);
    ctxred_k<<<512, 256>>>();
    mproj_k<<<32, 256>>>(Wproj2, Wproj3);
    // attn out = M @ q (per-batch fp16 weights)
    tg16_64_k<<<dim3(32, 1, NB), 256, SM64>>>(Mm16,             q16,                        preB, 64, 4096, (long)64 * HW, 0, (long)256 * HW, 128, 512);
    tg16_64_k<<<dim3(32, 1, NB), 256, SM64>>>(Mm16 + 16 * 4096, q16 + (size_t)16 * 64 * HW, preB, 64, 4096, (long)64 * HW, 0, (long)256 * HW, 192, 512);

    // Branch BN params
    finalize_k<<<64, 256>>>(512, gb0, bb0);
    finalize_k<<<64, 256>>>(576, gb1, bb1);
    finalize_k<<<64, 256>>>(640, ga2, ba2);
    finalize_k<<<64, 256>>>(704, ga3, ba3);
    bnrelu16_k<<<16384, 256>>>(preB, pB16, 512);

    // Final 256->256 GEMM
    tg16_k<<<dim3(32, 2, NB), 256, SM128>>>(W16 + OFF_W2, pB16, pout, 256, 0, (long)256 * HW, 0, (long)256 * HW, 0, 768);
    finalize_k<<<256, 256>>>(768, g2, b2);
    final_k<<<16384, 256>>>((float*)d_out);
}

// round 12
// speedup vs baseline: 1.7098x; 1.0447x over previous
#include <cuda_runtime.h>
#include <cuda_fp16.h>
#include <cstdint>
#include <math.h>

#define HW 4096
#define NB 16
#define NPART 2048

// ---------------- fp32 scratch ----------------
static __device__ float  g_s1  [(size_t)NB*512*HW];   // ch 0-255 = tsc(pre-BN), 256-511 = h(pre-BN)
static __device__ float  g_qkv [(size_t)NB*384*HW];   // ch 0-191 = qkv2, 192-383 = qkv3
static __device__ float  g_preB[(size_t)NB*256*HW];
static __device__ float  g_pout[(size_t)NB*256*HW];
static __device__ float  g_ctxp[2*NB*8*4096];
static __device__ float  g_ctx [2*NB*4096];
static __device__ float  g_psum  [(size_t)1024*NPART];
static __device__ float  g_psumsq[(size_t)1024*NPART];
static __device__ float  g_scale [1024];
static __device__ float  g_shift [1024];
// fp16 operand buffers (16B-aligned: cp.async sources)
static __device__ __align__(16) __half g_x16 [(size_t)NB*128*HW];
static __device__ __align__(16) __half g_h16 [(size_t)NB*256*HW];
static __device__ __align__(16) __half g_pB16[(size_t)NB*256*HW];
static __device__ __align__(16) __half g_q16 [(size_t)NB*128*HW];  // ch 0-63 = q2, 64-127 = q3
static __device__ __align__(16) __half g_Mm16[(size_t)NB*128*64];  // [b][128][64]: rows 0-63 lga0, 64-127 lga1
static __device__ __align__(16) __half g_W16 [196608];
#define OFF_WSC 0
#define OFF_W1  32768
#define OFF_WB0 65536
#define OFF_WQ2 69632
#define OFF_WQ3 81920
#define OFF_W2  94208
#define OFF_WC  159744

__device__ __forceinline__ uint32_t pk2(float a, float b) {
    __half2 h = __floats2half2_rn(a, b);
    return *(uint32_t*)&h;
}
__device__ __forceinline__ void mma16(float* c, const uint32_t* a, const uint32_t* b) {
    asm volatile("mma.sync.aligned.m16n8k16.row.col.f32.f16.f16.f32 "
        "{%0,%1,%2,%3}, {%4,%5,%6,%7}, {%8,%9}, {%0,%1,%2,%3};"
        : "+f"(c[0]), "+f"(c[1]), "+f"(c[2]), "+f"(c[3])
        : "r"(a[0]), "r"(a[1]), "r"(a[2]), "r"(a[3]), "r"(b[0]), "r"(b[1]));
}
__device__ __forceinline__ void cpa16(uint32_t dst, const void* src) {
    asm volatile("cp.async.ca.shared.global [%0], [%1], 16;" :: "r"(dst), "l"(src));
}
#define CP_COMMIT() asm volatile("cp.async.commit_group;")
#define CP_WAIT(n)  asm volatile("cp.async.wait_group %0;" :: "n"(n))
#define LDSM4(r0,r1,r2,r3,addr) \
    asm volatile("ldmatrix.sync.aligned.m8n8.x4.shared.b16 {%0,%1,%2,%3}, [%4];" \
        : "=r"(r0), "=r"(r1), "=r"(r2), "=r"(r3) : "r"(addr))
#define LDSM4T(r0,r1,r2,r3,addr) \
    asm volatile("ldmatrix.sync.aligned.m8n8.x4.trans.shared.b16 {%0,%1,%2,%3}, [%4];" \
        : "=r"(r0), "=r"(r1), "=r"(r2), "=r"(r3) : "r"(addr))

// smem layout (bytes): A rows 80B (32 halfs + pad), B rows 272B (128 halfs + pad)
#define AROW 80
#define BROW 272
#define ABUF128 10240
#define ABUF64  5120
#define BBUF    8704
#define SM128 (2*ABUF128 + 2*BBUF)
#define SM64  (2*ABUF64  + 2*BBUF)
#define SMCV  (ABUF64 + BBUF)

#define STATS_EPI(MT_, mexpr_, slotbase_)                                            \
    {                                                                                \
        float s0 = 0.f, q0 = 0.f, s1 = 0.f, q1 = 0.f;                                \
        _Pragma("unroll")                                                            \
        for (int nt = 0; nt < 4; nt++) {                                             \
            s0 += acc[MT_][nt][0] + acc[MT_][nt][1];                                 \
            q0 += acc[MT_][nt][0]*acc[MT_][nt][0] + acc[MT_][nt][1]*acc[MT_][nt][1]; \
            s1 += acc[MT_][nt][2] + acc[MT_][nt][3];                                 \
            q1 += acc[MT_][nt][2]*acc[MT_][nt][2] + acc[MT_][nt][3]*acc[MT_][nt][3]; \
        }                                                                            \
        _Pragma("unroll")                                                            \
        for (int off = 1; off < 4; off <<= 1) {                                      \
            s0 += __shfl_xor_sync(0xffffffffu, s0, off);                             \
            q0 += __shfl_xor_sync(0xffffffffu, q0, off);                             \
            s1 += __shfl_xor_sync(0xffffffffu, s1, off);                             \
            q1 += __shfl_xor_sync(0xffffffffu, q1, off);                             \
        }                                                                            \
        if (qc == 0) {                                                               \
            g_psum  [(size_t)((slotbase_) + (mexpr_)) * NPART + pidx] = s0;          \
            g_psumsq[(size_t)((slotbase_) + (mexpr_)) * NPART + pidx] = q0;          \
            g_psum  [(size_t)((slotbase_) + (mexpr_) + 8) * NPART + pidx] = s1;      \
            g_psumsq[(size_t)((slotbase_) + (mexpr_) + 8) * NPART + pidx] = q1;      \
        }                                                                            \
    }

// ================= 128-row tile fp16 GEMM, cp.async double-buffered =================
__global__ __launch_bounds__(256, 2) void tg16_k(
    const __half* __restrict__ Wg, const __half* __restrict__ A16, float* __restrict__ C,
    int K, long wbs, long abs16, int acoff, long cbs, int ccoff, int statslot)
{
    extern __shared__ char smem[];
    const uint32_t sbase = (uint32_t)__cvta_generic_to_shared(smem);
    const int b = blockIdx.z;
    const __half* Wp = Wg + (size_t)b * wbs;
    const __half* Ap = A16 + (size_t)b * abs16 + (size_t)acoff * HW;
    float* Cp = C + (size_t)b * cbs + (size_t)ccoff * HW;
    const int n0 = blockIdx.x * 128, m0 = blockIdx.y * 128;
    const int tid = threadIdx.x, lane = tid & 31, wid = tid >> 5;
    const int wm0 = (wid >> 2) * 64, wn0 = (wid & 3) * 32;
    const int qr = lane >> 2, qc = lane & 3;
    const int nk = K / 32;
    const int ar = tid >> 1, ac = (tid & 1) * 2;
    const int br = tid >> 3, bc = tid & 7;
    const int l15 = lane & 15, l8 = (lane >> 4) << 3;

    float acc[4][4][4];
#pragma unroll
    for (int i = 0; i < 4; i++)
#pragma unroll
        for (int j = 0; j < 4; j++)
#pragma unroll
            for (int e = 0; e < 4; e++) acc[i][j][e] = 0.f;

    {
        uint32_t da = sbase + ar * AROW + ac * 16;
        const __half* sa = Wp + (size_t)(m0 + ar) * K + ac * 8;
        cpa16(da, sa); cpa16(da + 16, sa + 8);
        uint32_t db = sbase + 2 * ABUF128 + br * BROW + bc * 16;
        const __half* sb = Ap + (size_t)br * HW + n0 + bc * 8;
        cpa16(db, sb); cpa16(db + 128, sb + 64);
    }
    CP_COMMIT();

    for (int kc = 0; kc < nk; kc++) {
        const int buf = kc & 1;
        if (kc + 1 < nk) {
            const int nb = buf ^ 1, k1 = kc + 1;
            uint32_t da = sbase + nb * ABUF128 + ar * AROW + ac * 16;
            const __half* sa = Wp + (size_t)(m0 + ar) * K + k1 * 32 + ac * 8;
            cpa16(da, sa); cpa16(da + 16, sa + 8);
            uint32_t db = sbase + 2 * ABUF128 + nb * BBUF + br * BROW + bc * 16;
            const __half* sb = Ap + (size_t)(k1 * 32 + br) * HW + n0 + bc * 8;
            cpa16(db, sb); cpa16(db + 128, sb + 64);
            CP_COMMIT();
            CP_WAIT(1);
        } else {
            CP_WAIT(0);
        }
        __syncthreads();
        const uint32_t ab = sbase + buf * ABUF128;
        const uint32_t bb = sbase + 2 * ABUF128 + buf * BBUF;
#pragma unroll
        for (int ks = 0; ks < 2; ks++) {
            const int kb = ks * 16;
            uint32_t af[4][4], bf[2][4];
#pragma unroll
            for (int mt = 0; mt < 4; mt++)
                LDSM4(af[mt][0], af[mt][1], af[mt][2], af[mt][3],
                      ab + (wm0 + mt * 16 + l15) * AROW + (kb + l8) * 2);
#pragma unroll
            for (int nh = 0; nh < 2; nh++)
                LDSM4T(bf[nh][0], bf[nh][1], bf[nh][2], bf[nh][3],
                       bb + (kb + l15) * BROW + (wn0 + nh * 16 + l8) * 2);
#pragma unroll
            for (int mt = 0; mt < 4; mt++)
#pragma unroll
                for (int nt = 0; nt < 4; nt++)
                    mma16(acc[mt][nt], af[mt], &bf[nt >> 1][(nt & 1) * 2]);
        }
        __syncthreads();
    }

    const int pidx = (b * 32 + blockIdx.x) * 4 + (wid & 3);
#pragma unroll
    for (int mt = 0; mt < 4; mt++) {
        const int m = m0 + wm0 + mt * 16 + qr;
#pragma unroll
        for (int nt = 0; nt < 4; nt++) {
            const int n = n0 + wn0 + nt * 8 + qc * 2;
            *(float2*)(Cp + (size_t)m * HW + n) = make_float2(acc[mt][nt][0], acc[mt][nt][1]);
            *(float2*)(Cp + (size_t)(m + 8) * HW + n) = make_float2(acc[mt][nt][2], acc[mt][nt][3]);
        }
        if (statslot >= 0) STATS_EPI(mt, ccoff + m, statslot)
    }
}

// ================= 64-row tile fp16 GEMM (per-y A-group step: Ap += (y/agrp)*astep*HW) =================
__global__ __launch_bounds__(256, 2) void tg16_64_k(
    const __half* __restrict__ Wg, const __half* __restrict__ A16, float* __restrict__ C,
    int K, long wbs, long abs16, int acoff, int agrp, int astep, long cbs, int ccoff, int statslot)
{
    extern __shared__ char smem[];
    const uint32_t sbase = (uint32_t)__cvta_generic_to_shared(smem);
    const int b = blockIdx.z;
    const __half* Wp = Wg + (size_t)b * wbs;
    const __half* Ap = A16 + (size_t)b * abs16 + (size_t)(acoff + (blockIdx.y / agrp) * astep) * HW;
    float* Cp = C + (size_t)b * cbs + (size_t)ccoff * HW;
    const int n0 = blockIdx.x * 128, m0 = blockIdx.y * 64;
    const int tid = threadIdx.x, lane = tid & 31, wid = tid >> 5;
    const int wm0 = (wid >> 2) * 32, wn0 = (wid & 3) * 32;
    const int qr = lane >> 2, qc = lane & 3;
    const int nk = K / 32;
    const int ar = tid >> 2, ac = tid & 3;
    const int br = tid >> 3, bc = tid & 7;
    const int l15 = lane & 15, l8 = (lane >> 4) << 3;

    float acc[2][4][4];
#pragma unroll
    for (int i = 0; i < 2; i++)
#pragma unroll
        for (int j = 0; j < 4; j++)
#pragma unroll
            for (int e = 0; e < 4; e++) acc[i][j][e] = 0.f;

    {
        cpa16(sbase + ar * AROW + ac * 16, Wp + (size_t)(m0 + ar) * K + ac * 8);
        uint32_t db = sbase + 2 * ABUF64 + br * BROW + bc * 16;
        const __half* sb = Ap + (size_t)br * HW + n0 + bc * 8;
        cpa16(db, sb); cpa16(db + 128, sb + 64);
    }
    CP_COMMIT();

    for (int kc = 0; kc < nk; kc++) {
        const int buf = kc & 1;
        if (kc + 1 < nk) {
            const int nb = buf ^ 1, k1 = kc + 1;
            cpa16(sbase + nb * ABUF64 + ar * AROW + ac * 16,
                  Wp + (size_t)(m0 + ar) * K + k1 * 32 + ac * 8);
            uint32_t db = sbase + 2 * ABUF64 + nb * BBUF + br * BROW + bc * 16;
            const __half* sb = Ap + (size_t)(k1 * 32 + br) * HW + n0 + bc * 8;
            cpa16(db, sb); cpa16(db + 128, sb + 64);
            CP_COMMIT();
            CP_WAIT(1);
        } else {
            CP_WAIT(0);
        }
        __syncthreads();
        const uint32_t ab = sbase + buf * ABUF64;
        const uint32_t bb = sbase + 2 * ABUF64 + buf * BBUF;
#pragma unroll
        for (int ks = 0; ks < 2; ks++) {
            const int kb = ks * 16;
            uint32_t af[2][4], bf[2][4];
#pragma unroll
            for (int mt = 0; mt < 2; mt++)
                LDSM4(af[mt][0], af[mt][1], af[mt][2], af[mt][3],
                      ab + (wm0 + mt * 16 + l15) * AROW + (kb + l8) * 2);
#pragma unroll
            for (int nh = 0; nh < 2; nh++)
                LDSM4T(bf[nh][0], bf[nh][1], bf[nh][2], bf[nh][3],
                       bb + (kb + l15) * BROW + (wn0 + nh * 16 + l8) * 2);
#pragma unroll
            for (int mt = 0; mt < 2; mt++)
#pragma unroll
                for (int nt = 0; nt < 4; nt++)
                    mma16(acc[mt][nt], af[mt], &bf[nt >> 1][(nt & 1) * 2]);
        }
        __syncthreads();
    }

    const int pidx = (b * 32 + blockIdx.x) * 4 + (wid & 3);
#pragma unroll
    for (int mt = 0; mt < 2; mt++) {
        const int m = m0 + wm0 + mt * 16 + qr;
#pragma unroll
        for (int nt = 0; nt < 4; nt++) {
            const int n = n0 + wn0 + nt * 8 + qc * 2;
            *(float2*)(Cp + (size_t)m * HW + n) = make_float2(acc[mt][nt][0], acc[mt][nt][1]);
            *(float2*)(Cp + (size_t)(m + 8) * HW + n) = make_float2(acc[mt][nt][2], acc[mt][nt][3]);
        }
        if (statslot >= 0) STATS_EPI(mt, ccoff + m, statslot)
    }
}

// ================= fp16 implicit-GEMM 3x3 conv (single-buffer, M=64) =================
__global__ __launch_bounds__(256, 2) void tcv16_k()
{
    extern __shared__ char smem[];
    const uint32_t sbase = (uint32_t)__cvta_generic_to_shared(smem);
    const int b = blockIdx.z;
    const __half* Ap = g_h16 + (size_t)b * 256 * HW + (size_t)64 * HW;
    const __half* Wc = g_W16 + OFF_WC;
    float* Cp = g_preB + (size_t)b * 256 * HW + (size_t)64 * HW;
    const int n0 = blockIdx.x * 128;
    const int tid = threadIdx.x, lane = tid & 31, wid = tid >> 5;
    const int wm0 = (wid >> 2) * 32, wn0 = (wid & 3) * 32;
    const int qr = lane >> 2, qc = lane & 3;
    const int l15 = lane & 15, l8 = (lane >> 4) << 3;

    float acc[2][4][4];
#pragma unroll
    for (int i = 0; i < 2; i++)
#pragma unroll
        for (int j = 0; j < 4; j++)
#pragma unroll
            for (int e = 0; e < 4; e++) acc[i][j][e] = 0.f;

    for (int kc = 0; kc < 18; kc++) {
        const int tap = kc >> 1, half = kc & 1;
        const int dy = tap / 3 - 1, dx = tap % 3 - 1;
        {
            const int row = tid >> 2, c = tid & 3;
            uint4 v = *(const uint4*)(Wc + (size_t)tap * 4096 + row * 64 + half * 32 + c * 8);
            *(uint4*)(smem + row * AROW + c * 16) = v;
        }
        {
            const int r = tid >> 3, g = tid & 7;
            const int ic = half * 32 + r;
            const __half* plane = Ap + (size_t)ic * HW;
            uint32_t w[8];
#pragma unroll
            for (int jj = 0; jj < 8; jj++) {
                uint32_t lohi[2];
#pragma unroll
                for (int e = 0; e < 2; e++) {
                    int p = n0 + g * 16 + jj * 2 + e;
                    int y = (p >> 6) + dy, x = (p & 63) + dx;
                    __half u = __float2half(0.f);
                    if ((unsigned)y < 64u && (unsigned)x < 64u) u = plane[y * 64 + x];
                    lohi[e] = (uint32_t)*(uint16_t*)&u;
                }
                w[jj] = lohi[0] | (lohi[1] << 16);
            }
            char* db = smem + ABUF64 + r * BROW + g * 32;
            *(uint4*)(db)      = make_uint4(w[0], w[1], w[2], w[3]);
            *(uint4*)(db + 16) = make_uint4(w[4], w[5], w[6], w[7]);
        }
        __syncthreads();
        const uint32_t ab = sbase;
        const uint32_t bb = sbase + ABUF64;
#pragma unroll
        for (int ks = 0; ks < 2; ks++) {
            const int kb = ks * 16;
            uint32_t af[2][4], bf[2][4];
#pragma unroll
            for (int mt = 0; mt < 2; mt++)
                LDSM4(af[mt][0], af[mt][1], af[mt][2], af[mt][3],
                      ab + (wm0 + mt * 16 + l15) * AROW + (kb + l8) * 2);
#pragma unroll
            for (int nh = 0; nh < 2; nh++)
                LDSM4T(bf[nh][0], bf[nh][1], bf[nh][2], bf[nh][3],
                       bb + (kb + l15) * BROW + (wn0 + nh * 16 + l8) * 2);
#pragma unroll
            for (int mt = 0; mt < 2; mt++)
#pragma unroll
                for (int nt = 0; nt < 4; nt++)
                    mma16(acc[mt][nt], af[mt], &bf[nt >> 1][(nt & 1) * 2]);
        }
        __syncthreads();
    }

    const int pidx = (b * 32 + blockIdx.x) * 4 + (wid & 3);
#pragma unroll
    for (int mt = 0; mt < 2; mt++) {
        const int m = wm0 + mt * 16 + qr;
#pragma unroll
        for (int nt = 0; nt < 4; nt++) {
            const int n = n0 + wn0 + nt * 8 + qc * 2;
            *(float2*)(Cp + (size_t)m * HW + n) = make_float2(acc[mt][nt][0], acc[mt][nt][1]);
            *(float2*)(Cp + (size_t)(m + 8) * HW + n) = make_float2(acc[mt][nt][2], acc[mt][nt][3]);
        }
        STATS_EPI(mt, m, 576)
    }
}

// ---------------- conversion kernels ----------------
__global__ __launch_bounds__(256) void wcvt_k(
    const float* __restrict__ Wsc, const float* __restrict__ W1, const float* __restrict__ Wb0,
    const float* __restrict__ Wq2, const float* __restrict__ Wq3, const float* __restrict__ W2,
    const float* __restrict__ Wb1)
{
    int i = blockIdx.x * 256 + threadIdx.x;
    if (i >= 196608) return;
    float v;
    if (i < 32768)       v = Wsc[i];
    else if (i < 65536)  v = W1[i - 32768];
    else if (i < 69632)  v = Wb0[i - 65536];
    else if (i < 81920)  v = Wq2[i - 69632];
    else if (i < 94208)  v = Wq3[i - 81920];
    else if (i < 159744) v = W2[i - 94208];
    else {
        int e = i - 159744;
        int tap = e >> 12, oc = (e >> 6) & 63, ic = e & 63;
        v = Wb1[oc * 576 + ic * 9 + tap];
    }
    g_W16[i] = __float2half(v);
}

__global__ __launch_bounds__(256) void cvtx_k(const float* __restrict__ x)
{
    size_t i = (size_t)blockIdx.x * 256 + threadIdx.x;   // 2,097,152 float4s
    float4 v = ((const float4*)x)[i];
    *(uint2*)(g_x16 + i * 4) = make_uint2(pk2(v.x, v.y), pk2(v.z, v.w));
}

// h16 = bnrelu(g_s1 ch 256-511)
__global__ __launch_bounds__(256) void bnreluH_k()
{
    size_t i = (size_t)blockIdx.x * 256 + threadIdx.x;   // 4,194,304 float4s over h
    int b = (int)(i >> 18);
    int off = (int)(i & 262143);
    int c = off >> 10;
    float sc = g_scale[256 + c], sh = g_shift[256 + c];
    float4 v = ((const float4*)g_s1)[(size_t)b * 524288 + 262144 + off];
    v.x = fmaxf(v.x * sc + sh, 0.f);
    v.y = fmaxf(v.y * sc + sh, 0.f);
    v.z = fmaxf(v.z * sc + sh, 0.f);
    v.w = fmaxf(v.w * sc + sh, 0.f);
    *(uint2*)(g_h16 + i * 4) = make_uint2(pk2(v.x, v.y), pk2(v.z, v.w));
}

// pB16 = bnrelu(g_preB)
__global__ __launch_bounds__(256) void bnreluP_k()
{
    size_t i = (size_t)blockIdx.x * 256 + threadIdx.x;   // 4,194,304 float4s
    int c = (int)((i >> 10) & 255);
    float sc = g_scale[512 + c], sh = g_shift[512 + c];
    float4 v = ((const float4*)g_preB)[i];
    v.x = fmaxf(v.x * sc + sh, 0.f);
    v.y = fmaxf(v.y * sc + sh, 0.f);
    v.z = fmaxf(v.z * sc + sh, 0.f);
    v.w = fmaxf(v.w * sc + sh, 0.f);
    *(uint2*)(g_pB16 + i * 4) = make_uint2(pk2(v.x, v.y), pk2(v.z, v.w));
}

// q16[b][128][HW]: ch 0-63 from g_qkv ch 0-63, ch 64-127 from g_qkv ch 192-255
__global__ __launch_bounds__(256) void cvtq_k()
{
    size_t i = (size_t)blockIdx.x * 256 + threadIdx.x;   // 2,097,152 float4s
    int b = (int)(i >> 17);
    int within = (int)(i & 131071);
    int ch = within >> 10, hw4 = within & 1023;
    int srcch = ((ch >> 6) * 192) + (ch & 63);
    float4 v = *(const float4*)(g_qkv + ((size_t)b * 384 + srcch) * HW + hw4 * 4);
    *(uint2*)(g_q16 + (((size_t)b * 128 + ch) * HW + hw4 * 4)) =
        make_uint2(pk2(v.x, v.y), pk2(v.z, v.w));
}

// ---------------- finalize: grouped gamma/beta selection ----------------
__global__ __launch_bounds__(256) void finalizeG_k(
    int slot, int shift,
    const float* __restrict__ g0, const float* __restrict__ b0,
    const float* __restrict__ g1, const float* __restrict__ b1,
    const float* __restrict__ g2, const float* __restrict__ b2,
    const float* __restrict__ g3, const float* __restrict__ b3)
{
    const int c = blockIdx.x, tid = threadIdx.x;
    const float* ps = g_psum   + (size_t)(slot + c) * NPART;
    const float* pq = g_psumsq + (size_t)(slot + c) * NPART;
    float s = 0.f, q = 0.f;
    for (int i = tid; i < NPART; i += 256) { s += ps[i]; q += pq[i]; }
    __shared__ float ss[256], sq[256];
    ss[tid] = s; sq[tid] = q; __syncthreads();
    for (int st = 128; st > 0; st >>= 1) {
        if (tid < st) { ss[tid] += ss[tid + st]; sq[tid] += sq[tid + st]; }
        __syncthreads();
    }
    if (tid == 0) {
        const int grp = c >> shift, idx = c & ((1 << shift) - 1);
        const float* gp; const float* bp;
        if (grp == 0)      { gp = g0; bp = b0; }
        else if (grp == 1) { gp = g1; bp = b1; }
        else if (grp == 2) { gp = g2; bp = b2; }
        else               { gp = g3; bp = b3; }
        const float inv = 1.f / 65536.f;
        float m = ss[0] * inv;
        float v = sq[0] * inv - m * m;
        float sc = gp[idx] * rsqrtf(v + 1e-5f);
        g_scale[slot + c] = sc;
        g_shift[slot + c] = bp[idx] - m * sc;
    }
}

// ---------------- softmax over k-sections of g_qkv ----------------
__global__ __launch_bounds__(256) void softmax_k()
{
    __shared__ float row[4096];
    __shared__ float red[256];
    const int id = blockIdx.x;
    const int lga = id >> 10, rem = id & 1023;
    const int b = rem >> 6, c = rem & 63;
    float* p = g_qkv + ((size_t)b * 384 + lga * 192 + 64 + c) * HW;
    const int tid = threadIdx.x;

    float m = -1e30f;
    for (int i = tid; i < 4096; i += 256) { float v = p[i]; row[i] = v; m = fmaxf(m, v); }
    red[tid] = m; __syncthreads();
    for (int st = 128; st > 0; st >>= 1) { if (tid < st) red[tid] = fmaxf(red[tid], red[tid + st]); __syncthreads(); }
    m = red[0]; __syncthreads();

    float s = 0.f;
    for (int i = tid; i < 4096; i += 256) { float e = expf(row[i] - m); row[i] = e; s += e; }
    red[tid] = s; __syncthreads();
    for (int st = 128; st > 0; st >>= 1) { if (tid < st) red[tid] += red[tid + st]; __syncthreads(); }
    float inv = 1.f / red[0];
    for (int i = tid; i < 4096; i += 256) p[i] = row[i] * inv;
}

// ---------------- ctx ----------------
__global__ __launch_bounds__(256) void ctx_k()
{
    __shared__ float Ks[64][33];
    __shared__ float Vs[64][33];
    const int chunk = blockIdx.x >> 4, b = blockIdx.x & 15, lga = blockIdx.y;
    const float* base = g_qkv + ((size_t)b * 384 + lga * 192) * HW;
    const float* kp = base + (size_t)64 * HW;
    const float* vp = base + (size_t)128 * HW;
    const int tid = threadIdx.x;
    const int cb = (tid >> 4) << 2, db = (tid & 15) << 2;

    float acc[4][4];
#pragma unroll
    for (int i = 0; i < 4; i++)
#pragma unroll
        for (int j = 0; j < 4; j++) acc[i][j] = 0.f;

    for (int sub = 0; sub < 16; sub++) {
        const int n0 = chunk * 512 + sub * 32;
        for (int idx = tid; idx < 2048; idx += 256) {
            int r = idx >> 5, cc = idx & 31;
            Ks[r][cc] = kp[(size_t)r * HW + n0 + cc];
            Vs[r][cc] = vp[(size_t)r * HW + n0 + cc];
        }
        __syncthreads();
#pragma unroll 8
        for (int nn = 0; nn < 32; nn++) {
            float kc[4], vd[4];
#pragma unroll
            for (int i = 0; i < 4; i++) { kc[i] = Ks[cb + i][nn]; vd[i] = Vs[db + i][nn]; }
#pragma unroll
            for (int i = 0; i < 4; i++)
#pragma unroll
                for (int j = 0; j < 4; j++) acc[i][j] += kc[i] * vd[j];
        }
        __syncthreads();
    }
    float* cp = g_ctxp + ((size_t)(lga * 16 + b) * 8 + chunk) * 4096;
#pragma unroll
    for (int i = 0; i < 4; i++)
#pragma unroll
        for (int j = 0; j < 4; j++) cp[(cb + i) * 64 + db + j] = acc[i][j];
}

__global__ void ctxred_k()
{
    int i = blockIdx.x * 256 + threadIdx.x;
    if (i >= 2 * NB * 4096) return;
    int pair = i >> 12, e = i & 4095;
    const float* cp = g_ctxp + (size_t)pair * 8 * 4096 + e;
    float s = 0.f;
#pragma unroll
    for (int p = 0; p < 8; p++) s += cp[p * 4096];
    g_ctx[i] = s;
}

// ---------------- M = Wproj @ ctx^T -> g_Mm16[b][lga*64+o][c] ----------------
__global__ __launch_bounds__(256) void mproj_k(const float* __restrict__ Wp2, const float* __restrict__ Wp3)
{
    const int id = blockIdx.x;               // 32 = lga*16 + b
    const int lga = id >> 4, b = id & 15;
    const float* Wp = lga ? Wp3 : Wp2;
    const float* cx = g_ctx + (size_t)id * 4096;
    __half* Mo = g_Mm16 + (size_t)b * 8192 + (size_t)lga * 64 * 64;
    for (int e = threadIdx.x; e < 4096; e += 256) {
        int o = e >> 6, c = e & 63;
        float s = 0.f;
#pragma unroll 16
        for (int d = 0; d < 64; d++) s += Wp[o * 64 + d] * cx[c * 64 + d];
        Mo[o * 64 + c] = __float2half(s);
    }
}

// ---------------- final: out = relu( bn2(pout) + bn_sc(s1 ch 0-255) ) ----------------
__global__ __launch_bounds__(256) void final_k(float* __restrict__ out)
{
    size_t i = (size_t)blockIdx.x * 256 + threadIdx.x;
    int b = (int)(i >> 18);
    int off = (int)(i & 262143);
    int c = off >> 10;
    float s2 = g_scale[768 + c], h2v = g_shift[768 + c];
    float s0 = g_scale[c],       h0v = g_shift[c];
    float4 p = ((const float4*)g_pout)[i];
    float4 r = ((const float4*)g_s1)[(size_t)b * 524288 + off];
    p.x = fmaxf(p.x * s2 + h2v + r.x * s0 + h0v, 0.f);
    p.y = fmaxf(p.y * s2 + h2v + r.y * s0 + h0v, 0.f);
    p.z = fmaxf(p.z * s2 + h2v + r.z * s0 + h0v, 0.f);
    p.w = fmaxf(p.w * s2 + h2v + r.w * s0 + h0v, 0.f);
    ((float4*)out)[i] = p;
}

// ---------------- launch ----------------
extern "C" void kernel_launch(void* const* d_in, const int* in_sizes, int n_in,
                              void* d_out, int out_size)
{
    (void)in_sizes; (void)n_in; (void)out_size;
    const float* x      = (const float*)d_in[0];
    const float* W_sc   = (const float*)d_in[1];
    const float* gsc    = (const float*)d_in[2];
    const float* bsc    = (const float*)d_in[3];
    const float* W1     = (const float*)d_in[4];
    const float* g1     = (const float*)d_in[5];
    const float* b1     = (const float*)d_in[6];
    const float* Wb0    = (const float*)d_in[7];
    const float* gb0    = (const float*)d_in[8];
    const float* bb0    = (const float*)d_in[9];
    const float* Wb1    = (const float*)d_in[10];
    const float* gb1    = (const float*)d_in[11];
    const float* bb1    = (const float*)d_in[12];
    const float* Wqkv2  = (const float*)d_in[13];
    const float* Wproj2 = (const float*)d_in[14];
    const float* ga2    = (const float*)d_in[15];
    const float* ba2    = (const float*)d_in[16];
    const float* Wqkv3  = (const float*)d_in[17];
    const float* Wproj3 = (const float*)d_in[18];
    const float* ga3    = (const float*)d_in[19];
    const float* ba3    = (const float*)d_in[20];
    const float* W2     = (const float*)d_in[21];
    const float* g2     = (const float*)d_in[22];
    const float* b2     = (const float*)d_in[23];

    cudaFuncSetAttribute(tg16_k,    cudaFuncAttributeMaxDynamicSharedMemorySize, SM128);
    cudaFuncSetAttribute(tg16_64_k, cudaFuncAttributeMaxDynamicSharedMemorySize, SM64);

    float *s1, *qkv, *preB, *pout;
    __half *x16, *h16, *pB16, *q16, *Mm16, *W16;
    cudaGetSymbolAddress((void**)&s1,   g_s1);
    cudaGetSymbolAddress((void**)&qkv,  g_qkv);
    cudaGetSymbolAddress((void**)&preB, g_preB);
    cudaGetSymbolAddress((void**)&pout, g_pout);
    cudaGetSymbolAddress((void**)&x16,  g_x16);
    cudaGetSymbolAddress((void**)&h16,  g_h16);
    cudaGetSymbolAddress((void**)&pB16, g_pB16);
    cudaGetSymbolAddress((void**)&q16,  g_q16);
    cudaGetSymbolAddress((void**)&Mm16, g_Mm16);
    cudaGetSymbolAddress((void**)&W16,  g_W16);

    // conversions
    wcvt_k<<<768, 256>>>(W_sc, W1, Wb0, Wqkv2, Wqkv3, W2, Wb1);
    cvtx_k<<<8192, 256>>>(x);

    // Stage 1 (merged): [tsc; h_pre] = [Wsc; W1] @ x16 ; stats slots 0-511
    tg16_k<<<dim3(32, 4, NB), 256, SM128>>>(W16, x16, s1, 128, 0, (long)128 * HW, 0, (long)512 * HW, 0, 0);
    finalizeG_k<<<512, 256>>>(0, 8, gsc, bsc, g1, b1, g1, b1, g1, b1);
    bnreluH_k<<<16384, 256>>>();

    // Branch 0: 1x1 conv
    tg16_64_k<<<dim3(32, 1, NB), 256, SM64>>>(W16 + OFF_WB0, h16, preB, 64, 0, (long)256 * HW, 0, 1, 0, (long)256 * HW, 0, 512);
    // Branch 1: 3x3 conv
    tcv16_k<<<dim3(32, 1, NB), 256, SMCV>>>();
    // Branches 2/3 (merged): [qkv2; qkv3] = [Wq2; Wq3] @ h16(s2|s3)
    tg16_64_k<<<dim3(32, 6, NB), 256, SM64>>>(W16 + OFF_WQ2, h16, qkv, 64, 0, (long)256 * HW, 128, 3, 64, (long)384 * HW, 0, -1);
    cvtq_k<<<8192, 256>>>();
    softmax_k<<<2048, 256>>>();
    ctx_k<<<dim3(128, 2), 256>>>();
    ctxred_k<<<512, 256>>>();
    mproj_k<<<32, 256>>>(Wproj2, Wproj3);
    // attn out (merged): preB ch 128-255 = [M2; M3] @ [q2; q3] (block-row-wise)
    tg16_64_k<<<dim3(32, 2, NB), 256, SM64>>>(Mm16, q16, preB, 64, 8192, (long)128 * HW, 0, 1, 64, (long)256 * HW, 128, 512);

    // Branch BN params (merged: slots 512-767)
    finalizeG_k<<<256, 256>>>(512, 6, gb0, bb0, gb1, bb1, ga2, ba2, ga3, ba3);
    bnreluP_k<<<16384, 256>>>();

    // Final 256->256 GEMM
    tg16_k<<<dim3(32, 2, NB), 256, SM128>>>(W16 + OFF_W2, pB16, pout, 256, 0, (long)256 * HW, 0, (long)256 * HW, 0, 768);
    finalizeG_k<<<256, 256>>>(768, 8, g2, b2, g2, b2, g2, b2, g2, b2);
    final_k<<<16384, 256>>>((float*)d_out);
}

// round 13
// speedup vs baseline: 1.7719x; 1.0364x over previous
#include <cuda_runtime.h>
#include <cuda_fp16.h>
#include <cstdint>
#include <math.h>

#define HW 4096
#define NB 16
#define NPART 2048

// ---------------- fp32 scratch ----------------
static __device__ float  g_s1  [(size_t)NB*512*HW];   // ch 0-255 = tsc(pre-BN), 256-511 = h(pre-BN)
static __device__ float  g_qkv [(size_t)NB*384*HW];   // ch 0-191 = qkv2, 192-383 = qkv3 (q ch skipped)
static __device__ float  g_preB[(size_t)NB*256*HW];
static __device__ float  g_pout[(size_t)NB*256*HW];
static __device__ float  g_ctxp[2*NB*8*4096];
static __device__ float  g_ctx [2*NB*4096];
static __device__ float2 g_smx [2*NB*64];             // per (lga,b,c): {rowmax, 1/Z}
static __device__ float  g_psum  [(size_t)1024*NPART];
static __device__ float  g_psumsq[(size_t)1024*NPART];
static __device__ float  g_scale [1024];
static __device__ float  g_shift [1024];
// fp16 operand buffers (16B-aligned: cp.async sources)
static __device__ __align__(16) __half g_x16 [(size_t)NB*128*HW];
static __device__ __align__(16) __half g_h16 [(size_t)NB*256*HW];
static __device__ __align__(16) __half g_pB16[(size_t)NB*256*HW];
static __device__ __align__(16) __half g_q16 [(size_t)NB*128*HW];  // ch 0-63 = q2, 64-127 = q3
static __device__ __align__(16) __half g_Mm16[(size_t)NB*128*64];
static __device__ __align__(16) __half g_W16 [196608];
#define OFF_WSC 0
#define OFF_W1  32768
#define OFF_WB0 65536
#define OFF_WQ2 69632
#define OFF_WQ3 81920
#define OFF_W2  94208
#define OFF_WC  159744

__device__ __forceinline__ uint32_t pk2(float a, float b) {
    __half2 h = __floats2half2_rn(a, b);
    return *(uint32_t*)&h;
}
__device__ __forceinline__ void mma16(float* c, const uint32_t* a, const uint32_t* b) {
    asm volatile("mma.sync.aligned.m16n8k16.row.col.f32.f16.f16.f32 "
        "{%0,%1,%2,%3}, {%4,%5,%6,%7}, {%8,%9}, {%0,%1,%2,%3};"
        : "+f"(c[0]), "+f"(c[1]), "+f"(c[2]), "+f"(c[3])
        : "r"(a[0]), "r"(a[1]), "r"(a[2]), "r"(a[3]), "r"(b[0]), "r"(b[1]));
}
__device__ __forceinline__ void cpa16(uint32_t dst, const void* src) {
    asm volatile("cp.async.ca.shared.global [%0], [%1], 16;" :: "r"(dst), "l"(src));
}
#define CP_COMMIT() asm volatile("cp.async.commit_group;")
#define CP_WAIT(n)  asm volatile("cp.async.wait_group %0;" :: "n"(n))
#define LDSM4(r0,r1,r2,r3,addr) \
    asm volatile("ldmatrix.sync.aligned.m8n8.x4.shared.b16 {%0,%1,%2,%3}, [%4];" \
        : "=r"(r0), "=r"(r1), "=r"(r2), "=r"(r3) : "r"(addr))
#define LDSM4T(r0,r1,r2,r3,addr) \
    asm volatile("ldmatrix.sync.aligned.m8n8.x4.trans.shared.b16 {%0,%1,%2,%3}, [%4];" \
        : "=r"(r0), "=r"(r1), "=r"(r2), "=r"(r3) : "r"(addr))

#define AROW 80
#define BROW 272
#define ABUF128 10240
#define ABUF64  5120
#define BBUF    8704
#define SM128 (3*ABUF128 + 3*BBUF)   // 56832
#define SM64  (3*ABUF64  + 3*BBUF)   // 41472
#define SMCV  (ABUF64 + BBUF)

#define STATS_EPI(MT_, mexpr_, slotbase_)                                            \
    {                                                                                \
        float s0 = 0.f, q0 = 0.f, s1 = 0.f, q1 = 0.f;                                \
        _Pragma("unroll")                                                            \
        for (int nt = 0; nt < 4; nt++) {                                             \
            s0 += acc[MT_][nt][0] + acc[MT_][nt][1];                                 \
            q0 += acc[MT_][nt][0]*acc[MT_][nt][0] + acc[MT_][nt][1]*acc[MT_][nt][1]; \
            s1 += acc[MT_][nt][2] + acc[MT_][nt][3];                                 \
            q1 += acc[MT_][nt][2]*acc[MT_][nt][2] + acc[MT_][nt][3]*acc[MT_][nt][3]; \
        }                                                                            \
        _Pragma("unroll")                                                            \
        for (int off = 1; off < 4; off <<= 1) {                                      \
            s0 += __shfl_xor_sync(0xffffffffu, s0, off);                             \
            q0 += __shfl_xor_sync(0xffffffffu, q0, off);                             \
            s1 += __shfl_xor_sync(0xffffffffu, s1, off);                             \
            q1 += __shfl_xor_sync(0xffffffffu, q1, off);                             \
        }                                                                            \
        if (qc == 0) {                                                               \
            g_psum  [(size_t)((slotbase_) + (mexpr_)) * NPART + pidx] = s0;          \
            g_psumsq[(size_t)((slotbase_) + (mexpr_)) * NPART + pidx] = q0;          \
            g_psum  [(size_t)((slotbase_) + (mexpr_) + 8) * NPART + pidx] = s1;      \
            g_psumsq[(size_t)((slotbase_) + (mexpr_) + 8) * NPART + pidx] = q1;      \
        }                                                                            \
    }

// ================= 128-row tile fp16 GEMM, 3-stage cp.async pipeline =================
__global__ __launch_bounds__(256, 2) void tg16_k(
    const __half* __restrict__ Wg, const __half* __restrict__ A16, float* __restrict__ C,
    int K, long wbs, long abs16, int acoff, long cbs, int ccoff, int statslot)
{
    extern __shared__ char smem[];
    const uint32_t sbase = (uint32_t)__cvta_generic_to_shared(smem);
    const int b = blockIdx.z;
    const __half* Wp = Wg + (size_t)b * wbs;
    const __half* Ap = A16 + (size_t)b * abs16 + (size_t)acoff * HW;
    float* Cp = C + (size_t)b * cbs + (size_t)ccoff * HW;
    const int n0 = blockIdx.x * 128, m0 = blockIdx.y * 128;
    const int tid = threadIdx.x, lane = tid & 31, wid = tid >> 5;
    const int wm0 = (wid >> 2) * 64, wn0 = (wid & 3) * 32;
    const int qr = lane >> 2, qc = lane & 3;
    const int nk = K / 32;
    const int ar = tid >> 1, ac = (tid & 1) * 2;
    const int br = tid >> 3, bc = tid & 7;
    const int l15 = lane & 15, l8 = (lane >> 4) << 3;

    float acc[4][4][4];
#pragma unroll
    for (int i = 0; i < 4; i++)
#pragma unroll
        for (int j = 0; j < 4; j++)
#pragma unroll
            for (int e = 0; e < 4; e++) acc[i][j][e] = 0.f;

    auto fill = [&](int kcx, int st) {
        uint32_t da = sbase + st * ABUF128 + ar * AROW + ac * 16;
        const __half* sa = Wp + (size_t)(m0 + ar) * K + kcx * 32 + ac * 8;
        cpa16(da, sa); cpa16(da + 16, sa + 8);
        uint32_t db = sbase + 3 * ABUF128 + st * BBUF + br * BROW + bc * 16;
        const __half* sb = Ap + (size_t)(kcx * 32 + br) * HW + n0 + bc * 8;
        cpa16(db, sb); cpa16(db + 128, sb + 64);
        CP_COMMIT();
    };

    fill(0, 0);
    if (nk > 1) fill(1, 1);

    for (int kc = 0; kc < nk; kc++) {
        if (kc < nk - 1) { CP_WAIT(1); } else { CP_WAIT(0); }
        __syncthreads();
        const int st = kc % 3;
        const uint32_t ab = sbase + st * ABUF128;
        const uint32_t bb = sbase + 3 * ABUF128 + st * BBUF;
#pragma unroll
        for (int ks = 0; ks < 2; ks++) {
            const int kb = ks * 16;
            uint32_t af[4][4], bf[2][4];
#pragma unroll
            for (int mt = 0; mt < 4; mt++)
                LDSM4(af[mt][0], af[mt][1], af[mt][2], af[mt][3],
                      ab + (wm0 + mt * 16 + l15) * AROW + (kb + l8) * 2);
#pragma unroll
            for (int nh = 0; nh < 2; nh++)
                LDSM4T(bf[nh][0], bf[nh][1], bf[nh][2], bf[nh][3],
                       bb + (kb + l15) * BROW + (wn0 + nh * 16 + l8) * 2);
#pragma unroll
            for (int mt = 0; mt < 4; mt++)
#pragma unroll
                for (int nt = 0; nt < 4; nt++)
                    mma16(acc[mt][nt], af[mt], &bf[nt >> 1][(nt & 1) * 2]);
        }
        if (kc + 2 < nk) fill(kc + 2, (kc + 2) % 3);
    }

    const int pidx = (b * 32 + blockIdx.x) * 4 + (wid & 3);
#pragma unroll
    for (int mt = 0; mt < 4; mt++) {
        const int m = m0 + wm0 + mt * 16 + qr;
#pragma unroll
        for (int nt = 0; nt < 4; nt++) {
            const int n = n0 + wn0 + nt * 8 + qc * 2;
            *(float2*)(Cp + (size_t)m * HW + n) = make_float2(acc[mt][nt][0], acc[mt][nt][1]);
            *(float2*)(Cp + (size_t)(m + 8) * HW + n) = make_float2(acc[mt][nt][2], acc[mt][nt][3]);
        }
        if (statslot >= 0) STATS_EPI(mt, ccoff + m, statslot)
    }
}

// ================= 64-row tile fp16 GEMM, 3-stage pipeline, optional fp16-q epilogue =================
__global__ __launch_bounds__(256, 2) void tg16_64_k(
    const __half* __restrict__ Wg, const __half* __restrict__ A16, float* __restrict__ C,
    int K, long wbs, long abs16, int acoff, int agrp, int astep, long cbs, int ccoff,
    int statslot, __half* __restrict__ q16out)
{
    extern __shared__ char smem[];
    const uint32_t sbase = (uint32_t)__cvta_generic_to_shared(smem);
    const int b = blockIdx.z;
    const __half* Wp = Wg + (size_t)b * wbs;
    const __half* Ap = A16 + (size_t)b * abs16 + (size_t)(acoff + (blockIdx.y / agrp) * astep) * HW;
    float* Cp = C + (size_t)b * cbs + (size_t)ccoff * HW;
    const int n0 = blockIdx.x * 128, m0 = blockIdx.y * 64;
    const int tid = threadIdx.x, lane = tid & 31, wid = tid >> 5;
    const int wm0 = (wid >> 2) * 32, wn0 = (wid & 3) * 32;
    const int qr = lane >> 2, qc = lane & 3;
    const int nk = K / 32;
    const int ar = tid >> 2, ac = tid & 3;
    const int br = tid >> 3, bc = tid & 7;
    const int l15 = lane & 15, l8 = (lane >> 4) << 3;

    float acc[2][4][4];
#pragma unroll
    for (int i = 0; i < 2; i++)
#pragma unroll
        for (int j = 0; j < 4; j++)
#pragma unroll
            for (int e = 0; e < 4; e++) acc[i][j][e] = 0.f;

    auto fill = [&](int kcx, int st) {
        cpa16(sbase + st * ABUF64 + ar * AROW + ac * 16,
              Wp + (size_t)(m0 + ar) * K + kcx * 32 + ac * 8);
        uint32_t db = sbase + 3 * ABUF64 + st * BBUF + br * BROW + bc * 16;
        const __half* sb = Ap + (size_t)(kcx * 32 + br) * HW + n0 + bc * 8;
        cpa16(db, sb); cpa16(db + 128, sb + 64);
        CP_COMMIT();
    };

    fill(0, 0);
    if (nk > 1) fill(1, 1);

    for (int kc = 0; kc < nk; kc++) {
        if (kc < nk - 1) { CP_WAIT(1); } else { CP_WAIT(0); }
        __syncthreads();
        const int st = kc % 3;
        const uint32_t ab = sbase + st * ABUF64;
        const uint32_t bb = sbase + 3 * ABUF64 + st * BBUF;
#pragma unroll
        for (int ks = 0; ks < 2; ks++) {
            const int kb = ks * 16;
            uint32_t af[2][4], bf[2][4];
#pragma unroll
            for (int mt = 0; mt < 2; mt++)
                LDSM4(af[mt][0], af[mt][1], af[mt][2], af[mt][3],
                      ab + (wm0 + mt * 16 + l15) * AROW + (kb + l8) * 2);
#pragma unroll
            for (int nh = 0; nh < 2; nh++)
                LDSM4T(bf[nh][0], bf[nh][1], bf[nh][2], bf[nh][3],
                       bb + (kb + l15) * BROW + (wn0 + nh * 16 + l8) * 2);
#pragma unroll
            for (int mt = 0; mt < 2; mt++)
#pragma unroll
                for (int nt = 0; nt < 4; nt++)
                    mma16(acc[mt][nt], af[mt], &bf[nt >> 1][(nt & 1) * 2]);
        }
        if (kc + 2 < nk) fill(kc + 2, (kc + 2) % 3);
    }

    const int pidx = (b * 32 + blockIdx.x) * 4 + (wid & 3);
#pragma unroll
    for (int mt = 0; mt < 2; mt++) {
        const int m = m0 + wm0 + mt * 16 + qr;
        const int lm = m % 192;
        const bool isq = (q16out != nullptr) && (lm < 64);
        __half* qp0 = nullptr; __half* qp1 = nullptr;
        if (isq) {
            const int qch = (m / 192) * 64 + lm;
            qp0 = q16out + ((size_t)b * 128 + qch) * HW;
            qp1 = qp0 + 8 * HW;    // m+8 stays within same 64-ch q block (wm0+mt*16+qr <= 55 => lm+8 < 64)
        }
#pragma unroll
        for (int nt = 0; nt < 4; nt++) {
            const int n = n0 + wn0 + nt * 8 + qc * 2;
            if (isq) {
                *(uint32_t*)(qp0 + n) = pk2(acc[mt][nt][0], acc[mt][nt][1]);
                *(uint32_t*)(qp1 + n) = pk2(acc[mt][nt][2], acc[mt][nt][3]);
            } else {
                *(float2*)(Cp + (size_t)m * HW + n) = make_float2(acc[mt][nt][0], acc[mt][nt][1]);
                *(float2*)(Cp + (size_t)(m + 8) * HW + n) = make_float2(acc[mt][nt][2], acc[mt][nt][3]);
            }
        }
        if (statslot >= 0) STATS_EPI(mt, ccoff + m, statslot)
    }
}

// ================= fp16 implicit-GEMM 3x3 conv (single-buffer, M=64) =================
__global__ __launch_bounds__(256, 2) void tcv16_k()
{
    extern __shared__ char smem[];
    const uint32_t sbase = (uint32_t)__cvta_generic_to_shared(smem);
    const int b = blockIdx.z;
    const __half* Ap = g_h16 + (size_t)b * 256 * HW + (size_t)64 * HW;
    const __half* Wc = g_W16 + OFF_WC;
    float* Cp = g_preB + (size_t)b * 256 * HW + (size_t)64 * HW;
    const int n0 = blockIdx.x * 128;
    const int tid = threadIdx.x, lane = tid & 31, wid = tid >> 5;
    const int wm0 = (wid >> 2) * 32, wn0 = (wid & 3) * 32;
    const int qr = lane >> 2, qc = lane & 3;
    const int l15 = lane & 15, l8 = (lane >> 4) << 3;

    float acc[2][4][4];
#pragma unroll
    for (int i = 0; i < 2; i++)
#pragma unroll
        for (int j = 0; j < 4; j++)
#pragma unroll
            for (int e = 0; e < 4; e++) acc[i][j][e] = 0.f;

    for (int kc = 0; kc < 18; kc++) {
        const int tap = kc >> 1, half = kc & 1;
        const int dy = tap / 3 - 1, dx = tap % 3 - 1;
        {
            const int row = tid >> 2, c = tid & 3;
            uint4 v = *(const uint4*)(Wc + (size_t)tap * 4096 + row * 64 + half * 32 + c * 8);
            *(uint4*)(smem + row * AROW + c * 16) = v;
        }
        {
            const int r = tid >> 3, g = tid & 7;
            const int ic = half * 32 + r;
            const __half* plane = Ap + (size_t)ic * HW;
            uint32_t w[8];
#pragma unroll
            for (int jj = 0; jj < 8; jj++) {
                uint32_t lohi[2];
#pragma unroll
                for (int e = 0; e < 2; e++) {
                    int p = n0 + g * 16 + jj * 2 + e;
                    int y = (p >> 6) + dy, x = (p & 63) + dx;
                    __half u = __float2half(0.f);
                    if ((unsigned)y < 64u && (unsigned)x < 64u) u = plane[y * 64 + x];
                    lohi[e] = (uint32_t)*(uint16_t*)&u;
                }
                w[jj] = lohi[0] | (lohi[1] << 16);
            }
            char* db = smem + ABUF64 + r * BROW + g * 32;
            *(uint4*)(db)      = make_uint4(w[0], w[1], w[2], w[3]);
            *(uint4*)(db + 16) = make_uint4(w[4], w[5], w[6], w[7]);
        }
        __syncthreads();
        const uint32_t ab = sbase;
        const uint32_t bb = sbase + ABUF64;
#pragma unroll
        for (int ks = 0; ks < 2; ks++) {
            const int kb = ks * 16;
            uint32_t af[2][4], bf[2][4];
#pragma unroll
            for (int mt = 0; mt < 2; mt++)
                LDSM4(af[mt][0], af[mt][1], af[mt][2], af[mt][3],
                      ab + (wm0 + mt * 16 + l15) * AROW + (kb + l8) * 2);
#pragma unroll
            for (int nh = 0; nh < 2; nh++)
                LDSM4T(bf[nh][0], bf[nh][1], bf[nh][2], bf[nh][3],
                       bb + (kb + l15) * BROW + (wn0 + nh * 16 + l8) * 2);
#pragma unroll
            for (int mt = 0; mt < 2; mt++)
#pragma unroll
                for (int nt = 0; nt < 4; nt++)
                    mma16(acc[mt][nt], af[mt], &bf[nt >> 1][(nt & 1) * 2]);
        }
        __syncthreads();
    }

    const int pidx = (b * 32 + blockIdx.x) * 4 + (wid & 3);
#pragma unroll
    for (int mt = 0; mt < 2; mt++) {
        const int m = wm0 + mt * 16 + qr;
#pragma unroll
        for (int nt = 0; nt < 4; nt++) {
            const int n = n0 + wn0 + nt * 8 + qc * 2;
            *(float2*)(Cp + (size_t)m * HW + n) = make_float2(acc[mt][nt][0], acc[mt][nt][1]);
            *(float2*)(Cp + (size_t)(m + 8) * HW + n) = make_float2(acc[mt][nt][2], acc[mt][nt][3]);
        }
        STATS_EPI(mt, m, 576)
    }
}

// ---------------- conversion kernels ----------------
__global__ __launch_bounds__(256) void wcvt_k(
    const float* __restrict__ Wsc, const float* __restrict__ W1, const float* __restrict__ Wb0,
    const float* __restrict__ Wq2, const float* __restrict__ Wq3, const float* __restrict__ W2,
    const float* __restrict__ Wb1)
{
    int i = blockIdx.x * 256 + threadIdx.x;
    if (i >= 196608) return;
    float v;
    if (i < 32768)       v = Wsc[i];
    else if (i < 65536)  v = W1[i - 32768];
    else if (i < 69632)  v = Wb0[i - 65536];
    else if (i < 81920)  v = Wq2[i - 69632];
    else if (i < 94208)  v = Wq3[i - 81920];
    else if (i < 159744) v = W2[i - 94208];
    else {
        int e = i - 159744;
        int tap = e >> 12, oc = (e >> 6) & 63, ic = e & 63;
        v = Wb1[oc * 576 + ic * 9 + tap];
    }
    g_W16[i] = __float2half(v);
}

__global__ __launch_bounds__(256) void cvtx_k(const float* __restrict__ x)
{
    size_t i = (size_t)blockIdx.x * 256 + threadIdx.x;
    float4 v = ((const float4*)x)[i];
    *(uint2*)(g_x16 + i * 4) = make_uint2(pk2(v.x, v.y), pk2(v.z, v.w));
}

__global__ __launch_bounds__(256) void bnreluH_k()
{
    size_t i = (size_t)blockIdx.x * 256 + threadIdx.x;
    int b = (int)(i >> 18);
    int off = (int)(i & 262143);
    int c = off >> 10;
    float sc = g_scale[256 + c], sh = g_shift[256 + c];
    float4 v = ((const float4*)g_s1)[(size_t)b * 524288 + 262144 + off];
    v.x = fmaxf(v.x * sc + sh, 0.f);
    v.y = fmaxf(v.y * sc + sh, 0.f);
    v.z = fmaxf(v.z * sc + sh, 0.f);
    v.w = fmaxf(v.w * sc + sh, 0.f);
    *(uint2*)(g_h16 + i * 4) = make_uint2(pk2(v.x, v.y), pk2(v.z, v.w));
}

__global__ __launch_bounds__(256) void bnreluP_k()
{
    size_t i = (size_t)blockIdx.x * 256 + threadIdx.x;
    int c = (int)((i >> 10) & 255);
    float sc = g_scale[512 + c], sh = g_shift[512 + c];
    float4 v = ((const float4*)g_preB)[i];
    v.x = fmaxf(v.x * sc + sh, 0.f);
    v.y = fmaxf(v.y * sc + sh, 0.f);
    v.z = fmaxf(v.z * sc + sh, 0.f);
    v.w = fmaxf(v.w * sc + sh, 0.f);
    *(uint2*)(g_pB16 + i * 4) = make_uint2(pk2(v.x, v.y), pk2(v.z, v.w));
}

// ---------------- finalize (float4 partial loads) ----------------
__global__ __launch_bounds__(256) void finalizeG_k(
    int slot, int shift,
    const float* __restrict__ g0, const float* __restrict__ b0,
    const float* __restrict__ g1, const float* __restrict__ b1,
    const float* __restrict__ g2, const float* __restrict__ b2,
    const float* __restrict__ g3, const float* __restrict__ b3)
{
    const int c = blockIdx.x, tid = threadIdx.x;
    const float4* ps = (const float4*)(g_psum   + (size_t)(slot + c) * NPART);
    const float4* pq = (const float4*)(g_psumsq + (size_t)(slot + c) * NPART);
    float s = 0.f, q = 0.f;
    for (int i = tid; i < NPART / 4; i += 256) {
        float4 a = ps[i]; s += (a.x + a.y) + (a.z + a.w);
        float4 d = pq[i]; q += (d.x + d.y) + (d.z + d.w);
    }
    __shared__ float ss[256], sq[256];
    ss[tid] = s; sq[tid] = q; __syncthreads();
    for (int st = 128; st > 0; st >>= 1) {
        if (tid < st) { ss[tid] += ss[tid + st]; sq[tid] += sq[tid + st]; }
        __syncthreads();
    }
    if (tid == 0) {
        const int grp = c >> shift, idx = c & ((1 << shift) - 1);
        const float* gp; const float* bp;
        if (grp == 0)      { gp = g0; bp = b0; }
        else if (grp == 1) { gp = g1; bp = b1; }
        else if (grp == 2) { gp = g2; bp = b2; }
        else               { gp = g3; bp = b3; }
        const float inv = 1.f / 65536.f;
        float m = ss[0] * inv;
        float v = sq[0] * inv - m * m;
        float sc = gp[idx] * rsqrtf(v + 1e-5f);
        g_scale[slot + c] = sc;
        g_shift[slot + c] = bp[idx] - m * sc;
    }
}

// ---------------- softmax stats only: per (lga,b,c) rowmax + 1/Z ----------------
__global__ __launch_bounds__(256) void smxstat_k()
{
    __shared__ float row[4096];
    __shared__ float red[256];
    const int id = blockIdx.x;                  // 2048 = lga*1024 + b*64 + c
    const int lga = id >> 10, rem = id & 1023;
    const int b = rem >> 6, c = rem & 63;
    const float* p = g_qkv + ((size_t)b * 384 + lga * 192 + 64 + c) * HW;
    const int tid = threadIdx.x;

    float m = -1e30f;
    for (int i = tid; i < 4096; i += 256) { float v = p[i]; row[i] = v; m = fmaxf(m, v); }
    red[tid] = m; __syncthreads();
    for (int st = 128; st > 0; st >>= 1) { if (tid < st) red[tid] = fmaxf(red[tid], red[tid + st]); __syncthreads(); }
    m = red[0]; __syncthreads();

    float s = 0.f;
    for (int i = tid; i < 4096; i += 256) { float e = expf(row[i] - m); s += e; }
    red[tid] = s; __syncthreads();
    for (int st = 128; st > 0; st >>= 1) { if (tid < st) red[tid] += red[tid + st]; __syncthreads(); }
    if (tid == 0) g_smx[id] = make_float2(m, 1.f / red[0]);
}

// ---------------- ctx: applies exp(k-m)*inv at load ----------------
__global__ __launch_bounds__(256) void ctx_k()
{
    __shared__ float Ks[64][33];
    __shared__ float Vs[64][33];
    __shared__ float2 mz[64];
    const int chunk = blockIdx.x >> 4, b = blockIdx.x & 15, lga = blockIdx.y;
    const float* base = g_qkv + ((size_t)b * 384 + lga * 192) * HW;
    const float* kp = base + (size_t)64 * HW;
    const float* vp = base + (size_t)128 * HW;
    const int tid = threadIdx.x;
    const int cb = (tid >> 4) << 2, db = (tid & 15) << 2;

    if (tid < 64) mz[tid] = g_smx[lga * 1024 + b * 64 + tid];
    __syncthreads();

    float acc[4][4];
#pragma unroll
    for (int i = 0; i < 4; i++)
#pragma unroll
        for (int j = 0; j < 4; j++) acc[i][j] = 0.f;

    for (int sub = 0; sub < 16; sub++) {
        const int n0 = chunk * 512 + sub * 32;
        for (int idx = tid; idx < 2048; idx += 256) {
            int r = idx >> 5, cc = idx & 31;
            float2 z = mz[r];
            Ks[r][cc] = expf(kp[(size_t)r * HW + n0 + cc] - z.x) * z.y;
            Vs[r][cc] = vp[(size_t)r * HW + n0 + cc];
        }
        __syncthreads();
#pragma unroll 8
        for (int nn = 0; nn < 32; nn++) {
            float kc[4], vd[4];
#pragma unroll
            for (int i = 0; i < 4; i++) { kc[i] = Ks[cb + i][nn]; vd[i] = Vs[db + i][nn]; }
#pragma unroll
            for (int i = 0; i < 4; i++)
#pragma unroll
                for (int j = 0; j < 4; j++) acc[i][j] += kc[i] * vd[j];
        }
        __syncthreads();
    }
    float* cp = g_ctxp + ((size_t)(lga * 16 + b) * 8 + chunk) * 4096;
#pragma unroll
    for (int i = 0; i < 4; i++)
#pragma unroll
        for (int j = 0; j < 4; j++) cp[(cb + i) * 64 + db + j] = acc[i][j];
}

__global__ void ctxred_k()
{
    int i = blockIdx.x * 256 + threadIdx.x;
    if (i >= 2 * NB * 4096) return;
    int pair = i >> 12, e = i & 4095;
    const float* cp = g_ctxp + (size_t)pair * 8 * 4096 + e;
    float s = 0.f;
#pragma unroll
    for (int p = 0; p < 8; p++) s += cp[p * 4096];
    g_ctx[i] = s;
}

// ---------------- M = Wproj @ ctx^T -> g_Mm16[b][lga*64+o][c] ----------------
__global__ __launch_bounds__(256) void mproj_k(const float* __restrict__ Wp2, const float* __restrict__ Wp3)
{
    const int id = blockIdx.x;
    const int lga = id >> 4, b = id & 15;
    const float* Wp = lga ? Wp3 : Wp2;
    const float* cx = g_ctx + (size_t)id * 4096;
    __half* Mo = g_Mm16 + (size_t)b * 8192 + (size_t)lga * 64 * 64;
    for (int e = threadIdx.x; e < 4096; e += 256) {
        int o = e >> 6, c = e & 63;
        float s = 0.f;
#pragma unroll 16
        for (int d = 0; d < 64; d++) s += Wp[o * 64 + d] * cx[c * 64 + d];
        Mo[o * 64 + c] = __float2half(s);
    }
}

// ---------------- final ----------------
__global__ __launch_bounds__(256) void final_k(float* __restrict__ out)
{
    size_t i = (size_t)blockIdx.x * 256 + threadIdx.x;
    int b = (int)(i >> 18);
    int off = (int)(i & 262143);
    int c = off >> 10;
    float s2 = g_scale[768 + c], h2v = g_shift[768 + c];
    float s0 = g_scale[c],       h0v = g_shift[c];
    float4 p = ((const float4*)g_pout)[i];
    float4 r = ((const float4*)g_s1)[(size_t)b * 524288 + off];
    p.x = fmaxf(p.x * s2 + h2v + r.x * s0 + h0v, 0.f);
    p.y = fmaxf(p.y * s2 + h2v + r.y * s0 + h0v, 0.f);
    p.z = fmaxf(p.z * s2 + h2v + r.z * s0 + h0v, 0.f);
    p.w = fmaxf(p.w * s2 + h2v + r.w * s0 + h0v, 0.f);
    ((float4*)out)[i] = p;
}

// ---------------- launch ----------------
extern "C" void kernel_launch(void* const* d_in, const int* in_sizes, int n_in,
                              void* d_out, int out_size)
{
    (void)in_sizes; (void)n_in; (void)out_size;
    const float* x      = (const float*)d_in[0];
    const float* W_sc   = (const float*)d_in[1];
    const float* gsc    = (const float*)d_in[2];
    const float* bsc    = (const float*)d_in[3];
    const float* W1     = (const float*)d_in[4];
    const float* g1     = (const float*)d_in[5];
    const float* b1     = (const float*)d_in[6];
    const float* Wb0    = (const float*)d_in[7];
    const float* gb0    = (const float*)d_in[8];
    const float* bb0    = (const float*)d_in[9];
    const float* Wb1    = (const float*)d_in[10];
    const float* gb1    = (const float*)d_in[11];
    const float* bb1    = (const float*)d_in[12];
    const float* Wqkv2  = (const float*)d_in[13];
    const float* Wproj2 = (const float*)d_in[14];
    const float* ga2    = (const float*)d_in[15];
    const float* ba2    = (const float*)d_in[16];
    const float* Wqkv3  = (const float*)d_in[17];
    const float* Wproj3 = (const float*)d_in[18];
    const float* ga3    = (const float*)d_in[19];
    const float* ba3    = (const float*)d_in[20];
    const float* W2     = (const float*)d_in[21];
    const float* g2     = (const float*)d_in[22];
    const float* b2     = (const float*)d_in[23];

    cudaFuncSetAttribute(tg16_k,    cudaFuncAttributeMaxDynamicSharedMemorySize, SM128);
    cudaFuncSetAttribute(tg16_64_k, cudaFuncAttributeMaxDynamicSharedMemorySize, SM64);

    float *s1, *qkv, *preB, *pout;
    __half *x16, *h16, *pB16, *q16, *Mm16, *W16;
    cudaGetSymbolAddress((void**)&s1,   g_s1);
    cudaGetSymbolAddress((void**)&qkv,  g_qkv);
    cudaGetSymbolAddress((void**)&preB, g_preB);
    cudaGetSymbolAddress((void**)&pout, g_pout);
    cudaGetSymbolAddress((void**)&x16,  g_x16);
    cudaGetSymbolAddress((void**)&h16,  g_h16);
    cudaGetSymbolAddress((void**)&pB16, g_pB16);
    cudaGetSymbolAddress((void**)&q16,  g_q16);
    cudaGetSymbolAddress((void**)&Mm16, g_Mm16);
    cudaGetSymbolAddress((void**)&W16,  g_W16);

    // conversions
    wcvt_k<<<768, 256>>>(W_sc, W1, Wb0, Wqkv2, Wqkv3, W2, Wb1);
    cvtx_k<<<8192, 256>>>(x);

    // Stage 1 (merged): [tsc; h_pre] = [Wsc; W1] @ x16 ; stats slots 0-511
    tg16_k<<<dim3(32, 4, NB), 256, SM128>>>(W16, x16, s1, 128, 0, (long)128 * HW, 0, (long)512 * HW, 0, 0);
    finalizeG_k<<<512, 256>>>(0, 8, gsc, bsc, g1, b1, g1, b1, g1, b1);
    bnreluH_k<<<16384, 256>>>();

    // Branch 0: 1x1 conv
    tg16_64_k<<<dim3(32, 1, NB), 256, SM64>>>(W16 + OFF_WB0, h16, preB, 64, 0, (long)256 * HW, 0, 1, 0, (long)256 * HW, 0, 512, nullptr);
    // Branch 1: 3x3 conv
    tcv16_k<<<dim3(32, 1, NB), 256, SMCV>>>();
    // Branches 2/3 (merged): [qkv2; qkv3]; q channels go straight to fp16 q16
    tg16_64_k<<<dim3(32, 6, NB), 256, SM64>>>(W16 + OFF_WQ2, h16, qkv, 64, 0, (long)256 * HW, 128, 3, 64, (long)384 * HW, 0, -1, q16);
    smxstat_k<<<2048, 256>>>();
    ctx_k<<<dim3(128, 2), 256>>>();
    ctxred_k<<<512, 256>>>();
    mproj_k<<<32, 256>>>(Wproj2, Wproj3);
    // attn out (merged): preB ch 128-255 = [M2; M3] @ [q2; q3]
    tg16_64_k<<<dim3(32, 2, NB), 256, SM64>>>(Mm16, q16, preB, 64, 8192, (long)128 * HW, 0, 1, 64, (long)256 * HW, 128, 512, nullptr);

    // Branch BN params (merged: slots 512-767)
    finalizeG_k<<<256, 256>>>(512, 6, gb0, bb0, gb1, bb1, ga2, ba2, ga3, ba3);
    bnreluP_k<<<16384, 256>>>();

    // Final 256->256 GEMM
    tg16_k<<<dim3(32, 2, NB), 256, SM128>>>(W16 + OFF_W2, pB16, pout, 256, 0, (long)256 * HW, 0, (long)256 * HW, 0, 768);
    finalizeG_k<<<256, 256>>>(768, 8, g2, b2, g2, b2, g2, b2, g2, b2);
    final_k<<<16384, 256>>>((float*)d_out);
}

// round 14
// speedup vs baseline: 1.8445x; 1.0410x over previous
#include <cuda_runtime.h>
#include <cuda_fp16.h>
#include <cstdint>
#include <math.h>

#define HW 4096
#define NB 16
#define NPART 2048

// ---------------- scratch ----------------
static __device__ float  g_qkv [(size_t)NB*384*HW];   // fp32: ch 64-191 k2,v2 ; 256-383 k3,v3 (q skipped)
static __device__ float  g_ctxp[2*NB*8*4096];
static __device__ float  g_ctx [2*NB*4096];
static __device__ float2 g_smx [2*NB*64];
static __device__ float  g_psum  [(size_t)1024*NPART];
static __device__ float  g_psumsq[(size_t)1024*NPART];
static __device__ float  g_scale [1024];
static __device__ float  g_shift [1024];
// fp16 buffers (16B-aligned)
static __device__ __align__(16) __half g_s1  [(size_t)NB*512*HW];  // pre-BN: ch0-255 tsc, 256-511 h
static __device__ __align__(16) __half g_preB[(size_t)NB*256*HW];  // pre-BN branch outputs
static __device__ __align__(16) __half g_pout[(size_t)NB*256*HW];  // pre-BN final conv
static __device__ __align__(16) __half g_x16 [(size_t)NB*128*HW];
static __device__ __align__(16) __half g_h16 [(size_t)NB*256*HW];
static __device__ __align__(16) __half g_pB16[(size_t)NB*256*HW];
static __device__ __align__(16) __half g_q16 [(size_t)NB*128*HW];
static __device__ __align__(16) __half g_Mm16[(size_t)NB*128*64];
static __device__ __align__(16) __half g_W16 [196608];
#define OFF_WSC 0
#define OFF_W1  32768
#define OFF_WB0 65536
#define OFF_WQ2 69632
#define OFF_WQ3 81920
#define OFF_W2  94208
#define OFF_WC  159744

__device__ __forceinline__ uint32_t pk2(float a, float b) {
    __half2 h = __floats2half2_rn(a, b);
    return *(uint32_t*)&h;
}
__device__ __forceinline__ float2 up2(uint32_t u) {
    __half2 h = *(__half2*)&u;
    return __half22float2(h);
}
__device__ __forceinline__ void mma16(float* c, const uint32_t* a, const uint32_t* b) {
    asm volatile("mma.sync.aligned.m16n8k16.row.col.f32.f16.f16.f32 "
        "{%0,%1,%2,%3}, {%4,%5,%6,%7}, {%8,%9}, {%0,%1,%2,%3};"
        : "+f"(c[0]), "+f"(c[1]), "+f"(c[2]), "+f"(c[3])
        : "r"(a[0]), "r"(a[1]), "r"(a[2]), "r"(a[3]), "r"(b[0]), "r"(b[1]));
}
__device__ __forceinline__ void cpa16(uint32_t dst, const void* src) {
    asm volatile("cp.async.ca.shared.global [%0], [%1], 16;" :: "r"(dst), "l"(src));
}
#define CP_COMMIT() asm volatile("cp.async.commit_group;")
#define CP_WAIT(n)  asm volatile("cp.async.wait_group %0;" :: "n"(n))
#define LDSM4(r0,r1,r2,r3,addr) \
    asm volatile("ldmatrix.sync.aligned.m8n8.x4.shared.b16 {%0,%1,%2,%3}, [%4];" \
        : "=r"(r0), "=r"(r1), "=r"(r2), "=r"(r3) : "r"(addr))
#define LDSM4T(r0,r1,r2,r3,addr) \
    asm volatile("ldmatrix.sync.aligned.m8n8.x4.trans.shared.b16 {%0,%1,%2,%3}, [%4];" \
        : "=r"(r0), "=r"(r1), "=r"(r2), "=r"(r3) : "r"(addr))

#define AROW 80
#define BROW 272
#define ABUF128 10240
#define ABUF64  5120
#define BBUF    8704
#define SM128 (3*ABUF128 + 3*BBUF)
#define SM64  (3*ABUF64  + 3*BBUF)
#define SMCV  (ABUF64 + BBUF)

#define STATS_EPI(MT_, mexpr_, slotbase_)                                            \
    {                                                                                \
        float s0 = 0.f, q0 = 0.f, s1 = 0.f, q1 = 0.f;                                \
        _Pragma("unroll")                                                            \
        for (int nt = 0; nt < 4; nt++) {                                             \
            s0 += acc[MT_][nt][0] + acc[MT_][nt][1];                                 \
            q0 += acc[MT_][nt][0]*acc[MT_][nt][0] + acc[MT_][nt][1]*acc[MT_][nt][1]; \
            s1 += acc[MT_][nt][2] + acc[MT_][nt][3];                                 \
            q1 += acc[MT_][nt][2]*acc[MT_][nt][2] + acc[MT_][nt][3]*acc[MT_][nt][3]; \
        }                                                                            \
        _Pragma("unroll")                                                            \
        for (int off = 1; off < 4; off <<= 1) {                                      \
            s0 += __shfl_xor_sync(0xffffffffu, s0, off);                             \
            q0 += __shfl_xor_sync(0xffffffffu, q0, off);                             \
            s1 += __shfl_xor_sync(0xffffffffu, s1, off);                             \
            q1 += __shfl_xor_sync(0xffffffffu, q1, off);                             \
        }                                                                            \
        if (qc == 0) {                                                               \
            g_psum  [(size_t)((slotbase_) + (mexpr_)) * NPART + pidx] = s0;          \
            g_psumsq[(size_t)((slotbase_) + (mexpr_)) * NPART + pidx] = q0;          \
            g_psum  [(size_t)((slotbase_) + (mexpr_) + 8) * NPART + pidx] = s1;      \
            g_psumsq[(size_t)((slotbase_) + (mexpr_) + 8) * NPART + pidx] = q1;      \
        }                                                                            \
    }

// ================= 128-row tile fp16 GEMM, 3-stage pipeline, fp16 C =================
__global__ __launch_bounds__(256, 2) void tg16_k(
    const __half* __restrict__ Wg, const __half* __restrict__ A16, __half* __restrict__ C16,
    int K, long wbs, long abs16, int acoff, long cbs, int ccoff, int statslot)
{
    extern __shared__ char smem[];
    const uint32_t sbase = (uint32_t)__cvta_generic_to_shared(smem);
    const int b = blockIdx.z;
    const __half* Wp = Wg + (size_t)b * wbs;
    const __half* Ap = A16 + (size_t)b * abs16 + (size_t)acoff * HW;
    __half* Cp = C16 + (size_t)b * cbs + (size_t)ccoff * HW;
    const int n0 = blockIdx.x * 128, m0 = blockIdx.y * 128;
    const int tid = threadIdx.x, lane = tid & 31, wid = tid >> 5;
    const int wm0 = (wid >> 2) * 64, wn0 = (wid & 3) * 32;
    const int qr = lane >> 2, qc = lane & 3;
    const int nk = K / 32;
    const int ar = tid >> 1, ac = (tid & 1) * 2;
    const int br = tid >> 3, bc = tid & 7;
    const int l15 = lane & 15, l8 = (lane >> 4) << 3;

    float acc[4][4][4];
#pragma unroll
    for (int i = 0; i < 4; i++)
#pragma unroll
        for (int j = 0; j < 4; j++)
#pragma unroll
            for (int e = 0; e < 4; e++) acc[i][j][e] = 0.f;

    auto fill = [&](int kcx, int st) {
        uint32_t da = sbase + st * ABUF128 + ar * AROW + ac * 16;
        const __half* sa = Wp + (size_t)(m0 + ar) * K + kcx * 32 + ac * 8;
        cpa16(da, sa); cpa16(da + 16, sa + 8);
        uint32_t db = sbase + 3 * ABUF128 + st * BBUF + br * BROW + bc * 16;
        const __half* sb = Ap + (size_t)(kcx * 32 + br) * HW + n0 + bc * 8;
        cpa16(db, sb); cpa16(db + 128, sb + 64);
        CP_COMMIT();
    };

    fill(0, 0);
    if (nk > 1) fill(1, 1);

    for (int kc = 0; kc < nk; kc++) {
        if (kc < nk - 1) { CP_WAIT(1); } else { CP_WAIT(0); }
        __syncthreads();
        const int st = kc % 3;
        const uint32_t ab = sbase + st * ABUF128;
        const uint32_t bb = sbase + 3 * ABUF128 + st * BBUF;
#pragma unroll
        for (int ks = 0; ks < 2; ks++) {
            const int kb = ks * 16;
            uint32_t af[4][4], bf[2][4];
#pragma unroll
            for (int mt = 0; mt < 4; mt++)
                LDSM4(af[mt][0], af[mt][1], af[mt][2], af[mt][3],
                      ab + (wm0 + mt * 16 + l15) * AROW + (kb + l8) * 2);
#pragma unroll
            for (int nh = 0; nh < 2; nh++)
                LDSM4T(bf[nh][0], bf[nh][1], bf[nh][2], bf[nh][3],
                       bb + (kb + l15) * BROW + (wn0 + nh * 16 + l8) * 2);
#pragma unroll
            for (int mt = 0; mt < 4; mt++)
#pragma unroll
                for (int nt = 0; nt < 4; nt++)
                    mma16(acc[mt][nt], af[mt], &bf[nt >> 1][(nt & 1) * 2]);
        }
        if (kc + 2 < nk) fill(kc + 2, (kc + 2) % 3);
    }

    const int pidx = (b * 32 + blockIdx.x) * 4 + (wid & 3);
#pragma unroll
    for (int mt = 0; mt < 4; mt++) {
        const int m = m0 + wm0 + mt * 16 + qr;
#pragma unroll
        for (int nt = 0; nt < 4; nt++) {
            const int n = n0 + wn0 + nt * 8 + qc * 2;
            *(uint32_t*)(Cp + (size_t)m * HW + n) = pk2(acc[mt][nt][0], acc[mt][nt][1]);
            *(uint32_t*)(Cp + (size_t)(m + 8) * HW + n) = pk2(acc[mt][nt][2], acc[mt][nt][3]);
        }
        if (statslot >= 0) STATS_EPI(mt, ccoff + m, statslot)
    }
}

// ================= 64-row tile fp16 GEMM; fp16 C16 or qkv mode (C32 + q16out) =================
__global__ __launch_bounds__(256, 2) void tg16_64_k(
    const __half* __restrict__ Wg, const __half* __restrict__ A16,
    __half* __restrict__ C16, float* __restrict__ C32,
    int K, long wbs, long abs16, int acoff, int agrp, int astep, long cbs, int ccoff,
    int statslot, __half* __restrict__ q16out)
{
    extern __shared__ char smem[];
    const uint32_t sbase = (uint32_t)__cvta_generic_to_shared(smem);
    const int b = blockIdx.z;
    const __half* Wp = Wg + (size_t)b * wbs;
    const __half* Ap = A16 + (size_t)b * abs16 + (size_t)(acoff + (blockIdx.y / agrp) * astep) * HW;
    const int n0 = blockIdx.x * 128, m0 = blockIdx.y * 64;
    const int tid = threadIdx.x, lane = tid & 31, wid = tid >> 5;
    const int wm0 = (wid >> 2) * 32, wn0 = (wid & 3) * 32;
    const int qr = lane >> 2, qc = lane & 3;
    const int nk = K / 32;
    const int ar = tid >> 2, ac = tid & 3;
    const int br = tid >> 3, bc = tid & 7;
    const int l15 = lane & 15, l8 = (lane >> 4) << 3;

    float acc[2][4][4];
#pragma unroll
    for (int i = 0; i < 2; i++)
#pragma unroll
        for (int j = 0; j < 4; j++)
#pragma unroll
            for (int e = 0; e < 4; e++) acc[i][j][e] = 0.f;

    auto fill = [&](int kcx, int st) {
        cpa16(sbase + st * ABUF64 + ar * AROW + ac * 16,
              Wp + (size_t)(m0 + ar) * K + kcx * 32 + ac * 8);
        uint32_t db = sbase + 3 * ABUF64 + st * BBUF + br * BROW + bc * 16;
        const __half* sb = Ap + (size_t)(kcx * 32 + br) * HW + n0 + bc * 8;
        cpa16(db, sb); cpa16(db + 128, sb + 64);
        CP_COMMIT();
    };

    fill(0, 0);
    if (nk > 1) fill(1, 1);

    for (int kc = 0; kc < nk; kc++) {
        if (kc < nk - 1) { CP_WAIT(1); } else { CP_WAIT(0); }
        __syncthreads();
        const int st = kc % 3;
        const uint32_t ab = sbase + st * ABUF64;
        const uint32_t bb = sbase + 3 * ABUF64 + st * BBUF;
#pragma unroll
        for (int ks = 0; ks < 2; ks++) {
            const int kb = ks * 16;
            uint32_t af[2][4], bf[2][4];
#pragma unroll
            for (int mt = 0; mt < 2; mt++)
                LDSM4(af[mt][0], af[mt][1], af[mt][2], af[mt][3],
                      ab + (wm0 + mt * 16 + l15) * AROW + (kb + l8) * 2);
#pragma unroll
            for (int nh = 0; nh < 2; nh++)
                LDSM4T(bf[nh][0], bf[nh][1], bf[nh][2], bf[nh][3],
                       bb + (kb + l15) * BROW + (wn0 + nh * 16 + l8) * 2);
#pragma unroll
            for (int mt = 0; mt < 2; mt++)
#pragma unroll
                for (int nt = 0; nt < 4; nt++)
                    mma16(acc[mt][nt], af[mt], &bf[nt >> 1][(nt & 1) * 2]);
        }
        if (kc + 2 < nk) fill(kc + 2, (kc + 2) % 3);
    }

    const int pidx = (b * 32 + blockIdx.x) * 4 + (wid & 3);
#pragma unroll
    for (int mt = 0; mt < 2; mt++) {
        const int m = m0 + wm0 + mt * 16 + qr;
        if (C32) {
            // qkv mode: q channels (lm<64) -> q16out fp16; k/v -> fp32 C32
            const int lm = m % 192;
            if (lm < 64) {
                const int qch = (m / 192) * 64 + lm;
                __half* qp0 = q16out + ((size_t)b * 128 + qch) * HW;
                __half* qp1 = qp0 + 8 * HW;
#pragma unroll
                for (int nt = 0; nt < 4; nt++) {
                    const int n = n0 + wn0 + nt * 8 + qc * 2;
                    *(uint32_t*)(qp0 + n) = pk2(acc[mt][nt][0], acc[mt][nt][1]);
                    *(uint32_t*)(qp1 + n) = pk2(acc[mt][nt][2], acc[mt][nt][3]);
                }
            } else {
                float* Cp = C32 + (size_t)b * cbs + (size_t)ccoff * HW;
#pragma unroll
                for (int nt = 0; nt < 4; nt++) {
                    const int n = n0 + wn0 + nt * 8 + qc * 2;
                    *(float2*)(Cp + (size_t)m * HW + n) = make_float2(acc[mt][nt][0], acc[mt][nt][1]);
                    *(float2*)(Cp + (size_t)(m + 8) * HW + n) = make_float2(acc[mt][nt][2], acc[mt][nt][3]);
                }
            }
        } else {
            __half* Cp = C16 + (size_t)b * cbs + (size_t)ccoff * HW;
#pragma unroll
            for (int nt = 0; nt < 4; nt++) {
                const int n = n0 + wn0 + nt * 8 + qc * 2;
                *(uint32_t*)(Cp + (size_t)m * HW + n) = pk2(acc[mt][nt][0], acc[mt][nt][1]);
                *(uint32_t*)(Cp + (size_t)(m + 8) * HW + n) = pk2(acc[mt][nt][2], acc[mt][nt][3]);
            }
        }
        if (statslot >= 0) STATS_EPI(mt, ccoff + m, statslot)
    }
}

// ================= fp16 implicit-GEMM 3x3 conv (fp16 C) =================
__global__ __launch_bounds__(256, 2) void tcv16_k()
{
    extern __shared__ char smem[];
    const uint32_t sbase = (uint32_t)__cvta_generic_to_shared(smem);
    const int b = blockIdx.z;
    const __half* Ap = g_h16 + (size_t)b * 256 * HW + (size_t)64 * HW;
    const __half* Wc = g_W16 + OFF_WC;
    __half* Cp = g_preB + (size_t)b * 256 * HW + (size_t)64 * HW;
    const int n0 = blockIdx.x * 128;
    const int tid = threadIdx.x, lane = tid & 31, wid = tid >> 5;
    const int wm0 = (wid >> 2) * 32, wn0 = (wid & 3) * 32;
    const int qr = lane >> 2, qc = lane & 3;
    const int l15 = lane & 15, l8 = (lane >> 4) << 3;

    float acc[2][4][4];
#pragma unroll
    for (int i = 0; i < 2; i++)
#pragma unroll
        for (int j = 0; j < 4; j++)
#pragma unroll
            for (int e = 0; e < 4; e++) acc[i][j][e] = 0.f;

    for (int kc = 0; kc < 18; kc++) {
        const int tap = kc >> 1, half = kc & 1;
        const int dy = tap / 3 - 1, dx = tap % 3 - 1;
        {
            const int row = tid >> 2, c = tid & 3;
            uint4 v = *(const uint4*)(Wc + (size_t)tap * 4096 + row * 64 + half * 32 + c * 8);
            *(uint4*)(smem + row * AROW + c * 16) = v;
        }
        {
            const int r = tid >> 3, g = tid & 7;
            const int ic = half * 32 + r;
            const __half* plane = Ap + (size_t)ic * HW;
            uint32_t w[8];
#pragma unroll
            for (int jj = 0; jj < 8; jj++) {
                uint32_t lohi[2];
#pragma unroll
                for (int e = 0; e < 2; e++) {
                    int p = n0 + g * 16 + jj * 2 + e;
                    int y = (p >> 6) + dy, x = (p & 63) + dx;
                    __half u = __float2half(0.f);
                    if ((unsigned)y < 64u && (unsigned)x < 64u) u = plane[y * 64 + x];
                    lohi[e] = (uint32_t)*(uint16_t*)&u;
                }
                w[jj] = lohi[0] | (lohi[1] << 16);
            }
            char* db = smem + ABUF64 + r * BROW + g * 32;
            *(uint4*)(db)      = make_uint4(w[0], w[1], w[2], w[3]);
            *(uint4*)(db + 16) = make_uint4(w[4], w[5], w[6], w[7]);
        }
        __syncthreads();
        const uint32_t ab = sbase;
        const uint32_t bb = sbase + ABUF64;
#pragma unroll
        for (int ks = 0; ks < 2; ks++) {
            const int kb = ks * 16;
            uint32_t af[2][4], bf[2][4];
#pragma unroll
            for (int mt = 0; mt < 2; mt++)
                LDSM4(af[mt][0], af[mt][1], af[mt][2], af[mt][3],
                      ab + (wm0 + mt * 16 + l15) * AROW + (kb + l8) * 2);
#pragma unroll
            for (int nh = 0; nh < 2; nh++)
                LDSM4T(bf[nh][0], bf[nh][1], bf[nh][2], bf[nh][3],
                       bb + (kb + l15) * BROW + (wn0 + nh * 16 + l8) * 2);
#pragma unroll
            for (int mt = 0; mt < 2; mt++)
#pragma unroll
                for (int nt = 0; nt < 4; nt++)
                    mma16(acc[mt][nt], af[mt], &bf[nt >> 1][(nt & 1) * 2]);
        }
        __syncthreads();
    }

    const int pidx = (b * 32 + blockIdx.x) * 4 + (wid & 3);
#pragma unroll
    for (int mt = 0; mt < 2; mt++) {
        const int m = wm0 + mt * 16 + qr;
#pragma unroll
        for (int nt = 0; nt < 4; nt++) {
            const int n = n0 + wn0 + nt * 8 + qc * 2;
            *(uint32_t*)(Cp + (size_t)m * HW + n) = pk2(acc[mt][nt][0], acc[mt][nt][1]);
            *(uint32_t*)(Cp + (size_t)(m + 8) * HW + n) = pk2(acc[mt][nt][2], acc[mt][nt][3]);
        }
        STATS_EPI(mt, m, 576)
    }
}

// ---------------- conversion kernels ----------------
__global__ __launch_bounds__(256) void wcvt_k(
    const float* __restrict__ Wsc, const float* __restrict__ W1, const float* __restrict__ Wb0,
    const float* __restrict__ Wq2, const float* __restrict__ Wq3, const float* __restrict__ W2,
    const float* __restrict__ Wb1)
{
    int i = blockIdx.x * 256 + threadIdx.x;
    if (i >= 196608) return;
    float v;
    if (i < 32768)       v = Wsc[i];
    else if (i < 65536)  v = W1[i - 32768];
    else if (i < 69632)  v = Wb0[i - 65536];
    else if (i < 81920)  v = Wq2[i - 69632];
    else if (i < 94208)  v = Wq3[i - 81920];
    else if (i < 159744) v = W2[i - 94208];
    else {
        int e = i - 159744;
        int tap = e >> 12, oc = (e >> 6) & 63, ic = e & 63;
        v = Wb1[oc * 576 + ic * 9 + tap];
    }
    g_W16[i] = __float2half(v);
}

__global__ __launch_bounds__(256) void cvtx_k(const float* __restrict__ x)
{
    size_t i = (size_t)blockIdx.x * 256 + threadIdx.x;
    float4 v = ((const float4*)x)[i];
    *(uint2*)(g_x16 + i * 4) = make_uint2(pk2(v.x, v.y), pk2(v.z, v.w));
}

// h16 = bnrelu(s1 fp16 ch 256-511)
__global__ __launch_bounds__(256) void bnreluH_k()
{
    size_t i = (size_t)blockIdx.x * 256 + threadIdx.x;   // 4,194,304 groups of 4 halfs
    int b = (int)(i >> 18);
    int off = (int)(i & 262143);
    int c = off >> 10;
    float sc = g_scale[256 + c], sh = g_shift[256 + c];
    uint2 u = *(const uint2*)(g_s1 + ((size_t)b * 2097152 + 1048576 + (size_t)off * 4));
    float2 a = up2(u.x), d = up2(u.y);
    a.x = fmaxf(a.x * sc + sh, 0.f); a.y = fmaxf(a.y * sc + sh, 0.f);
    d.x = fmaxf(d.x * sc + sh, 0.f); d.y = fmaxf(d.y * sc + sh, 0.f);
    *(uint2*)(g_h16 + i * 4) = make_uint2(pk2(a.x, a.y), pk2(d.x, d.y));
}

// pB16 = bnrelu(preB fp16)
__global__ __launch_bounds__(256) void bnreluP_k()
{
    size_t i = (size_t)blockIdx.x * 256 + threadIdx.x;
    int c = (int)((i >> 10) & 255);
    float sc = g_scale[512 + c], sh = g_shift[512 + c];
    uint2 u = *(const uint2*)(g_preB + i * 4);
    float2 a = up2(u.x), d = up2(u.y);
    a.x = fmaxf(a.x * sc + sh, 0.f); a.y = fmaxf(a.y * sc + sh, 0.f);
    d.x = fmaxf(d.x * sc + sh, 0.f); d.y = fmaxf(d.y * sc + sh, 0.f);
    *(uint2*)(g_pB16 + i * 4) = make_uint2(pk2(a.x, a.y), pk2(d.x, d.y));
}

// ---------------- finalize (float4 partial loads) ----------------
__global__ __launch_bounds__(256) void finalizeG_k(
    int slot, int shift,
    const float* __restrict__ g0, const float* __restrict__ b0,
    const float* __restrict__ g1, const float* __restrict__ b1,
    const float* __restrict__ g2, const float* __restrict__ b2,
    const float* __restrict__ g3, const float* __restrict__ b3)
{
    const int c = blockIdx.x, tid = threadIdx.x;
    const float4* ps = (const float4*)(g_psum   + (size_t)(slot + c) * NPART);
    const float4* pq = (const float4*)(g_psumsq + (size_t)(slot + c) * NPART);
    float s = 0.f, q = 0.f;
    for (int i = tid; i < NPART / 4; i += 256) {
        float4 a = ps[i]; s += (a.x + a.y) + (a.z + a.w);
        float4 d = pq[i]; q += (d.x + d.y) + (d.z + d.w);
    }
    __shared__ float ss[256], sq[256];
    ss[tid] = s; sq[tid] = q; __syncthreads();
    for (int st = 128; st > 0; st >>= 1) {
        if (tid < st) { ss[tid] += ss[tid + st]; sq[tid] += sq[tid + st]; }
        __syncthreads();
    }
    if (tid == 0) {
        const int grp = c >> shift, idx = c & ((1 << shift) - 1);
        const float* gp; const float* bp;
        if (grp == 0)      { gp = g0; bp = b0; }
        else if (grp == 1) { gp = g1; bp = b1; }
        else if (grp == 2) { gp = g2; bp = b2; }
        else               { gp = g3; bp = b3; }
        const float inv = 1.f / 65536.f;
        float m = ss[0] * inv;
        float v = sq[0] * inv - m * m;
        float sc = gp[idx] * rsqrtf(v + 1e-5f);
        g_scale[slot + c] = sc;
        g_shift[slot + c] = bp[idx] - m * sc;
    }
}

// ---------------- softmax stats ----------------
__global__ __launch_bounds__(256) void smxstat_k()
{
    __shared__ float row[4096];
    __shared__ float red[256];
    const int id = blockIdx.x;
    const int lga = id >> 10, rem = id & 1023;
    const int b = rem >> 6, c = rem & 63;
    const float* p = g_qkv + ((size_t)b * 384 + lga * 192 + 64 + c) * HW;
    const int tid = threadIdx.x;

    float m = -1e30f;
    for (int i = tid; i < 4096; i += 256) { float v = p[i]; row[i] = v; m = fmaxf(m, v); }
    red[tid] = m; __syncthreads();
    for (int st = 128; st > 0; st >>= 1) { if (tid < st) red[tid] = fmaxf(red[tid], red[tid + st]); __syncthreads(); }
    m = red[0]; __syncthreads();

    float s = 0.f;
    for (int i = tid; i < 4096; i += 256) { float e = expf(row[i] - m); s += e; }
    red[tid] = s; __syncthreads();
    for (int st = 128; st > 0; st >>= 1) { if (tid < st) red[tid] += red[tid + st]; __syncthreads(); }
    if (tid == 0) g_smx[id] = make_float2(m, 1.f / red[0]);
}

// ---------------- ctx ----------------
__global__ __launch_bounds__(256) void ctx_k()
{
    __shared__ float Ks[64][33];
    __shared__ float Vs[64][33];
    __shared__ float2 mz[64];
    const int chunk = blockIdx.x >> 4, b = blockIdx.x & 15, lga = blockIdx.y;
    const float* base = g_qkv + ((size_t)b * 384 + lga * 192) * HW;
    const float* kp = base + (size_t)64 * HW;
    const float* vp = base + (size_t)128 * HW;
    const int tid = threadIdx.x;
    const int cb = (tid >> 4) << 2, db = (tid & 15) << 2;

    if (tid < 64) mz[tid] = g_smx[lga * 1024 + b * 64 + tid];
    __syncthreads();

    float acc[4][4];
#pragma unroll
    for (int i = 0; i < 4; i++)
#pragma unroll
        for (int j = 0; j < 4; j++) acc[i][j] = 0.f;

    for (int sub = 0; sub < 16; sub++) {
        const int n0 = chunk * 512 + sub * 32;
        for (int idx = tid; idx < 2048; idx += 256) {
            int r = idx >> 5, cc = idx & 31;
            float2 z = mz[r];
            Ks[r][cc] = expf(kp[(size_t)r * HW + n0 + cc] - z.x) * z.y;
            Vs[r][cc] = vp[(size_t)r * HW + n0 + cc];
        }
        __syncthreads();
#pragma unroll 8
        for (int nn = 0; nn < 32; nn++) {
            float kc[4], vd[4];
#pragma unroll
            for (int i = 0; i < 4; i++) { kc[i] = Ks[cb + i][nn]; vd[i] = Vs[db + i][nn]; }
#pragma unroll
            for (int i = 0; i < 4; i++)
#pragma unroll
                for (int j = 0; j < 4; j++) acc[i][j] += kc[i] * vd[j];
        }
        __syncthreads();
    }
    float* cp = g_ctxp + ((size_t)(lga * 16 + b) * 8 + chunk) * 4096;
#pragma unroll
    for (int i = 0; i < 4; i++)
#pragma unroll
        for (int j = 0; j < 4; j++) cp[(cb + i) * 64 + db + j] = acc[i][j];
}

__global__ void ctxred_k()
{
    int i = blockIdx.x * 256 + threadIdx.x;
    if (i >= 2 * NB * 4096) return;
    int pair = i >> 12, e = i & 4095;
    const float* cp = g_ctxp + (size_t)pair * 8 * 4096 + e;
    float s = 0.f;
#pragma unroll
    for (int p = 0; p < 8; p++) s += cp[p * 4096];
    g_ctx[i] = s;
}

// ---------------- M = Wproj @ ctx^T ----------------
__global__ __launch_bounds__(256) void mproj_k(const float* __restrict__ Wp2, const float* __restrict__ Wp3)
{
    const int id = blockIdx.x;
    const int lga = id >> 4, b = id & 15;
    const float* Wp = lga ? Wp3 : Wp2;
    const float* cx = g_ctx + (size_t)id * 4096;
    __half* Mo = g_Mm16 + (size_t)b * 8192 + (size_t)lga * 64 * 64;
    for (int e = threadIdx.x; e < 4096; e += 256) {
        int o = e >> 6, c = e & 63;
        float s = 0.f;
#pragma unroll 16
        for (int d = 0; d < 64; d++) s += Wp[o * 64 + d] * cx[c * 64 + d];
        Mo[o * 64 + c] = __float2half(s);
    }
}

// ---------------- final: out = relu( bn2(pout16) + bn_sc(s1 tsc fp16) ) ----------------
__global__ __launch_bounds__(256) void final_k(float* __restrict__ out)
{
    size_t i = (size_t)blockIdx.x * 256 + threadIdx.x;   // 4,194,304 groups of 4
    int b = (int)(i >> 18);
    int off = (int)(i & 262143);
    int c = off >> 10;
    float s2 = g_scale[768 + c], h2v = g_shift[768 + c];
    float s0 = g_scale[c],       h0v = g_shift[c];
    uint2 pu = *(const uint2*)(g_pout + i * 4);
    uint2 ru = *(const uint2*)(g_s1 + ((size_t)b * 2097152 + (size_t)off * 4));
    float2 p0 = up2(pu.x), p1 = up2(pu.y);
    float2 r0 = up2(ru.x), r1 = up2(ru.y);
    float4 o;
    o.x = fmaxf(p0.x * s2 + h2v + r0.x * s0 + h0v, 0.f);
    o.y = fmaxf(p0.y * s2 + h2v + r0.y * s0 + h0v, 0.f);
    o.z = fmaxf(p1.x * s2 + h2v + r1.x * s0 + h0v, 0.f);
    o.w = fmaxf(p1.y * s2 + h2v + r1.y * s0 + h0v, 0.f);
    ((float4*)out)[i] = o;
}

// ---------------- launch ----------------
extern "C" void kernel_launch(void* const* d_in, const int* in_sizes, int n_in,
                              void* d_out, int out_size)
{
    (void)in_sizes; (void)n_in; (void)out_size;
    const float* x      = (const float*)d_in[0];
    const float* W_sc   = (const float*)d_in[1];
    const float* gsc    = (const float*)d_in[2];
    const float* bsc    = (const float*)d_in[3];
    const float* W1     = (const float*)d_in[4];
    const float* g1     = (const float*)d_in[5];
    const float* b1     = (const float*)d_in[6];
    const float* Wb0    = (const float*)d_in[7];
    const float* gb0    = (const float*)d_in[8];
    const float* bb0    = (const float*)d_in[9];
    const float* Wb1    = (const float*)d_in[10];
    const float* gb1    = (const float*)d_in[11];
    const float* bb1    = (const float*)d_in[12];
    const float* Wqkv2  = (const float*)d_in[13];
    const float* Wproj2 = (const float*)d_in[14];
    const float* ga2    = (const float*)d_in[15];
    const float* ba2    = (const float*)d_in[16];
    const float* Wqkv3  = (const float*)d_in[17];
    const float* Wproj3 = (const float*)d_in[18];
    const float* ga3    = (const float*)d_in[19];
    const float* ba3    = (const float*)d_in[20];
    const float* W2     = (const float*)d_in[21];
    const float* g2     = (const float*)d_in[22];
    const float* b2     = (const float*)d_in[23];

    cudaFuncSetAttribute(tg16_k,    cudaFuncAttributeMaxDynamicSharedMemorySize, SM128);
    cudaFuncSetAttribute(tg16_64_k, cudaFuncAttributeMaxDynamicSharedMemorySize, SM64);

    float *qkv;
    __half *s1h, *preBh, *pouth, *x16, *h16, *pB16, *q16, *Mm16, *W16;
    cudaGetSymbolAddress((void**)&qkv,   g_qkv);
    cudaGetSymbolAddress((void**)&s1h,   g_s1);
    cudaGetSymbolAddress((void**)&preBh, g_preB);
    cudaGetSymbolAddress((void**)&pouth, g_pout);
    cudaGetSymbolAddress((void**)&x16,   g_x16);
    cudaGetSymbolAddress((void**)&h16,   g_h16);
    cudaGetSymbolAddress((void**)&pB16,  g_pB16);
    cudaGetSymbolAddress((void**)&q16,   g_q16);
    cudaGetSymbolAddress((void**)&Mm16,  g_Mm16);
    cudaGetSymbolAddress((void**)&W16,   g_W16);

    // conversions
    wcvt_k<<<768, 256>>>(W_sc, W1, Wb0, Wqkv2, Wqkv3, W2, Wb1);
    cvtx_k<<<8192, 256>>>(x);

    // Stage 1 (merged): [tsc; h_pre] fp16; stats slots 0-511
    tg16_k<<<dim3(32, 4, NB), 256, SM128>>>(W16, x16, s1h, 128, 0, (long)128 * HW, 0, (long)512 * HW, 0, 0);
    finalizeG_k<<<512, 256>>>(0, 8, gsc, bsc, g1, b1, g1, b1, g1, b1);
    bnreluH_k<<<16384, 256>>>();

    // Branch 0: 1x1 conv -> preB fp16
    tg16_64_k<<<dim3(32, 1, NB), 256, SM64>>>(W16 + OFF_WB0, h16, preBh, nullptr, 64, 0, (long)256 * HW, 0, 1, 0, (long)256 * HW, 0, 512, nullptr);
    // Branch 1: 3x3 conv -> preB fp16
    tcv16_k<<<dim3(32, 1, NB), 256, SMCV>>>();
    // Branches 2/3 (merged): q -> q16 fp16, k/v -> qkv fp32
    tg16_64_k<<<dim3(32, 6, NB), 256, SM64>>>(W16 + OFF_WQ2, h16, nullptr, qkv, 64, 0, (long)256 * HW, 128, 3, 64, (long)384 * HW, 0, -1, q16);
    smxstat_k<<<2048, 256>>>();
    ctx_k<<<dim3(128, 2), 256>>>();
    ctxred_k<<<512, 256>>>();
    mproj_k<<<32, 256>>>(Wproj2, Wproj3);
    // attn out (merged): preB ch 128-255 fp16
    tg16_64_k<<<dim3(32, 2, NB), 256, SM64>>>(Mm16, q16, preBh, nullptr, 64, 8192, (long)128 * HW, 0, 1, 64, (long)256 * HW, 128, 512, nullptr);

    // Branch BN params
    finalizeG_k<<<256, 256>>>(512, 6, gb0, bb0, gb1, bb1, ga2, ba2, ga3, ba3);
    bnreluP_k<<<16384, 256>>>();

    // Final 256->256 GEMM -> pout fp16
    tg16_k<<<dim3(32, 2, NB), 256, SM128>>>(W16 + OFF_W2, pB16, pouth, 256, 0, (long)256 * HW, 0, (long)256 * HW, 0, 768);
    finalizeG_k<<<256, 256>>>(768, 8, g2, b2, g2, b2, g2, b2, g2, b2);
    final_k<<<16384, 256>>>((float*)d_out);
}

// round 17
// speedup vs baseline: 2.3163x; 1.2558x over previous
#include <cuda_runtime.h>
#include <cuda_fp16.h>
#include <cstdint>
#include <math.h>

#define HW 4096
#define NB 16
#define NPART 512

// ---------------- scratch ----------------
static __device__ float  g_qkv [(size_t)NB*384*HW];   // fp32 k/v planes (q slots unused), stride 384*HW/batch
static __device__ float  g_ctxp[2*NB*8*4096];
static __device__ float2 g_smx [2*NB*64];
static __device__ float  g_psum  [(size_t)1024*NPART];
static __device__ float  g_psumsq[(size_t)1024*NPART];
static __device__ float  g_scale [1024];
static __device__ float  g_shift [1024];
// fp16 buffers (16B-aligned)
static __device__ __align__(16) __half g_s1  [(size_t)NB*512*HW];
static __device__ __align__(16) __half g_preB[(size_t)NB*256*HW];
static __device__ __align__(16) __half g_pout[(size_t)NB*256*HW];
static __device__ __align__(16) __half g_x16 [(size_t)NB*128*HW];
static __device__ __align__(16) __half g_h16 [(size_t)NB*256*HW];
static __device__ __align__(16) __half g_pB16[(size_t)NB*256*HW];
static __device__ __align__(16) __half g_q16 [(size_t)NB*128*HW];
static __device__ __align__(16) __half g_Mm16[(size_t)NB*128*64];
static __device__ __align__(16) __half g_W16 [196608];
#define OFF_WSC 0
#define OFF_W1  32768
#define OFF_WB0 65536
#define OFF_W2  94208
#define OFF_WC  159744

__device__ __forceinline__ uint32_t pk2(float a, float b) {
    __half2 h = __floats2half2_rn(a, b);
    return *(uint32_t*)&h;
}
__device__ __forceinline__ float2 up2(uint32_t u) {
    __half2 h = *(__half2*)&u;
    return __half22float2(h);
}
__device__ __forceinline__ void mma16(float* c, const uint32_t* a, const uint32_t* b) {
    asm volatile("mma.sync.aligned.m16n8k16.row.col.f32.f16.f16.f32 "
        "{%0,%1,%2,%3}, {%4,%5,%6,%7}, {%8,%9}, {%0,%1,%2,%3};"
        : "+f"(c[0]), "+f"(c[1]), "+f"(c[2]), "+f"(c[3])
        : "r"(a[0]), "r"(a[1]), "r"(a[2]), "r"(a[3]), "r"(b[0]), "r"(b[1]));
}
__device__ __forceinline__ void cpa16(uint32_t dst, const void* src) {
    asm volatile("cp.async.ca.shared.global [%0], [%1], 16;" :: "r"(dst), "l"(src));
}
#define CP_COMMIT() asm volatile("cp.async.commit_group;")
#define CP_WAIT(n)  asm volatile("cp.async.wait_group %0;" :: "n"(n))
#define LDSM4(r0,r1,r2,r3,addr) \
    asm volatile("ldmatrix.sync.aligned.m8n8.x4.shared.b16 {%0,%1,%2,%3}, [%4];" \
        : "=r"(r0), "=r"(r1), "=r"(r2), "=r"(r3) : "r"(addr))
#define LDSM4T(r0,r1,r2,r3,addr) \
    asm volatile("ldmatrix.sync.aligned.m8n8.x4.trans.shared.b16 {%0,%1,%2,%3}, [%4];" \
        : "=r"(r0), "=r"(r1), "=r"(r2), "=r"(r3) : "r"(addr))

#define AROW 80
#define BROW 272
#define ABUF128 10240
#define ABUF64  5120
#define BBUF    8704
#define SM128 (3*ABUF128 + 3*BBUF)
#define SM64  (3*ABUF64  + 3*BBUF)
#define SMCV  (ABUF64 + BBUF)

#define STATS_SHFL(MT_)                                                              \
        float s0 = 0.f, q0 = 0.f, s1 = 0.f, q1 = 0.f;                                \
        _Pragma("unroll")                                                            \
        for (int nt = 0; nt < 4; nt++) {                                             \
            s0 += acc[MT_][nt][0] + acc[MT_][nt][1];                                 \
            q0 += acc[MT_][nt][0]*acc[MT_][nt][0] + acc[MT_][nt][1]*acc[MT_][nt][1]; \
            s1 += acc[MT_][nt][2] + acc[MT_][nt][3];                                 \
            q1 += acc[MT_][nt][2]*acc[MT_][nt][2] + acc[MT_][nt][3]*acc[MT_][nt][3]; \
        }                                                                            \
        _Pragma("unroll")                                                            \
        for (int off = 1; off < 4; off <<= 1) {                                      \
            s0 += __shfl_xor_sync(0xffffffffu, s0, off);                             \
            q0 += __shfl_xor_sync(0xffffffffu, q0, off);                             \
            s1 += __shfl_xor_sync(0xffffffffu, s1, off);                             \
            q1 += __shfl_xor_sync(0xffffffffu, q1, off);                             \
        }

// ================= 128-row tile fp16 GEMM, 3-stage pipeline, fp16 C, block-reduced stats =================
__global__ __launch_bounds__(256, 2) void tg16_k(
    const __half* __restrict__ Wg, const __half* __restrict__ A16, __half* __restrict__ C16,
    int K, long abs16, int acoff, long cbs, int ccoff, int statslot)
{
    extern __shared__ char smem[];
    const uint32_t sbase = (uint32_t)__cvta_generic_to_shared(smem);
    const int b = blockIdx.z;
    const __half* Ap = A16 + (size_t)b * abs16 + (size_t)acoff * HW;
    __half* Cp = C16 + (size_t)b * cbs + (size_t)ccoff * HW;
    const int n0 = blockIdx.x * 128, m0 = blockIdx.y * 128;
    const int tid = threadIdx.x, lane = tid & 31, wid = tid >> 5;
    const int wm0 = (wid >> 2) * 64, wn0 = (wid & 3) * 32;
    const int qr = lane >> 2, qc = lane & 3;
    const int nk = K / 32;
    const int ar = tid >> 1, ac = (tid & 1) * 2;
    const int br = tid >> 3, bc = tid & 7;
    const int l15 = lane & 15, l8 = (lane >> 4) << 3;

    float acc[4][4][4];
#pragma unroll
    for (int i = 0; i < 4; i++)
#pragma unroll
        for (int j = 0; j < 4; j++)
#pragma unroll
            for (int e = 0; e < 4; e++) acc[i][j][e] = 0.f;

    auto fill = [&](int kcx, int st) {
        uint32_t da = sbase + st * ABUF128 + ar * AROW + ac * 16;
        const __half* sa = Wg + (size_t)(m0 + ar) * K + kcx * 32 + ac * 8;
        cpa16(da, sa); cpa16(da + 16, sa + 8);
        uint32_t db = sbase + 3 * ABUF128 + st * BBUF + br * BROW + bc * 16;
        const __half* sb = Ap + (size_t)(kcx * 32 + br) * HW + n0 + bc * 8;
        cpa16(db, sb); cpa16(db + 128, sb + 64);
        CP_COMMIT();
    };

    fill(0, 0);
    if (nk > 1) fill(1, 1);

    for (int kc = 0; kc < nk; kc++) {
        if (kc < nk - 1) { CP_WAIT(1); } else { CP_WAIT(0); }
        __syncthreads();
        const int st = kc % 3;
        const uint32_t ab = sbase + st * ABUF128;
        const uint32_t bb = sbase + 3 * ABUF128 + st * BBUF;
#pragma unroll
        for (int ks = 0; ks < 2; ks++) {
            const int kb = ks * 16;
            uint32_t af[4][4], bf[2][4];
#pragma unroll
            for (int mt = 0; mt < 4; mt++)
                LDSM4(af[mt][0], af[mt][1], af[mt][2], af[mt][3],
                      ab + (wm0 + mt * 16 + l15) * AROW + (kb + l8) * 2);
#pragma unroll
            for (int nh = 0; nh < 2; nh++)
                LDSM4T(bf[nh][0], bf[nh][1], bf[nh][2], bf[nh][3],
                       bb + (kb + l15) * BROW + (wn0 + nh * 16 + l8) * 2);
#pragma unroll
            for (int mt = 0; mt < 4; mt++)
#pragma unroll
                for (int nt = 0; nt < 4; nt++)
                    mma16(acc[mt][nt], af[mt], &bf[nt >> 1][(nt & 1) * 2]);
        }
        if (kc + 2 < nk) fill(kc + 2, (kc + 2) % 3);
    }

    __syncthreads();   // retire smem pipeline before stats-scratch reuse
    float* sms = (float*)smem;            // [4][128]
    float* smq = sms + 4 * 128;
#pragma unroll
    for (int mt = 0; mt < 4; mt++) {
        const int lch = wm0 + mt * 16 + qr;
        const int m = m0 + lch;
#pragma unroll
        for (int nt = 0; nt < 4; nt++) {
            const int n = n0 + wn0 + nt * 8 + qc * 2;
            *(uint32_t*)(Cp + (size_t)m * HW + n) = pk2(acc[mt][nt][0], acc[mt][nt][1]);
            *(uint32_t*)(Cp + (size_t)(m + 8) * HW + n) = pk2(acc[mt][nt][2], acc[mt][nt][3]);
        }
        if (statslot >= 0) {
            STATS_SHFL(mt)
            if (qc == 0) {
                sms[(wid & 3) * 128 + lch] = s0; smq[(wid & 3) * 128 + lch] = q0;
                sms[(wid & 3) * 128 + lch + 8] = s1; smq[(wid & 3) * 128 + lch + 8] = q1;
            }
        }
    }
    if (statslot >= 0) {
        __syncthreads();
        const int pidx = b * 32 + blockIdx.x;
        for (int ch = tid; ch < 128; ch += 256) {
            float s = sms[ch] + sms[128 + ch] + sms[256 + ch] + sms[384 + ch];
            float q = smq[ch] + smq[128 + ch] + smq[256 + ch] + smq[384 + ch];
            g_psum  [(size_t)(statslot + ccoff + m0 + ch) * NPART + pidx] = s;
            g_psumsq[(size_t)(statslot + ccoff + m0 + ch) * NPART + pidx] = q;
        }
    }
}

// ================= 64-row tile fp16 GEMM =================
// wbs: per-batch weight stride (0 = shared weights).
// mode 0: fp16 C16 (+optional stats), A offset = acoff + (y/agrp)*astep
// mode 1: merged branch0+qkv: y0 -> preB(C16)+stats; y>=1 -> q->q16out / kv->C32 (stride 384*HW)
__global__ __launch_bounds__(256, 2) void tg16_64_k(
    const __half* __restrict__ Wg, const __half* __restrict__ A16,
    __half* __restrict__ C16, float* __restrict__ C32,
    int K, long wbs, long abs16, int acoff, int agrp, int astep, long cbs, int ccoff,
    int statslot, __half* __restrict__ q16out, int mode)
{
    extern __shared__ char smem[];
    const uint32_t sbase = (uint32_t)__cvta_generic_to_shared(smem);
    const int b = blockIdx.z;
    const __half* Wp = Wg + (size_t)b * wbs;
    int aco;
    if (mode == 1) aco = (blockIdx.y == 0) ? 0 : (128 + ((blockIdx.y - 1) / 3) * 64);
    else           aco = acoff + (blockIdx.y / agrp) * astep;
    const __half* Ap = A16 + (size_t)b * abs16 + (size_t)aco * HW;
    const int n0 = blockIdx.x * 128, m0 = blockIdx.y * 64;
    const int tid = threadIdx.x, lane = tid & 31, wid = tid >> 5;
    const int wm0 = (wid >> 2) * 32, wn0 = (wid & 3) * 32;
    const int qr = lane >> 2, qc = lane & 3;
    const int nk = K / 32;
    const int ar = tid >> 2, ac = tid & 3;
    const int br = tid >> 3, bc = tid & 7;
    const int l15 = lane & 15, l8 = (lane >> 4) << 3;

    float acc[2][4][4];
#pragma unroll
    for (int i = 0; i < 2; i++)
#pragma unroll
        for (int j = 0; j < 4; j++)
#pragma unroll
            for (int e = 0; e < 4; e++) acc[i][j][e] = 0.f;

    auto fill = [&](int kcx, int st) {
        cpa16(sbase + st * ABUF64 + ar * AROW + ac * 16,
              Wp + (size_t)(m0 + ar) * K + kcx * 32 + ac * 8);
        uint32_t db = sbase + 3 * ABUF64 + st * BBUF + br * BROW + bc * 16;
        const __half* sb = Ap + (size_t)(kcx * 32 + br) * HW + n0 + bc * 8;
        cpa16(db, sb); cpa16(db + 128, sb + 64);
        CP_COMMIT();
    };

    fill(0, 0);
    if (nk > 1) fill(1, 1);

    for (int kc = 0; kc < nk; kc++) {
        if (kc < nk - 1) { CP_WAIT(1); } else { CP_WAIT(0); }
        __syncthreads();
        const int st = kc % 3;
        const uint32_t ab = sbase + st * ABUF64;
        const uint32_t bb = sbase + 3 * ABUF64 + st * BBUF;
#pragma unroll
        for (int ks = 0; ks < 2; ks++) {
            const int kb = ks * 16;
            uint32_t af[2][4], bf[2][4];
#pragma unroll
            for (int mt = 0; mt < 2; mt++)
                LDSM4(af[mt][0], af[mt][1], af[mt][2], af[mt][3],
                      ab + (wm0 + mt * 16 + l15) * AROW + (kb + l8) * 2);
#pragma unroll
            for (int nh = 0; nh < 2; nh++)
                LDSM4T(bf[nh][0], bf[nh][1], bf[nh][2], bf[nh][3],
                       bb + (kb + l15) * BROW + (wn0 + nh * 16 + l8) * 2);
#pragma unroll
            for (int mt = 0; mt < 2; mt++)
#pragma unroll
                for (int nt = 0; nt < 4; nt++)
                    mma16(acc[mt][nt], af[mt], &bf[nt >> 1][(nt & 1) * 2]);
        }
        if (kc + 2 < nk) fill(kc + 2, (kc + 2) % 3);
    }

    const bool dostats = (statslot >= 0) && (mode != 1 || blockIdx.y == 0);
    __syncthreads();
    float* sms = (float*)smem;            // [4][64]
    float* smq = sms + 4 * 64;
#pragma unroll
    for (int mt = 0; mt < 2; mt++) {
        const int lch = wm0 + mt * 16 + qr;
        const int m = m0 + lch;
        if (mode == 1 && m >= 64) {
            const int mq = m - 64;
            const int lm = mq % 192;
            if (lm < 64) {
                const int qch = (mq / 192) * 64 + lm;
                __half* qp0 = q16out + ((size_t)b * 128 + qch) * HW;
                __half* qp1 = qp0 + 8 * HW;
#pragma unroll
                for (int nt = 0; nt < 4; nt++) {
                    const int n = n0 + wn0 + nt * 8 + qc * 2;
                    *(uint32_t*)(qp0 + n) = pk2(acc[mt][nt][0], acc[mt][nt][1]);
                    *(uint32_t*)(qp1 + n) = pk2(acc[mt][nt][2], acc[mt][nt][3]);
                }
            } else {
                float* Cp = C32 + (size_t)b * 384 * HW;   // FIX: qkv tensor's own per-batch stride
#pragma unroll
                for (int nt = 0; nt < 4; nt++) {
                    const int n = n0 + wn0 + nt * 8 + qc * 2;
                    *(float2*)(Cp + (size_t)mq * HW + n) = make_float2(acc[mt][nt][0], acc[mt][nt][1]);
                    *(float2*)(Cp + (size_t)(mq + 8) * HW + n) = make_float2(acc[mt][nt][2], acc[mt][nt][3]);
                }
            }
        } else {
            __half* Cp = C16 + (size_t)b * cbs + (size_t)ccoff * HW;
#pragma unroll
            for (int nt = 0; nt < 4; nt++) {
                const int n = n0 + wn0 + nt * 8 + qc * 2;
                *(uint32_t*)(Cp + (size_t)m * HW + n) = pk2(acc[mt][nt][0], acc[mt][nt][1]);
                *(uint32_t*)(Cp + (size_t)(m + 8) * HW + n) = pk2(acc[mt][nt][2], acc[mt][nt][3]);
            }
        }
        if (dostats) {
            STATS_SHFL(mt)
            if (qc == 0) {
                sms[(wid & 3) * 64 + lch] = s0; smq[(wid & 3) * 64 + lch] = q0;
                sms[(wid & 3) * 64 + lch + 8] = s1; smq[(wid & 3) * 64 + lch + 8] = q1;
            }
        }
    }
    if (dostats) {
        __syncthreads();
        const int pidx = b * 32 + blockIdx.x;
        for (int ch = tid; ch < 64; ch += 256) {
            float s = sms[ch] + sms[64 + ch] + sms[128 + ch] + sms[192 + ch];
            float q = smq[ch] + smq[64 + ch] + smq[128 + ch] + smq[192 + ch];
            g_psum  [(size_t)(statslot + ccoff + m0 + ch) * NPART + pidx] = s;
            g_psumsq[(size_t)(statslot + ccoff + m0 + ch) * NPART + pidx] = q;
        }
    }
}

// ================= fp16 implicit-GEMM 3x3 conv =================
__global__ __launch_bounds__(256, 2) void tcv16_k()
{
    extern __shared__ char smem[];
    const uint32_t sbase = (uint32_t)__cvta_generic_to_shared(smem);
    const int b = blockIdx.z;
    const __half* Ap = g_h16 + (size_t)b * 256 * HW + (size_t)64 * HW;
    const __half* Wc = g_W16 + OFF_WC;
    __half* Cp = g_preB + (size_t)b * 256 * HW + (size_t)64 * HW;
    const int n0 = blockIdx.x * 128;
    const int tid = threadIdx.x, lane = tid & 31, wid = tid >> 5;
    const int wm0 = (wid >> 2) * 32, wn0 = (wid & 3) * 32;
    const int qr = lane >> 2, qc = lane & 3;
    const int l15 = lane & 15, l8 = (lane >> 4) << 3;

    float acc[2][4][4];
#pragma unroll
    for (int i = 0; i < 2; i++)
#pragma unroll
        for (int j = 0; j < 4; j++)
#pragma unroll
            for (int e = 0; e < 4; e++) acc[i][j][e] = 0.f;

    for (int kc = 0; kc < 18; kc++) {
        const int tap = kc >> 1, half = kc & 1;
        const int dy = tap / 3 - 1, dx = tap % 3 - 1;
        {
            const int row = tid >> 2, c = tid & 3;
            uint4 v = *(const uint4*)(Wc + (size_t)tap * 4096 + row * 64 + half * 32 + c * 8);
            *(uint4*)(smem + row * AROW + c * 16) = v;
        }
        {
            const int r = tid >> 3, g = tid & 7;
            const int ic = half * 32 + r;
            const __half* plane = Ap + (size_t)ic * HW;
            uint32_t w[8];
#pragma unroll
            for (int jj = 0; jj < 8; jj++) {
                uint32_t lohi[2];
#pragma unroll
                for (int e = 0; e < 2; e++) {
                    int p = n0 + g * 16 + jj * 2 + e;
                    int y = (p >> 6) + dy, x = (p & 63) + dx;
                    __half u = __float2half(0.f);
                    if ((unsigned)y < 64u && (unsigned)x < 64u) u = plane[y * 64 + x];
                    lohi[e] = (uint32_t)*(uint16_t*)&u;
                }
                w[jj] = lohi[0] | (lohi[1] << 16);
            }
            char* db = smem + ABUF64 + r * BROW + g * 32;
            *(uint4*)(db)      = make_uint4(w[0], w[1], w[2], w[3]);
            *(uint4*)(db + 16) = make_uint4(w[4], w[5], w[6], w[7]);
        }
        __syncthreads();
        const uint32_t ab = sbase;
        const uint32_t bb = sbase + ABUF64;
#pragma unroll
        for (int ks = 0; ks < 2; ks++) {
            const int kb = ks * 16;
            uint32_t af[2][4], bf[2][4];
#pragma unroll
            for (int mt = 0; mt < 2; mt++)
                LDSM4(af[mt][0], af[mt][1], af[mt][2], af[mt][3],
                      ab + (wm0 + mt * 16 + l15) * AROW + (kb + l8) * 2);
#pragma unroll
            for (int nh = 0; nh < 2; nh++)
                LDSM4T(bf[nh][0], bf[nh][1], bf[nh][2], bf[nh][3],
                       bb + (kb + l15) * BROW + (wn0 + nh * 16 + l8) * 2);
#pragma unroll
            for (int mt = 0; mt < 2; mt++)
#pragma unroll
                for (int nt = 0; nt < 4; nt++)
                    mma16(acc[mt][nt], af[mt], &bf[nt >> 1][(nt & 1) * 2]);
        }
        __syncthreads();
    }

    float* sms = (float*)smem;
    float* smq = sms + 4 * 64;
#pragma unroll
    for (int mt = 0; mt < 2; mt++) {
        const int lch = wm0 + mt * 16 + qr;
#pragma unroll
        for (int nt = 0; nt < 4; nt++) {
            const int n = n0 + wn0 + nt * 8 + qc * 2;
            *(uint32_t*)(Cp + (size_t)lch * HW + n) = pk2(acc[mt][nt][0], acc[mt][nt][1]);
            *(uint32_t*)(Cp + (size_t)(lch + 8) * HW + n) = pk2(acc[mt][nt][2], acc[mt][nt][3]);
        }
        STATS_SHFL(mt)
        if (qc == 0) {
            sms[(wid & 3) * 64 + lch] = s0; smq[(wid & 3) * 64 + lch] = q0;
            sms[(wid & 3) * 64 + lch + 8] = s1; smq[(wid & 3) * 64 + lch + 8] = q1;
        }
    }
    __syncthreads();
    const int pidx = b * 32 + blockIdx.x;
    for (int ch = tid; ch < 64; ch += 256) {
        float s = sms[ch] + sms[64 + ch] + sms[128 + ch] + sms[192 + ch];
        float q = smq[ch] + smq[64 + ch] + smq[128 + ch] + smq[192 + ch];
        g_psum  [(size_t)(576 + ch) * NPART + pidx] = s;
        g_psumsq[(size_t)(576 + ch) * NPART + pidx] = q;
    }
}

// ---------------- conversion kernels ----------------
__global__ __launch_bounds__(256) void wcvt_k(
    const float* __restrict__ Wsc, const float* __restrict__ W1, const float* __restrict__ Wb0,
    const float* __restrict__ Wq2, const float* __restrict__ Wq3, const float* __restrict__ W2,
    const float* __restrict__ Wb1)
{
    int i = blockIdx.x * 256 + threadIdx.x;
    if (i >= 196608) return;
    float v;
    if (i < 32768)       v = Wsc[i];
    else if (i < 65536)  v = W1[i - 32768];
    else if (i < 69632)  v = Wb0[i - 65536];
    else if (i < 81920)  v = Wq2[i - 69632];
    else if (i < 94208)  v = Wq3[i - 81920];
    else if (i < 159744) v = W2[i - 94208];
    else {
        int e = i - 159744;
        int tap = e >> 12, oc = (e >> 6) & 63, ic = e & 63;
        v = Wb1[oc * 576 + ic * 9 + tap];
    }
    g_W16[i] = __float2half(v);
}

__global__ __launch_bounds__(256) void cvtx_k(const float* __restrict__ x)
{
    size_t i = (size_t)blockIdx.x * 256 + threadIdx.x;
    float4 v = ((const float4*)x)[i];
    *(uint2*)(g_x16 + i * 4) = make_uint2(pk2(v.x, v.y), pk2(v.z, v.w));
}

__global__ __launch_bounds__(256) void bnreluH_k()
{
    size_t i = (size_t)blockIdx.x * 256 + threadIdx.x;
    int b = (int)(i >> 18);
    int off = (int)(i & 262143);
    int c = off >> 10;
    float sc = g_scale[256 + c], sh = g_shift[256 + c];
    uint2 u = *(const uint2*)(g_s1 + ((size_t)b * 2097152 + 1048576 + (size_t)off * 4));
    float2 a = up2(u.x), d = up2(u.y);
    a.x = fmaxf(a.x * sc + sh, 0.f); a.y = fmaxf(a.y * sc + sh, 0.f);
    d.x = fmaxf(d.x * sc + sh, 0.f); d.y = fmaxf(d.y * sc + sh, 0.f);
    *(uint2*)(g_h16 + i * 4) = make_uint2(pk2(a.x, a.y), pk2(d.x, d.y));
}

__global__ __launch_bounds__(256) void bnreluP_k()
{
    size_t i = (size_t)blockIdx.x * 256 + threadIdx.x;
    int c = (int)((i >> 10) & 255);
    float sc = g_scale[512 + c], sh = g_shift[512 + c];
    uint2 u = *(const uint2*)(g_preB + i * 4);
    float2 a = up2(u.x), d = up2(u.y);
    a.x = fmaxf(a.x * sc + sh, 0.f); a.y = fmaxf(a.y * sc + sh, 0.f);
    d.x = fmaxf(d.x * sc + sh, 0.f); d.y = fmaxf(d.y * sc + sh, 0.f);
    *(uint2*)(g_pB16 + i * 4) = make_uint2(pk2(a.x, a.y), pk2(d.x, d.y));
}

// ---------------- finalize ----------------
__global__ __launch_bounds__(256) void finalizeG_k(
    int slot, int shift,
    const float* __restrict__ g0, const float* __restrict__ b0,
    const float* __restrict__ g1, const float* __restrict__ b1,
    const float* __restrict__ g2, const float* __restrict__ b2,
    const float* __restrict__ g3, const float* __restrict__ b3)
{
    const int c = blockIdx.x, tid = threadIdx.x;
    const float4* ps = (const float4*)(g_psum   + (size_t)(slot + c) * NPART);
    const float4* pq = (const float4*)(g_psumsq + (size_t)(slot + c) * NPART);
    float s = 0.f, q = 0.f;
    for (int i = tid; i < NPART / 4; i += 256) {
        float4 a = ps[i]; s += (a.x + a.y) + (a.z + a.w);
        float4 d = pq[i]; q += (d.x + d.y) + (d.z + d.w);
    }
    __shared__ float ss[256], sq[256];
    ss[tid] = s; sq[tid] = q; __syncthreads();
    for (int st = 128; st > 0; st >>= 1) {
        if (tid < st) { ss[tid] += ss[tid + st]; sq[tid] += sq[tid + st]; }
        __syncthreads();
    }
    if (tid == 0) {
        const int grp = c >> shift, idx = c & ((1 << shift) - 1);
        const float* gp; const float* bp;
        if (grp == 0)      { gp = g0; bp = b0; }
        else if (grp == 1) { gp = g1; bp = b1; }
        else if (grp == 2) { gp = g2; bp = b2; }
        else               { gp = g3; bp = b3; }
        const float inv = 1.f / 65536.f;
        float m = ss[0] * inv;
        float v = sq[0] * inv - m * m;
        float sc = gp[idx] * rsqrtf(v + 1e-5f);
        g_scale[slot + c] = sc;
        g_shift[slot + c] = bp[idx] - m * sc;
    }
}

// ---------------- softmax stats ----------------
__global__ __launch_bounds__(256) void smxstat_k()
{
    __shared__ float row[4096];
    __shared__ float red[256];
    const int id = blockIdx.x;
    const int lga = id >> 10, rem = id & 1023;
    const int b = rem >> 6, c = rem & 63;
    const float* p = g_qkv + ((size_t)b * 384 + lga * 192 + 64 + c) * HW;
    const int tid = threadIdx.x;

    float m = -1e30f;
    for (int i = tid; i < 4096; i += 256) { float v = p[i]; row[i] = v; m = fmaxf(m, v); }
    red[tid] = m; __syncthreads();
    for (int st = 128; st > 0; st >>= 1) { if (tid < st) red[tid] = fmaxf(red[tid], red[tid + st]); __syncthreads(); }
    m = red[0]; __syncthreads();

    float s = 0.f;
    for (int i = tid; i < 4096; i += 256) { float e = expf(row[i] - m); s += e; }
    red[tid] = s; __syncthreads();
    for (int st = 128; st > 0; st >>= 1) { if (tid < st) red[tid] += red[tid + st]; __syncthreads(); }
    if (tid == 0) g_smx[id] = make_float2(m, 1.f / red[0]);
}

// ---------------- ctx ----------------
__global__ __launch_bounds__(256) void ctx_k()
{
    __shared__ float Ks[64][33];
    __shared__ float Vs[64][33];
    __shared__ float2 mz[64];
    const int chunk = blockIdx.x >> 4, b = blockIdx.x & 15, lga = blockIdx.y;
    const float* base = g_qkv + ((size_t)b * 384 + lga * 192) * HW;
    const float* kp = base + (size_t)64 * HW;
    const float* vp = base + (size_t)128 * HW;
    const int tid = threadIdx.x;
    const int cb = (tid >> 4) << 2, db = (tid & 15) << 2;

    if (tid < 64) mz[tid] = g_smx[lga * 1024 + b * 64 + tid];
    __syncthreads();

    float acc[4][4];
#pragma unroll
    for (int i = 0; i < 4; i++)
#pragma unroll
        for (int j = 0; j < 4; j++) acc[i][j] = 0.f;

    for (int sub = 0; sub < 16; sub++) {
        const int n0 = chunk * 512 + sub * 32;
        for (int idx = tid; idx < 2048; idx += 256) {
            int r = idx >> 5, cc = idx & 31;
            float2 z = mz[r];
            Ks[r][cc] = expf(kp[(size_t)r * HW + n0 + cc] - z.x) * z.y;
            Vs[r][cc] = vp[(size_t)r * HW + n0 + cc];
        }
        __syncthreads();
#pragma unroll 8
        for (int nn = 0; nn < 32; nn++) {
            float kc[4], vd[4];
#pragma unroll
            for (int i = 0; i < 4; i++) { kc[i] = Ks[cb + i][nn]; vd[i] = Vs[db + i][nn]; }
#pragma unroll
            for (int i = 0; i < 4; i++)
#pragma unroll
                for (int j = 0; j < 4; j++) acc[i][j] += kc[i] * vd[j];
        }
        __syncthreads();
    }
    float* cp = g_ctxp + ((size_t)(lga * 16 + b) * 8 + chunk) * 4096;
#pragma unroll
    for (int i = 0; i < 4; i++)
#pragma unroll
        for (int j = 0; j < 4; j++) cp[(cb + i) * 64 + db + j] = acc[i][j];
}

// ---------------- mproj (fused ctx-partial reduction) ----------------
__global__ __launch_bounds__(256) void mproj_k(const float* __restrict__ Wp2, const float* __restrict__ Wp3)
{
    __shared__ float cx[4096];
    const int id = blockIdx.x;
    const int lga = id >> 4, b = id & 15;
    const float* Wp = lga ? Wp3 : Wp2;
    const float* cp = g_ctxp + (size_t)id * 8 * 4096;
    const int tid = threadIdx.x;
    for (int e = tid; e < 4096; e += 256) {
        float s = 0.f;
#pragma unroll
        for (int p = 0; p < 8; p++) s += cp[p * 4096 + e];
        cx[e] = s;
    }
    __syncthreads();
    __half* Mo = g_Mm16 + (size_t)b * 8192 + (size_t)lga * 64 * 64;
    for (int e = tid; e < 4096; e += 256) {
        int o = e >> 6, c = e & 63;
        float s = 0.f;
#pragma unroll 16
        for (int d = 0; d < 64; d++) s += Wp[o * 64 + d] * cx[c * 64 + d];
        Mo[o * 64 + c] = __float2half(s);
    }
}

// ---------------- final ----------------
__global__ __launch_bounds__(256) void final_k(float* __restrict__ out)
{
    size_t i = (size_t)blockIdx.x * 256 + threadIdx.x;
    int b = (int)(i >> 18);
    int off = (int)(i & 262143);
    int c = off >> 10;
    float s2 = g_scale[768 + c], h2v = g_shift[768 + c];
    float s0 = g_scale[c],       h0v = g_shift[c];
    uint2 pu = *(const uint2*)(g_pout + i * 4);
    uint2 ru = *(const uint2*)(g_s1 + ((size_t)b * 2097152 + (size_t)off * 4));
    float2 p0 = up2(pu.x), p1 = up2(pu.y);
    float2 r0 = up2(ru.x), r1 = up2(ru.y);
    float4 o;
    o.x = fmaxf(p0.x * s2 + h2v + r0.x * s0 + h0v, 0.f);
    o.y = fmaxf(p0.y * s2 + h2v + r0.y * s0 + h0v, 0.f);
    o.z = fmaxf(p1.x * s2 + h2v + r1.x * s0 + h0v, 0.f);
    o.w = fmaxf(p1.y * s2 + h2v + r1.y * s0 + h0v, 0.f);
    ((float4*)out)[i] = o;
}

// ---------------- launch ----------------
extern "C" void kernel_launch(void* const* d_in, const int* in_sizes, int n_in,
                              void* d_out, int out_size)
{
    (void)in_sizes; (void)n_in; (void)out_size;
    const float* x      = (const float*)d_in[0];
    const float* W_sc   = (const float*)d_in[1];
    const float* gsc    = (const float*)d_in[2];
    const float* bsc    = (const float*)d_in[3];
    const float* W1     = (const float*)d_in[4];
    const float* g1     = (const float*)d_in[5];
    const float* b1     = (const float*)d_in[6];
    const float* Wb0    = (const float*)d_in[7];
    const float* gb0    = (const float*)d_in[8];
    const float* bb0    = (const float*)d_in[9];
    const float* Wb1    = (const float*)d_in[10];
    const float* gb1    = (const float*)d_in[11];
    const float* bb1    = (const float*)d_in[12];
    const float* Wqkv2  = (const float*)d_in[13];
    const float* Wproj2 = (const float*)d_in[14];
    const float* ga2    = (const float*)d_in[15];
    const float* ba2    = (const float*)d_in[16];
    const float* Wqkv3  = (const float*)d_in[17];
    const float* Wproj3 = (const float*)d_in[18];
    const float* ga3    = (const float*)d_in[19];
    const float* ba3    = (const float*)d_in[20];
    const float* W2     = (const float*)d_in[21];
    const float* g2     = (const float*)d_in[22];
    const float* b2     = (const float*)d_in[23];

    cudaFuncSetAttribute(tg16_k,    cudaFuncAttributeMaxDynamicSharedMemorySize, SM128);
    cudaFuncSetAttribute(tg16_64_k, cudaFuncAttributeMaxDynamicSharedMemorySize, SM64);

    float *qkv;
    __half *s1h, *preBh, *pouth, *x16, *h16, *pB16, *q16, *Mm16, *W16;
    cudaGetSymbolAddress((void**)&qkv,   g_qkv);
    cudaGetSymbolAddress((void**)&s1h,   g_s1);
    cudaGetSymbolAddress((void**)&preBh, g_preB);
    cudaGetSymbolAddress((void**)&pouth, g_pout);
    cudaGetSymbolAddress((void**)&x16,   g_x16);
    cudaGetSymbolAddress((void**)&h16,   g_h16);
    cudaGetSymbolAddress((void**)&pB16,  g_pB16);
    cudaGetSymbolAddress((void**)&q16,   g_q16);
    cudaGetSymbolAddress((void**)&Mm16,  g_Mm16);
    cudaGetSymbolAddress((void**)&W16,   g_W16);

    // conversions
    wcvt_k<<<768, 256>>>(W_sc, W1, Wb0, Wqkv2, Wqkv3, W2, Wb1);
    cvtx_k<<<8192, 256>>>(x);

    // Stage 1 (merged): [tsc; h_pre] fp16; stats slots 0-511
    tg16_k<<<dim3(32, 4, NB), 256, SM128>>>(W16, x16, s1h, 128, (long)128 * HW, 0, (long)512 * HW, 0, 0);
    finalizeG_k<<<512, 256>>>(0, 8, gsc, bsc, g1, b1, g1, b1, g1, b1);
    bnreluH_k<<<16384, 256>>>();

    // Branch 1: 3x3 conv -> preB fp16 (stats slot 576)
    tcv16_k<<<dim3(32, 1, NB), 256, SMCV>>>();
    // Merged branch0 + qkv: y0 -> preB ch0-63 + stats 512; y1-6 -> q16 / qkv fp32
    tg16_64_k<<<dim3(32, 7, NB), 256, SM64>>>(W16 + OFF_WB0, h16, preBh, qkv,
                                              64, 0, (long)256 * HW, 0, 1, 0, (long)256 * HW, 0, 512, q16, 1);
    smxstat_k<<<2048, 256>>>();
    ctx_k<<<dim3(128, 2), 256>>>();
    mproj_k<<<32, 256>>>(Wproj2, Wproj3);
    // attn out: preB ch 128-255 fp16, per-batch weights Mm16 (wbs=8192)
    tg16_64_k<<<dim3(32, 2, NB), 256, SM64>>>(Mm16, q16, preBh, nullptr,
                                              64, 8192, (long)128 * HW, 0, 1, 64, (long)256 * HW, 128, 512, nullptr, 0);

    // Branch BN params
    finalizeG_k<<<256, 256>>>(512, 6, gb0, bb0, gb1, bb1, ga2, ba2, ga3, ba3);
    bnreluP_k<<<16384, 256>>>();

    // Final 256->256 GEMM -> pout fp16
    tg16_k<<<dim3(32, 2, NB), 256, SM128>>>(W16 + OFF_W2, pB16, pouth, 256, (long)256 * HW, 0, (long)256 * HW, 0, 768);
    finalizeG_k<<<256, 256>>>(768, 8, g2, b2, g2, b2, g2, b2, g2, b2);
    final_k<<<16384, 256>>>((float*)d_out);
}